// round 7
// baseline (speedup 1.0000x reference)
#include <cuda_runtime.h>
#include <cuda_bf16.h>
#include <math.h>
#include <stdint.h>

#define T_SEQ 2048
#define D_MODEL 1024
#define N_HEADS 16
#define HEAD_DIM 64
#define FFN_DIM 4096
typedef __nv_bfloat16 bf16;

// ---------------- scratch ----------------
__device__ float g_q[T_SEQ * D_MODEL];
__device__ float g_k[T_SEQ * D_MODEL];
__device__ float g_v[T_SEQ * D_MODEL];
__device__ float g_x1[T_SEQ * D_MODEL];
__device__ bf16  g_xnh[T_SEQ * D_MODEL];
__device__ bf16  g_xnl[T_SEQ * D_MODEL];
__device__ bf16  g_ah[T_SEQ * D_MODEL];
__device__ bf16  g_al[T_SEQ * D_MODEL];
__device__ bf16  g_hh[T_SEQ * FFN_DIM];
__device__ bf16  g_hl[T_SEQ * FFN_DIM];
__device__ bf16 g_wqh[D_MODEL * D_MODEL], g_wql[D_MODEL * D_MODEL];
__device__ bf16 g_wkh[D_MODEL * D_MODEL], g_wkl[D_MODEL * D_MODEL];
__device__ bf16 g_wvh[D_MODEL * D_MODEL], g_wvl[D_MODEL * D_MODEL];
__device__ bf16 g_woh[D_MODEL * D_MODEL], g_wol[D_MODEL * D_MODEL];
__device__ bf16 g_w1h[FFN_DIM * D_MODEL], g_w1l[FFN_DIM * D_MODEL];
__device__ bf16 g_w2h[D_MODEL * FFN_DIM], g_w2l[D_MODEL * FFN_DIM];

// ---------------- helpers ----------------
__device__ __forceinline__ uint32_t smem_u32(const void* p) {
    uint32_t a;
    asm("{ .reg .u64 t; cvta.to.shared.u64 t, %1; cvt.u32.u64 %0, t; }" : "=r"(a) : "l"(p));
    return a;
}
__device__ __forceinline__ void cp16(uint32_t s, const void* g) {
    asm volatile("cp.async.cg.shared.global [%0], [%1], 16;" :: "r"(s), "l"(g));
}
#define CP_COMMIT() asm volatile("cp.async.commit_group;" ::: "memory")
#define CP_WAIT(n)  asm volatile("cp.async.wait_group %0;" :: "n"(n) : "memory")

__device__ __forceinline__ void ldsm4(uint32_t* r, uint32_t addr) {
    asm volatile("ldmatrix.sync.aligned.m8n8.x4.shared.b16 {%0,%1,%2,%3}, [%4];"
        : "=r"(r[0]), "=r"(r[1]), "=r"(r[2]), "=r"(r[3]) : "r"(addr));
}
__device__ __forceinline__ void ldsm4t(uint32_t* r, uint32_t addr) {
    asm volatile("ldmatrix.sync.aligned.m8n8.x4.trans.shared.b16 {%0,%1,%2,%3}, [%4];"
        : "=r"(r[0]), "=r"(r[1]), "=r"(r[2]), "=r"(r[3]) : "r"(addr));
}
__device__ __forceinline__ void mma_bf16(float* d, const uint32_t* a, const uint32_t* b) {
    asm volatile(
        "mma.sync.aligned.m16n8k16.row.col.f32.bf16.bf16.f32 "
        "{%0,%1,%2,%3}, {%4,%5,%6,%7}, {%8,%9}, {%0,%1,%2,%3};"
        : "+f"(d[0]), "+f"(d[1]), "+f"(d[2]), "+f"(d[3])
        : "r"(a[0]), "r"(a[1]), "r"(a[2]), "r"(a[3]), "r"(b[0]), "r"(b[1]));
}
__device__ __forceinline__ void mma_tf32(float* d, const uint32_t* a, const uint32_t* b) {
    asm volatile(
        "mma.sync.aligned.m16n8k8.row.col.f32.tf32.tf32.f32 "
        "{%0,%1,%2,%3}, {%4,%5,%6,%7}, {%8,%9}, {%0,%1,%2,%3};"
        : "+f"(d[0]), "+f"(d[1]), "+f"(d[2]), "+f"(d[3])
        : "r"(a[0]), "r"(a[1]), "r"(a[2]), "r"(a[3]), "r"(b[0]), "r"(b[1]));
}
__device__ __forceinline__ uint32_t bfpack(float a, float b) {
    __nv_bfloat162 t = __floats2bfloat162_rn(a, b);
    return *reinterpret_cast<uint32_t*>(&t);
}
__device__ __forceinline__ float bfhi(float v) {
    return __bfloat162float(__float2bfloat16(v));
}
__device__ __forceinline__ float fexp(float x) {
    float y = fmaxf(x * 1.4426950408889634f, -125.0f);
    float r = rintf(y);
    float f = y - r;
    float p = 1.3333558146e-3f;
    p = fmaf(p, f, 9.6181291076e-3f);
    p = fmaf(p, f, 5.5504108665e-2f);
    p = fmaf(p, f, 2.4022650696e-1f);
    p = fmaf(p, f, 6.9314718056e-1f);
    p = fmaf(p, f, 1.0f);
    return __int_as_float(__float_as_int(p) + (((int)r) << 23));
}

// ---------------- weight split (streaming, MLP=4) ----------------
__global__ void wsplit(const float* __restrict__ W, bf16* __restrict__ H,
                       bf16* __restrict__ L) {
    const size_t base = ((size_t)blockIdx.x * 4096) + threadIdx.x * 4;
    float4 v[4];
    #pragma unroll
    for (int j = 0; j < 4; ++j) v[j] = *(const float4*)&W[base + j * 1024];
    #pragma unroll
    for (int j = 0; j < 4; ++j) {
        uint2 hh, ll;
        hh.x = bfpack(v[j].x, v[j].y); hh.y = bfpack(v[j].z, v[j].w);
        ll.x = bfpack(v[j].x - bfhi(v[j].x), v[j].y - bfhi(v[j].y));
        ll.y = bfpack(v[j].z - bfhi(v[j].z), v[j].w - bfhi(v[j].w));
        *(uint2*)&H[base + j * 1024] = hh;
        *(uint2*)&L[base + j * 1024] = ll;
    }
}

// ---------------- LayerNorm -> bf16 hi/lo ----------------
__global__ void ln_kernel(const float* __restrict__ x, const float* __restrict__ g,
                          const float* __restrict__ b, bf16* __restrict__ yh,
                          bf16* __restrict__ yl) {
    const int row = blockIdx.x, tid = threadIdx.x;
    const float4 xv = *(const float4*)&x[(size_t)row * D_MODEL + tid * 4];
    float s  = (xv.x + xv.y) + (xv.z + xv.w);
    float s2 = (xv.x * xv.x + xv.y * xv.y) + (xv.z * xv.z + xv.w * xv.w);
    __shared__ float red0[8], red1[8];
    #pragma unroll
    for (int o = 16; o > 0; o >>= 1) {
        s  += __shfl_down_sync(0xffffffffu, s, o);
        s2 += __shfl_down_sync(0xffffffffu, s2, o);
    }
    const int w = tid >> 5, l = tid & 31;
    if (l == 0) { red0[w] = s; red1[w] = s2; }
    __syncthreads();
    if (w == 0) {
        s  = (l < 8) ? red0[l] : 0.f;
        s2 = (l < 8) ? red1[l] : 0.f;
        #pragma unroll
        for (int o = 4; o > 0; o >>= 1) {
            s  += __shfl_down_sync(0xffffffffu, s, o);
            s2 += __shfl_down_sync(0xffffffffu, s2, o);
        }
        if (l == 0) { red0[0] = s; red1[0] = s2; }
    }
    __syncthreads();
    const float mu  = red0[0] * (1.f / D_MODEL);
    const float var = red1[0] * (1.f / D_MODEL) - mu * mu;
    const float inv = rsqrtf(var + 1e-5f);
    const float4 gv = *(const float4*)&g[tid * 4];
    const float4 bv = *(const float4*)&b[tid * 4];
    float o0 = (xv.x - mu) * inv * gv.x + bv.x;
    float o1 = (xv.y - mu) * inv * gv.y + bv.y;
    float o2 = (xv.z - mu) * inv * gv.z + bv.z;
    float o3 = (xv.w - mu) * inv * gv.w + bv.w;
    uint2 H, L;
    H.x = bfpack(o0, o1); H.y = bfpack(o2, o3);
    L.x = bfpack(o0 - bfhi(o0), o1 - bfhi(o1));
    L.y = bfpack(o2 - bfhi(o2), o3 - bfhi(o3));
    *(uint2*)&yh[(size_t)row * D_MODEL + tid * 4] = H;
    *(uint2*)&yl[(size_t)row * D_MODEL + tid * 4] = L;
}

// ---------------- bf16x3 mma GEMM with ldmatrix ----------------
#define ARR_A 10240

template<int ACT, bool HAS_RES, bool OUT_HILO, int BN>
__global__ void __launch_bounds__(256, 2)
bgemm(const bf16* __restrict__ Ah, const bf16* __restrict__ Al,
      const bf16* __restrict__ W0h, const bf16* __restrict__ W0l,
      const bf16* __restrict__ W1h, const bf16* __restrict__ W1l,
      const bf16* __restrict__ W2h, const bf16* __restrict__ W2l,
      const float* __restrict__ b0, const float* __restrict__ b1, const float* __restrict__ b2,
      const float* __restrict__ Res,
      void* __restrict__ C0, void* __restrict__ C1, void* __restrict__ C2,
      void* __restrict__ Clo,
      int N, int K) {
    constexpr int B_STR = BN * 2 + 16;
    constexpr int ARR_B = 32 * B_STR;
    constexpr int STAGE = 2 * ARR_A + 2 * ARR_B;
    constexpr int NT = BN / 16;
    constexpr int NPAIR = NT / 2;
    constexpr int NS = (BN == 64) ? 3 : 2;     // pipeline depth

    extern __shared__ char smem[];
    const int z = blockIdx.z;
    const bf16* Wh    = (z == 0) ? W0h : (z == 1) ? W1h : W2h;
    const bf16* Wl    = (z == 0) ? W0l : (z == 1) ? W1l : W2l;
    const float* bias = (z == 0) ? b0 : (z == 1) ? b1 : b2;
    void* Cv          = (z == 0) ? C0 : (z == 1) ? C1 : C2;

    const int m0 = blockIdx.y * 128;
    const int n0 = blockIdx.x * BN;
    const int tid = threadIdx.x;
    const int wid = tid >> 5, lane = tid & 31;
    const int wrow = wid & 3, wcol = wid >> 2;
    const int lr = lane >> 2, lc = lane & 3;
    const int lrow = lane & 7, sub = lane >> 3;

    const uint32_t sbase = smem_u32(smem);
    const int NKB = K >> 5;

    const uint32_t aoff = (uint32_t)(wrow * 32 + lrow + 8 * (sub & 1)) * 80u + 16u * (sub >> 1);
    const uint32_t boff = (uint32_t)(lrow + 8 * (sub & 1)) * (uint32_t)B_STR +
                          (uint32_t)(wcol * (BN / 2) + 8 * (sub >> 1)) * 2u;

    auto load_stage = [&](int kb, int s) {
        const int k0 = kb << 5;
        const uint32_t st = sbase + s * STAGE;
        #pragma unroll
        for (int f = tid; f < 512; f += 256) {
            const int r = f >> 2, cc = f & 3;
            const uint32_t doff = (uint32_t)r * 80u + (uint32_t)cc * 16u;
            const size_t go = (size_t)(m0 + r) * K + k0 + cc * 8;
            cp16(st + doff, Ah + go);
            cp16(st + ARR_A + doff, Al + go);
        }
        #pragma unroll
        for (int f = tid; f < 32 * (BN / 8); f += 256) {
            const int r = f / (BN / 8), cc = f % (BN / 8);
            const uint32_t doff = (uint32_t)r * (uint32_t)B_STR + (uint32_t)cc * 16u;
            const size_t go = (size_t)(k0 + r) * N + n0 + cc * 8;
            cp16(st + 2 * ARR_A + doff, Wh + go);
            cp16(st + 2 * ARR_A + ARR_B + doff, Wl + go);
        }
    };

    float acc[2][NT][4];
    #pragma unroll
    for (int mt = 0; mt < 2; ++mt)
        #pragma unroll
        for (int nt = 0; nt < NT; ++nt)
            #pragma unroll
            for (int i = 0; i < 4; ++i) acc[mt][nt][i] = 0.f;

    auto domma = [&](int s) {
        const uint32_t stg = sbase + s * STAGE;
        #pragma unroll
        for (int kstep = 0; kstep < 2; ++kstep) {
            uint32_t ah[2][4], al[2][4];
            #pragma unroll
            for (int mt = 0; mt < 2; ++mt) {
                ldsm4(ah[mt], stg + aoff + mt * 1280 + kstep * 32);
                ldsm4(al[mt], stg + ARR_A + aoff + mt * 1280 + kstep * 32);
            }
            uint32_t bh[NT][2], bl[NT][2];
            #pragma unroll
            for (int p = 0; p < NPAIR; ++p) {
                uint32_t t[4];
                ldsm4t(t, stg + 2 * ARR_A + boff + p * 32 + kstep * 16 * B_STR);
                bh[2 * p][0] = t[0]; bh[2 * p][1] = t[1];
                bh[2 * p + 1][0] = t[2]; bh[2 * p + 1][1] = t[3];
                ldsm4t(t, stg + 2 * ARR_A + ARR_B + boff + p * 32 + kstep * 16 * B_STR);
                bl[2 * p][0] = t[0]; bl[2 * p][1] = t[1];
                bl[2 * p + 1][0] = t[2]; bl[2 * p + 1][1] = t[3];
            }
            #pragma unroll
            for (int nt = 0; nt < NT; ++nt) {
                mma_bf16(acc[0][nt], ah[0], bh[nt]);
                mma_bf16(acc[1][nt], ah[1], bh[nt]);
                mma_bf16(acc[0][nt], al[0], bh[nt]);
                mma_bf16(acc[1][nt], al[1], bh[nt]);
                mma_bf16(acc[0][nt], ah[0], bl[nt]);
                mma_bf16(acc[1][nt], ah[1], bl[nt]);
            }
        }
    };

    if (NS == 3) {
        load_stage(0, 0); CP_COMMIT();
        load_stage(1, 1); CP_COMMIT();
        int sc = 0;
        for (int kb = 0; kb < NKB; ++kb) {
            CP_WAIT(1);
            __syncthreads();
            if (kb + 2 < NKB) load_stage(kb + 2, (sc + 2) % 3);
            CP_COMMIT();
            domma(sc);
            sc = (sc == 2) ? 0 : sc + 1;
        }
    } else {
        load_stage(0, 0); CP_COMMIT();
        for (int kb = 0; kb < NKB; ++kb) {
            const int s = kb & 1;
            if (kb + 1 < NKB) {
                load_stage(kb + 1, s ^ 1);
                CP_COMMIT();
                CP_WAIT(1);
            } else {
                CP_WAIT(0);
            }
            __syncthreads();
            domma(s);
            __syncthreads();
        }
    }

    // epilogue
    #pragma unroll
    for (int nt = 0; nt < NT; ++nt) {
        const int col = n0 + wcol * (BN / 2) + nt * 8 + lc * 2;
        const float2 bv = *(const float2*)&bias[col];
        #pragma unroll
        for (int mt = 0; mt < 2; ++mt) {
            const int row = m0 + wrow * 32 + mt * 16 + lr;
            #pragma unroll
            for (int half = 0; half < 2; ++half) {
                const int r = row + half * 8;
                float vx = acc[mt][nt][half * 2 + 0] + bv.x;
                float vy = acc[mt][nt][half * 2 + 1] + bv.y;
                if (ACT == 1) {
                    vx = 0.5f * vx * (1.0f + erff(vx * 0.7071067811865475f));
                    vy = 0.5f * vy * (1.0f + erff(vy * 0.7071067811865475f));
                }
                if (HAS_RES) {
                    float2 rv = *(const float2*)&Res[(size_t)r * N + col];
                    vx += rv.x; vy += rv.y;
                }
                if (OUT_HILO) {
                    bf16* Ch = (bf16*)Cv;
                    bf16* Cl = (bf16*)Clo;
                    *(uint32_t*)&Ch[(size_t)r * N + col] = bfpack(vx, vy);
                    *(uint32_t*)&Cl[(size_t)r * N + col] =
                        bfpack(vx - bfhi(vx), vy - bfhi(vy));
                } else {
                    float2 o; o.x = vx; o.y = vy;
                    *(float2*)&((float*)Cv)[(size_t)r * N + col] = o;
                }
            }
        }
    }
}

// ---------------- flash attention, 512 threads (16 warps, 4x4) ----------------
#define AT_QS   0
#define AT_KS   (128 * 68)
#define AT_VST  (AT_KS + 128 * 68)
#define AT_SS   (AT_VST + 64 * 132)
#define AT_MST  (AT_SS + 128 * 132)
#define AT_FLOATS (AT_MST + 3 * 128)
#define SMEM_ATTN (AT_FLOATS * 4)

__global__ void __launch_bounds__(512, 1)
attn_mma(const float* __restrict__ Q, const float* __restrict__ K,
         const float* __restrict__ V, bf16* __restrict__ OH, bf16* __restrict__ OL) {
    extern __shared__ float sm[];
    float* Qs   = sm + AT_QS;
    float* Ks   = sm + AT_KS;
    float* VsT  = sm + AT_VST;
    float* Ss   = sm + AT_SS;
    float* m_sh = sm + AT_MST;
    float* l_sh = m_sh + 128;
    float* a_sh = l_sh + 128;

    const int qb = gridDim.x - 1 - blockIdx.x;
    const int h  = blockIdx.y;
    const int tid = threadIdx.x;
    const int wid = tid >> 5, lane = tid & 31;
    const int lr = lane >> 2, lc = lane & 3;
    const int wrow = wid & 3, wcol = wid >> 2;   // 4 x 4 warps

    #pragma unroll
    for (int i = 0; i < 4; ++i) {
        int f = tid + i * 512;
        int r = f >> 4, c4 = (f & 15) << 2;
        float4 v = *(const float4*)&Q[(size_t)(qb * 128 + r) * D_MODEL + h * 64 + c4];
        float* dst = &Qs[r * 68 + c4];
        dst[0] = v.x * 0.125f; dst[1] = v.y * 0.125f;
        dst[2] = v.z * 0.125f; dst[3] = v.w * 0.125f;
    }
    if (tid < 128) { m_sh[tid] = -1e30f; l_sh[tid] = 0.f; }

    float o_acc[2][2][4] = {};
    const float slope = exp2f(-0.5f * (float)(h + 1));

    for (int kb = 0; kb <= qb; ++kb) {
        __syncthreads();
        #pragma unroll
        for (int i = 0; i < 4; ++i) {
            int f = tid + i * 512;
            int r = f >> 4, c4 = (f & 15) << 2;
            float4 v = *(const float4*)&K[(size_t)(kb * 128 + r) * D_MODEL + h * 64 + c4];
            float* dst = &Ks[r * 68 + c4];
            dst[0] = v.x; dst[1] = v.y; dst[2] = v.z; dst[3] = v.w;
        }
        {
            const int d = tid & 63, k0 = tid >> 6;   // k0: 0..7
            const float* vp = V + (size_t)(kb * 128 + k0) * D_MODEL + h * 64 + d;
            #pragma unroll
            for (int i = 0; i < 16; ++i)
                VsT[d * 132 + k0 + i * 8] = vp[(size_t)i * 8 * D_MODEL];
        }
        __syncthreads();

        // S = Q @ K^T: warp tile 32 rows x 32 cols
        float s_acc[2][4][4] = {};
        #pragma unroll
        for (int ks = 0; ks < 8; ++ks) {
            uint32_t a[2][4];
            const int c = ks * 8 + lc;
            #pragma unroll
            for (int mt = 0; mt < 2; ++mt) {
                const int r = wrow * 32 + mt * 16 + lr;
                a[mt][0] = __float_as_uint(Qs[r * 68 + c]);
                a[mt][1] = __float_as_uint(Qs[(r + 8) * 68 + c]);
                a[mt][2] = __float_as_uint(Qs[r * 68 + c + 4]);
                a[mt][3] = __float_as_uint(Qs[(r + 8) * 68 + c + 4]);
            }
            #pragma unroll
            for (int nt = 0; nt < 4; ++nt) {
                const int n = wcol * 32 + nt * 8 + lr;
                uint32_t b[2];
                b[0] = __float_as_uint(Ks[n * 68 + c]);
                b[1] = __float_as_uint(Ks[n * 68 + c + 4]);
                mma_tf32(s_acc[0][nt], a[0], b);
                mma_tf32(s_acc[1][nt], a[1], b);
            }
        }
        #pragma unroll
        for (int mt = 0; mt < 2; ++mt) {
            const int r = wrow * 32 + mt * 16 + lr;
            #pragma unroll
            for (int nt = 0; nt < 4; ++nt) {
                const int col = wcol * 32 + nt * 8 + 2 * lc;
                float2 v0; v0.x = s_acc[mt][nt][0]; v0.y = s_acc[mt][nt][1];
                float2 v1; v1.x = s_acc[mt][nt][2]; v1.y = s_acc[mt][nt][3];
                *(float2*)&Ss[r * 132 + col] = v0;
                *(float2*)&Ss[(r + 8) * 132 + col] = v1;
            }
        }
        __syncthreads();

        // online softmax: 4 threads per row, 32 cols each
        {
            const int row = tid >> 2, quarter = tid & 3;
            const int qq = qb * 128 + row;
            const int colbase = quarter * 32;
            float mx = -1e30f;
            #pragma unroll
            for (int c4 = 0; c4 < 32; c4 += 4) {
                float4 s4 = *(float4*)&Ss[row * 132 + colbase + c4];
                const int kk = kb * 128 + colbase + c4;
                s4.x = (kk     <= qq) ? fmaf(slope, (float)(kk     - qq), s4.x) : -1e30f;
                s4.y = (kk + 1 <= qq) ? fmaf(slope, (float)(kk + 1 - qq), s4.y) : -1e30f;
                s4.z = (kk + 2 <= qq) ? fmaf(slope, (float)(kk + 2 - qq), s4.z) : -1e30f;
                s4.w = (kk + 3 <= qq) ? fmaf(slope, (float)(kk + 3 - qq), s4.w) : -1e30f;
                *(float4*)&Ss[row * 132 + colbase + c4] = s4;
                mx = fmaxf(mx, fmaxf(fmaxf(s4.x, s4.y), fmaxf(s4.z, s4.w)));
            }
            mx = fmaxf(mx, __shfl_xor_sync(0xffffffffu, mx, 1));
            mx = fmaxf(mx, __shfl_xor_sync(0xffffffffu, mx, 2));
            const float m_old = m_sh[row];
            const float m_new = fmaxf(m_old, mx);
            float sum = 0.f;
            #pragma unroll
            for (int c4 = 0; c4 < 32; c4 += 4) {
                float4 s4 = *(float4*)&Ss[row * 132 + colbase + c4];
                s4.x = fexp(s4.x - m_new); s4.y = fexp(s4.y - m_new);
                s4.z = fexp(s4.z - m_new); s4.w = fexp(s4.w - m_new);
                *(float4*)&Ss[row * 132 + colbase + c4] = s4;
                sum += (s4.x + s4.y) + (s4.z + s4.w);
            }
            sum += __shfl_xor_sync(0xffffffffu, sum, 1);
            sum += __shfl_xor_sync(0xffffffffu, sum, 2);
            if (quarter == 0) {
                const float alpha = fexp(m_old - m_new);
                m_sh[row] = m_new;
                l_sh[row] = l_sh[row] * alpha + sum;
                a_sh[row] = alpha;
            }
        }
        __syncthreads();

        // rescale O, then O += P @ V : warp tile 32 rows x 16 cols
        #pragma unroll
        for (int mt = 0; mt < 2; ++mt) {
            const float a0 = a_sh[wrow * 32 + mt * 16 + lr];
            const float a1 = a_sh[wrow * 32 + mt * 16 + lr + 8];
            #pragma unroll
            for (int nt = 0; nt < 2; ++nt) {
                o_acc[mt][nt][0] *= a0; o_acc[mt][nt][1] *= a0;
                o_acc[mt][nt][2] *= a1; o_acc[mt][nt][3] *= a1;
            }
        }
        #pragma unroll
        for (int ks = 0; ks < 16; ++ks) {
            uint32_t a[2][4];
            const int c = ks * 8 + lc;
            #pragma unroll
            for (int mt = 0; mt < 2; ++mt) {
                const int r = wrow * 32 + mt * 16 + lr;
                a[mt][0] = __float_as_uint(Ss[r * 132 + c]);
                a[mt][1] = __float_as_uint(Ss[(r + 8) * 132 + c]);
                a[mt][2] = __float_as_uint(Ss[r * 132 + c + 4]);
                a[mt][3] = __float_as_uint(Ss[(r + 8) * 132 + c + 4]);
            }
            #pragma unroll
            for (int nt = 0; nt < 2; ++nt) {
                const int n = wcol * 16 + nt * 8 + lr;
                uint32_t b[2];
                b[0] = __float_as_uint(VsT[n * 132 + c]);
                b[1] = __float_as_uint(VsT[n * 132 + c + 4]);
                mma_tf32(o_acc[0][nt], a[0], b);
                mma_tf32(o_acc[1][nt], a[1], b);
            }
        }
    }

    #pragma unroll
    for (int mt = 0; mt < 2; ++mt) {
        const int r = wrow * 32 + mt * 16 + lr;
        const float inv0 = 1.f / l_sh[r];
        const float inv1 = 1.f / l_sh[r + 8];
        #pragma unroll
        for (int nt = 0; nt < 2; ++nt) {
            const int col = h * 64 + wcol * 16 + nt * 8 + 2 * lc;
            float v0x = o_acc[mt][nt][0] * inv0, v0y = o_acc[mt][nt][1] * inv0;
            float v1x = o_acc[mt][nt][2] * inv1, v1y = o_acc[mt][nt][3] * inv1;
            size_t i0 = (size_t)(qb * 128 + r) * D_MODEL + col;
            size_t i1 = (size_t)(qb * 128 + r + 8) * D_MODEL + col;
            *(uint32_t*)&OH[i0] = bfpack(v0x, v0y);
            *(uint32_t*)&OL[i0] = bfpack(v0x - bfhi(v0x), v0y - bfhi(v0y));
            *(uint32_t*)&OH[i1] = bfpack(v1x, v1y);
            *(uint32_t*)&OL[i1] = bfpack(v1x - bfhi(v1x), v1y - bfhi(v1y));
        }
    }
}

// ---------------- launch ----------------
extern "C" void kernel_launch(void* const* d_in, const int* in_sizes, int n_in,
                              void* d_out, int out_size) {
    const float* x   = (const float*)d_in[0];
    const float* wq  = (const float*)d_in[3];
    const float* bq  = (const float*)d_in[4];
    const float* wk  = (const float*)d_in[5];
    const float* bk  = (const float*)d_in[6];
    const float* wv  = (const float*)d_in[7];
    const float* bv  = (const float*)d_in[8];
    const float* wo  = (const float*)d_in[9];
    const float* bo  = (const float*)d_in[10];
    const float* w1  = (const float*)d_in[11];
    const float* b1  = (const float*)d_in[12];
    const float* w2  = (const float*)d_in[13];
    const float* b2  = (const float*)d_in[14];
    const float* g1  = (const float*)d_in[15];
    const float* be1 = (const float*)d_in[16];
    const float* g2  = (const float*)d_in[17];
    const float* be2 = (const float*)d_in[18];
    float* out = (float*)d_out;

    float *p_q, *p_k, *p_v, *p_x1;
    bf16 *p_xnh, *p_xnl, *p_ah, *p_al, *p_hh, *p_hl;
    bf16 *p_wqh, *p_wql, *p_wkh, *p_wkl, *p_wvh, *p_wvl, *p_woh, *p_wol;
    bf16 *p_w1h, *p_w1l, *p_w2h, *p_w2l;
    cudaGetSymbolAddress((void**)&p_q,   g_q);
    cudaGetSymbolAddress((void**)&p_k,   g_k);
    cudaGetSymbolAddress((void**)&p_v,   g_v);
    cudaGetSymbolAddress((void**)&p_x1,  g_x1);
    cudaGetSymbolAddress((void**)&p_xnh, g_xnh);
    cudaGetSymbolAddress((void**)&p_xnl, g_xnl);
    cudaGetSymbolAddress((void**)&p_ah,  g_ah);
    cudaGetSymbolAddress((void**)&p_al,  g_al);
    cudaGetSymbolAddress((void**)&p_hh,  g_hh);
    cudaGetSymbolAddress((void**)&p_hl,  g_hl);
    cudaGetSymbolAddress((void**)&p_wqh, g_wqh);
    cudaGetSymbolAddress((void**)&p_wql, g_wql);
    cudaGetSymbolAddress((void**)&p_wkh, g_wkh);
    cudaGetSymbolAddress((void**)&p_wkl, g_wkl);
    cudaGetSymbolAddress((void**)&p_wvh, g_wvh);
    cudaGetSymbolAddress((void**)&p_wvl, g_wvl);
    cudaGetSymbolAddress((void**)&p_woh, g_woh);
    cudaGetSymbolAddress((void**)&p_wol, g_wol);
    cudaGetSymbolAddress((void**)&p_w1h, g_w1h);
    cudaGetSymbolAddress((void**)&p_w1l, g_w1l);
    cudaGetSymbolAddress((void**)&p_w2h, g_w2h);
    cudaGetSymbolAddress((void**)&p_w2l, g_w2l);

    const int smem64  = 3 * (2 * ARR_A + 2 * 32 * (64 * 2 + 16));    // 89088 (3-stage)
    const int smem128 = 2 * (2 * ARR_A + 2 * 32 * (128 * 2 + 16));   // 75776 (2-stage)

    cudaFuncSetAttribute(bgemm<0, false, false, 64>,  cudaFuncAttributeMaxDynamicSharedMemorySize, smem64);
    cudaFuncSetAttribute(bgemm<0, true,  false, 64>,  cudaFuncAttributeMaxDynamicSharedMemorySize, smem64);
    cudaFuncSetAttribute(bgemm<1, false, true,  128>, cudaFuncAttributeMaxDynamicSharedMemorySize, smem128);
    cudaFuncSetAttribute(attn_mma, cudaFuncAttributeMaxDynamicSharedMemorySize, SMEM_ATTN);

    // weight splits (MLP=4 streaming)
    wsplit<<<D_MODEL * D_MODEL / 4096, 256>>>(wq, p_wqh, p_wql);
    wsplit<<<D_MODEL * D_MODEL / 4096, 256>>>(wk, p_wkh, p_wkl);
    wsplit<<<D_MODEL * D_MODEL / 4096, 256>>>(wv, p_wvh, p_wvl);
    wsplit<<<D_MODEL * D_MODEL / 4096, 256>>>(wo, p_woh, p_wol);
    wsplit<<<D_MODEL * FFN_DIM / 4096, 256>>>(w1, p_w1h, p_w1l);
    wsplit<<<D_MODEL * FFN_DIM / 4096, 256>>>(w2, p_w2h, p_w2l);

    // LN1
    ln_kernel<<<T_SEQ, 256>>>(x, g1, be1, p_xnh, p_xnl);

    // fused QKV (BN=64, 3-stage)
    bgemm<0, false, false, 64><<<dim3(D_MODEL / 64, T_SEQ / 128, 3), 256, smem64>>>(
        p_xnh, p_xnl, p_wqh, p_wql, p_wkh, p_wkl, p_wvh, p_wvl,
        bq, bk, bv, nullptr, p_q, p_k, p_v, nullptr, D_MODEL, D_MODEL);

    // attention (512 threads)
    attn_mma<<<dim3(T_SEQ / 128, N_HEADS), 512, SMEM_ATTN>>>(p_q, p_k, p_v, p_ah, p_al);

    // O projection + residual(x)
    bgemm<0, true, false, 64><<<dim3(D_MODEL / 64, T_SEQ / 128, 1), 256, smem64>>>(
        p_ah, p_al, p_woh, p_wol, p_woh, p_wol, p_woh, p_wol,
        bo, bo, bo, x, p_x1, p_x1, p_x1, nullptr, D_MODEL, D_MODEL);

    // LN2
    ln_kernel<<<T_SEQ, 256>>>(p_x1, g2, be2, p_xnh, p_xnl);

    // FFN1 + GELU (BN=128, 2-stage)
    bgemm<1, false, true, 128><<<dim3(FFN_DIM / 128, T_SEQ / 128, 1), 256, smem128>>>(
        p_xnh, p_xnl, p_w1h, p_w1l, p_w1h, p_w1l, p_w1h, p_w1l,
        b1, b1, b1, nullptr, p_hh, p_hh, p_hh, p_hl, FFN_DIM, D_MODEL);

    // FFN2 + residual(x1)
    bgemm<0, true, false, 64><<<dim3(D_MODEL / 64, T_SEQ / 128, 1), 256, smem64>>>(
        p_hh, p_hl, p_w2h, p_w2l, p_w2h, p_w2l, p_w2h, p_w2l,
        b2, b2, b2, p_x1, out, out, out, nullptr, D_MODEL, FFN_DIM);
}

// round 8
// speedup vs baseline: 1.0192x; 1.0192x over previous
#include <cuda_runtime.h>
#include <cuda_bf16.h>
#include <math.h>
#include <stdint.h>

#define T_SEQ 2048
#define D_MODEL 1024
#define N_HEADS 16
#define HEAD_DIM 64
#define FFN_DIM 4096
typedef __nv_bfloat16 bf16;

// ---------------- scratch ----------------
__device__ float g_q[T_SEQ * D_MODEL];
__device__ float g_k[T_SEQ * D_MODEL];
__device__ float g_v[T_SEQ * D_MODEL];
__device__ float g_x1[T_SEQ * D_MODEL];
__device__ bf16  g_xnh[T_SEQ * D_MODEL];
__device__ bf16  g_xnl[T_SEQ * D_MODEL];
__device__ bf16  g_ah[T_SEQ * D_MODEL];
__device__ bf16  g_al[T_SEQ * D_MODEL];
__device__ bf16  g_hh[T_SEQ * FFN_DIM];
__device__ bf16  g_hl[T_SEQ * FFN_DIM];
__device__ bf16 g_wqh[D_MODEL * D_MODEL], g_wql[D_MODEL * D_MODEL];
__device__ bf16 g_wkh[D_MODEL * D_MODEL], g_wkl[D_MODEL * D_MODEL];
__device__ bf16 g_wvh[D_MODEL * D_MODEL], g_wvl[D_MODEL * D_MODEL];
__device__ bf16 g_woh[D_MODEL * D_MODEL], g_wol[D_MODEL * D_MODEL];
__device__ bf16 g_w1h[FFN_DIM * D_MODEL], g_w1l[FFN_DIM * D_MODEL];
__device__ bf16 g_w2h[D_MODEL * FFN_DIM], g_w2l[D_MODEL * FFN_DIM];

// ---------------- helpers ----------------
__device__ __forceinline__ uint32_t smem_u32(const void* p) {
    uint32_t a;
    asm("{ .reg .u64 t; cvta.to.shared.u64 t, %1; cvt.u32.u64 %0, t; }" : "=r"(a) : "l"(p));
    return a;
}
__device__ __forceinline__ void cp16(uint32_t s, const void* g) {
    asm volatile("cp.async.cg.shared.global [%0], [%1], 16;" :: "r"(s), "l"(g));
}
#define CP_COMMIT() asm volatile("cp.async.commit_group;" ::: "memory")
#define CP_WAIT(n)  asm volatile("cp.async.wait_group %0;" :: "n"(n) : "memory")

__device__ __forceinline__ void ldsm4(uint32_t* r, uint32_t addr) {
    asm volatile("ldmatrix.sync.aligned.m8n8.x4.shared.b16 {%0,%1,%2,%3}, [%4];"
        : "=r"(r[0]), "=r"(r[1]), "=r"(r[2]), "=r"(r[3]) : "r"(addr));
}
__device__ __forceinline__ void ldsm4t(uint32_t* r, uint32_t addr) {
    asm volatile("ldmatrix.sync.aligned.m8n8.x4.trans.shared.b16 {%0,%1,%2,%3}, [%4];"
        : "=r"(r[0]), "=r"(r[1]), "=r"(r[2]), "=r"(r[3]) : "r"(addr));
}
__device__ __forceinline__ void mma_bf16(float* d, const uint32_t* a, const uint32_t* b) {
    asm volatile(
        "mma.sync.aligned.m16n8k16.row.col.f32.bf16.bf16.f32 "
        "{%0,%1,%2,%3}, {%4,%5,%6,%7}, {%8,%9}, {%0,%1,%2,%3};"
        : "+f"(d[0]), "+f"(d[1]), "+f"(d[2]), "+f"(d[3])
        : "r"(a[0]), "r"(a[1]), "r"(a[2]), "r"(a[3]), "r"(b[0]), "r"(b[1]));
}
__device__ __forceinline__ void mma_tf32(float* d, const uint32_t* a, const uint32_t* b) {
    asm volatile(
        "mma.sync.aligned.m16n8k8.row.col.f32.tf32.tf32.f32 "
        "{%0,%1,%2,%3}, {%4,%5,%6,%7}, {%8,%9}, {%0,%1,%2,%3};"
        : "+f"(d[0]), "+f"(d[1]), "+f"(d[2]), "+f"(d[3])
        : "r"(a[0]), "r"(a[1]), "r"(a[2]), "r"(a[3]), "r"(b[0]), "r"(b[1]));
}
__device__ __forceinline__ uint32_t bfpack(float a, float b) {
    __nv_bfloat162 t = __floats2bfloat162_rn(a, b);
    return *reinterpret_cast<uint32_t*>(&t);
}
__device__ __forceinline__ float bfhi(float v) {
    return __bfloat162float(__float2bfloat16(v));
}
__device__ __forceinline__ float fexp(float x) {
    float y = fmaxf(x * 1.4426950408889634f, -125.0f);
    float r = rintf(y);
    float f = y - r;
    float p = 1.3333558146e-3f;
    p = fmaf(p, f, 9.6181291076e-3f);
    p = fmaf(p, f, 5.5504108665e-2f);
    p = fmaf(p, f, 2.4022650696e-1f);
    p = fmaf(p, f, 6.9314718056e-1f);
    p = fmaf(p, f, 1.0f);
    return __int_as_float(__float_as_int(p) + (((int)r) << 23));
}

// ---------------- batched weight splits ----------------
// 4 x [1024x1024] matrices, blockIdx.y selects
__global__ void wsplit4(const float* __restrict__ Wq, const float* __restrict__ Wk,
                        const float* __restrict__ Wv, const float* __restrict__ Wo,
                        bf16* __restrict__ Hq, bf16* __restrict__ Lq,
                        bf16* __restrict__ Hk, bf16* __restrict__ Lk,
                        bf16* __restrict__ Hv, bf16* __restrict__ Lv,
                        bf16* __restrict__ Ho, bf16* __restrict__ Lo) {
    const int m = blockIdx.y;
    const float* W = (m == 0) ? Wq : (m == 1) ? Wk : (m == 2) ? Wv : Wo;
    bf16* H = (m == 0) ? Hq : (m == 1) ? Hk : (m == 2) ? Hv : Ho;
    bf16* L = (m == 0) ? Lq : (m == 1) ? Lk : (m == 2) ? Lv : Lo;
    const size_t base = ((size_t)blockIdx.x * 4096) + threadIdx.x * 4;
    float4 v[4];
    #pragma unroll
    for (int j = 0; j < 4; ++j) v[j] = *(const float4*)&W[base + j * 1024];
    #pragma unroll
    for (int j = 0; j < 4; ++j) {
        uint2 hh, ll;
        hh.x = bfpack(v[j].x, v[j].y); hh.y = bfpack(v[j].z, v[j].w);
        ll.x = bfpack(v[j].x - bfhi(v[j].x), v[j].y - bfhi(v[j].y));
        ll.y = bfpack(v[j].z - bfhi(v[j].z), v[j].w - bfhi(v[j].w));
        *(uint2*)&H[base + j * 1024] = hh;
        *(uint2*)&L[base + j * 1024] = ll;
    }
}
// 2 x [1024x4096] matrices
__global__ void wsplit2(const float* __restrict__ W1, const float* __restrict__ W2,
                        bf16* __restrict__ H1, bf16* __restrict__ L1,
                        bf16* __restrict__ H2, bf16* __restrict__ L2) {
    const int m = blockIdx.y;
    const float* W = (m == 0) ? W1 : W2;
    bf16* H = (m == 0) ? H1 : H2;
    bf16* L = (m == 0) ? L1 : L2;
    const size_t base = ((size_t)blockIdx.x * 4096) + threadIdx.x * 4;
    float4 v[4];
    #pragma unroll
    for (int j = 0; j < 4; ++j) v[j] = *(const float4*)&W[base + j * 1024];
    #pragma unroll
    for (int j = 0; j < 4; ++j) {
        uint2 hh, ll;
        hh.x = bfpack(v[j].x, v[j].y); hh.y = bfpack(v[j].z, v[j].w);
        ll.x = bfpack(v[j].x - bfhi(v[j].x), v[j].y - bfhi(v[j].y));
        ll.y = bfpack(v[j].z - bfhi(v[j].z), v[j].w - bfhi(v[j].w));
        *(uint2*)&H[base + j * 1024] = hh;
        *(uint2*)&L[base + j * 1024] = ll;
    }
}

// ---------------- LayerNorm -> bf16 hi/lo ----------------
__global__ void ln_kernel(const float* __restrict__ x, const float* __restrict__ g,
                          const float* __restrict__ b, bf16* __restrict__ yh,
                          bf16* __restrict__ yl) {
    const int row = blockIdx.x, tid = threadIdx.x;
    const float4 xv = *(const float4*)&x[(size_t)row * D_MODEL + tid * 4];
    float s  = (xv.x + xv.y) + (xv.z + xv.w);
    float s2 = (xv.x * xv.x + xv.y * xv.y) + (xv.z * xv.z + xv.w * xv.w);
    __shared__ float red0[8], red1[8];
    #pragma unroll
    for (int o = 16; o > 0; o >>= 1) {
        s  += __shfl_down_sync(0xffffffffu, s, o);
        s2 += __shfl_down_sync(0xffffffffu, s2, o);
    }
    const int w = tid >> 5, l = tid & 31;
    if (l == 0) { red0[w] = s; red1[w] = s2; }
    __syncthreads();
    if (w == 0) {
        s  = (l < 8) ? red0[l] : 0.f;
        s2 = (l < 8) ? red1[l] : 0.f;
        #pragma unroll
        for (int o = 4; o > 0; o >>= 1) {
            s  += __shfl_down_sync(0xffffffffu, s, o);
            s2 += __shfl_down_sync(0xffffffffu, s2, o);
        }
        if (l == 0) { red0[0] = s; red1[0] = s2; }
    }
    __syncthreads();
    const float mu  = red0[0] * (1.f / D_MODEL);
    const float var = red1[0] * (1.f / D_MODEL) - mu * mu;
    const float inv = rsqrtf(var + 1e-5f);
    const float4 gv = *(const float4*)&g[tid * 4];
    const float4 bv = *(const float4*)&b[tid * 4];
    float o0 = (xv.x - mu) * inv * gv.x + bv.x;
    float o1 = (xv.y - mu) * inv * gv.y + bv.y;
    float o2 = (xv.z - mu) * inv * gv.z + bv.z;
    float o3 = (xv.w - mu) * inv * gv.w + bv.w;
    uint2 H, L;
    H.x = bfpack(o0, o1); H.y = bfpack(o2, o3);
    L.x = bfpack(o0 - bfhi(o0), o1 - bfhi(o1));
    L.y = bfpack(o2 - bfhi(o2), o3 - bfhi(o3));
    *(uint2*)&yh[(size_t)row * D_MODEL + tid * 4] = H;
    *(uint2*)&yl[(size_t)row * D_MODEL + tid * 4] = L;
}

// ---------------- bf16x3 mma GEMM with ldmatrix ----------------
#define ARR_A 10240

template<int ACT, bool HAS_RES, bool OUT_HILO, int BN>
__global__ void __launch_bounds__(256, 2)
bgemm(const bf16* __restrict__ Ah, const bf16* __restrict__ Al,
      const bf16* __restrict__ W0h, const bf16* __restrict__ W0l,
      const bf16* __restrict__ W1h, const bf16* __restrict__ W1l,
      const bf16* __restrict__ W2h, const bf16* __restrict__ W2l,
      const float* __restrict__ b0, const float* __restrict__ b1, const float* __restrict__ b2,
      const float* __restrict__ Res,
      void* __restrict__ C0, void* __restrict__ C1, void* __restrict__ C2,
      void* __restrict__ Clo,
      int N, int K) {
    constexpr int B_STR = BN * 2 + 16;
    constexpr int ARR_B = 32 * B_STR;
    constexpr int STAGE = 2 * ARR_A + 2 * ARR_B;
    constexpr int NT = BN / 16;
    constexpr int NPAIR = NT / 2;
    constexpr int NS = (BN == 64) ? 3 : 2;
    constexpr bool DUAL = (NT <= 4);   // dual accumulators (break RAW chains)

    extern __shared__ char smem[];
    const int z = blockIdx.z;
    const bf16* Wh    = (z == 0) ? W0h : (z == 1) ? W1h : W2h;
    const bf16* Wl    = (z == 0) ? W0l : (z == 1) ? W1l : W2l;
    const float* bias = (z == 0) ? b0 : (z == 1) ? b1 : b2;
    void* Cv          = (z == 0) ? C0 : (z == 1) ? C1 : C2;

    const int m0 = blockIdx.y * 128;
    const int n0 = blockIdx.x * BN;
    const int tid = threadIdx.x;
    const int wid = tid >> 5, lane = tid & 31;
    const int wrow = wid & 3, wcol = wid >> 2;
    const int lr = lane >> 2, lc = lane & 3;
    const int lrow = lane & 7, sub = lane >> 3;

    const uint32_t sbase = smem_u32(smem);
    const int NKB = K >> 5;

    const uint32_t aoff = (uint32_t)(wrow * 32 + lrow + 8 * (sub & 1)) * 80u + 16u * (sub >> 1);
    const uint32_t boff = (uint32_t)(lrow + 8 * (sub & 1)) * (uint32_t)B_STR +
                          (uint32_t)(wcol * (BN / 2) + 8 * (sub >> 1)) * 2u;

    auto load_stage = [&](int kb, int s) {
        const int k0 = kb << 5;
        const uint32_t st = sbase + s * STAGE;
        #pragma unroll
        for (int f = tid; f < 512; f += 256) {
            const int r = f >> 2, cc = f & 3;
            const uint32_t doff = (uint32_t)r * 80u + (uint32_t)cc * 16u;
            const size_t go = (size_t)(m0 + r) * K + k0 + cc * 8;
            cp16(st + doff, Ah + go);
            cp16(st + ARR_A + doff, Al + go);
        }
        #pragma unroll
        for (int f = tid; f < 32 * (BN / 8); f += 256) {
            const int r = f / (BN / 8), cc = f % (BN / 8);
            const uint32_t doff = (uint32_t)r * (uint32_t)B_STR + (uint32_t)cc * 16u;
            const size_t go = (size_t)(k0 + r) * N + n0 + cc * 8;
            cp16(st + 2 * ARR_A + doff, Wh + go);
            cp16(st + 2 * ARR_A + ARR_B + doff, Wl + go);
        }
    };

    float acc[2][NT][4];
    float accx[DUAL ? 2 : 1][DUAL ? NT : 1][4];
    #pragma unroll
    for (int mt = 0; mt < 2; ++mt)
        #pragma unroll
        for (int nt = 0; nt < NT; ++nt)
            #pragma unroll
            for (int i = 0; i < 4; ++i) {
                acc[mt][nt][i] = 0.f;
                if (DUAL) accx[mt][nt][i] = 0.f;
            }

    auto domma = [&](int s) {
        const uint32_t stg = sbase + s * STAGE;
        #pragma unroll
        for (int kstep = 0; kstep < 2; ++kstep) {
            uint32_t ah[2][4], al[2][4];
            #pragma unroll
            for (int mt = 0; mt < 2; ++mt) {
                ldsm4(ah[mt], stg + aoff + mt * 1280 + kstep * 32);
                ldsm4(al[mt], stg + ARR_A + aoff + mt * 1280 + kstep * 32);
            }
            uint32_t bh[NT][2], bl[NT][2];
            #pragma unroll
            for (int p = 0; p < NPAIR; ++p) {
                uint32_t t[4];
                ldsm4t(t, stg + 2 * ARR_A + boff + p * 32 + kstep * 16 * B_STR);
                bh[2 * p][0] = t[0]; bh[2 * p][1] = t[1];
                bh[2 * p + 1][0] = t[2]; bh[2 * p + 1][1] = t[3];
                ldsm4t(t, stg + 2 * ARR_A + ARR_B + boff + p * 32 + kstep * 16 * B_STR);
                bl[2 * p][0] = t[0]; bl[2 * p][1] = t[1];
                bl[2 * p + 1][0] = t[2]; bl[2 * p + 1][1] = t[3];
            }
            #pragma unroll
            for (int nt = 0; nt < NT; ++nt) {
                if (DUAL) {
                    mma_bf16(acc[0][nt],  ah[0], bh[nt]);
                    mma_bf16(acc[1][nt],  ah[1], bh[nt]);
                    mma_bf16(accx[0][nt], al[0], bh[nt]);
                    mma_bf16(accx[1][nt], al[1], bh[nt]);
                    mma_bf16(accx[0][nt], ah[0], bl[nt]);
                    mma_bf16(accx[1][nt], ah[1], bl[nt]);
                } else {
                    mma_bf16(acc[0][nt], ah[0], bh[nt]);
                    mma_bf16(acc[1][nt], ah[1], bh[nt]);
                    mma_bf16(acc[0][nt], al[0], bh[nt]);
                    mma_bf16(acc[1][nt], al[1], bh[nt]);
                    mma_bf16(acc[0][nt], ah[0], bl[nt]);
                    mma_bf16(acc[1][nt], ah[1], bl[nt]);
                }
            }
        }
    };

    if (NS == 3) {
        load_stage(0, 0); CP_COMMIT();
        load_stage(1, 1); CP_COMMIT();
        int sc = 0;
        for (int kb = 0; kb < NKB; ++kb) {
            CP_WAIT(1);
            __syncthreads();
            if (kb + 2 < NKB) load_stage(kb + 2, (sc + 2) % 3);
            CP_COMMIT();
            domma(sc);
            sc = (sc == 2) ? 0 : sc + 1;
        }
    } else {
        load_stage(0, 0); CP_COMMIT();
        for (int kb = 0; kb < NKB; ++kb) {
            const int s = kb & 1;
            if (kb + 1 < NKB) {
                load_stage(kb + 1, s ^ 1);
                CP_COMMIT();
                CP_WAIT(1);
            } else {
                CP_WAIT(0);
            }
            __syncthreads();
            domma(s);
            __syncthreads();
        }
    }

    // merge dual accumulators
    if (DUAL) {
        #pragma unroll
        for (int mt = 0; mt < 2; ++mt)
            #pragma unroll
            for (int nt = 0; nt < NT; ++nt)
                #pragma unroll
                for (int i = 0; i < 4; ++i)
                    acc[mt][nt][i] += accx[mt][nt][i];
    }

    // epilogue
    #pragma unroll
    for (int nt = 0; nt < NT; ++nt) {
        const int col = n0 + wcol * (BN / 2) + nt * 8 + lc * 2;
        const float2 bv = *(const float2*)&bias[col];
        #pragma unroll
        for (int mt = 0; mt < 2; ++mt) {
            const int row = m0 + wrow * 32 + mt * 16 + lr;
            #pragma unroll
            for (int half = 0; half < 2; ++half) {
                const int r = row + half * 8;
                float vx = acc[mt][nt][half * 2 + 0] + bv.x;
                float vy = acc[mt][nt][half * 2 + 1] + bv.y;
                if (ACT == 1) {
                    vx = 0.5f * vx * (1.0f + erff(vx * 0.7071067811865475f));
                    vy = 0.5f * vy * (1.0f + erff(vy * 0.7071067811865475f));
                }
                if (HAS_RES) {
                    float2 rv = *(const float2*)&Res[(size_t)r * N + col];
                    vx += rv.x; vy += rv.y;
                }
                if (OUT_HILO) {
                    bf16* Ch = (bf16*)Cv;
                    bf16* Cl = (bf16*)Clo;
                    *(uint32_t*)&Ch[(size_t)r * N + col] = bfpack(vx, vy);
                    *(uint32_t*)&Cl[(size_t)r * N + col] =
                        bfpack(vx - bfhi(vx), vy - bfhi(vy));
                } else {
                    float2 o; o.x = vx; o.y = vy;
                    *(float2*)&((float*)Cv)[(size_t)r * N + col] = o;
                }
            }
        }
    }
}

// ---------------- flash attention, 512 threads (16 warps, 4x4) ----------------
#define AT_QS   0
#define AT_KS   (128 * 68)
#define AT_VST  (AT_KS + 128 * 68)
#define AT_SS   (AT_VST + 64 * 132)
#define AT_MST  (AT_SS + 128 * 132)
#define AT_FLOATS (AT_MST + 3 * 128)
#define SMEM_ATTN (AT_FLOATS * 4)

__global__ void __launch_bounds__(512, 1)
attn_mma(const float* __restrict__ Q, const float* __restrict__ K,
         const float* __restrict__ V, bf16* __restrict__ OH, bf16* __restrict__ OL) {
    extern __shared__ float sm[];
    float* Qs   = sm + AT_QS;
    float* Ks   = sm + AT_KS;
    float* VsT  = sm + AT_VST;
    float* Ss   = sm + AT_SS;
    float* m_sh = sm + AT_MST;
    float* l_sh = m_sh + 128;
    float* a_sh = l_sh + 128;

    const int qb = gridDim.x - 1 - blockIdx.x;
    const int h  = blockIdx.y;
    const int tid = threadIdx.x;
    const int wid = tid >> 5, lane = tid & 31;
    const int lr = lane >> 2, lc = lane & 3;
    const int wrow = wid & 3, wcol = wid >> 2;

    #pragma unroll
    for (int i = 0; i < 4; ++i) {
        int f = tid + i * 512;
        int r = f >> 4, c4 = (f & 15) << 2;
        float4 v = *(const float4*)&Q[(size_t)(qb * 128 + r) * D_MODEL + h * 64 + c4];
        float* dst = &Qs[r * 68 + c4];
        dst[0] = v.x * 0.125f; dst[1] = v.y * 0.125f;
        dst[2] = v.z * 0.125f; dst[3] = v.w * 0.125f;
    }
    if (tid < 128) { m_sh[tid] = -1e30f; l_sh[tid] = 0.f; }

    float o_acc[2][2][4] = {};
    const float slope = exp2f(-0.5f * (float)(h + 1));

    for (int kb = 0; kb <= qb; ++kb) {
        __syncthreads();
        #pragma unroll
        for (int i = 0; i < 4; ++i) {
            int f = tid + i * 512;
            int r = f >> 4, c4 = (f & 15) << 2;
            float4 v = *(const float4*)&K[(size_t)(kb * 128 + r) * D_MODEL + h * 64 + c4];
            float* dst = &Ks[r * 68 + c4];
            dst[0] = v.x; dst[1] = v.y; dst[2] = v.z; dst[3] = v.w;
        }
        {
            const int d = tid & 63, k0 = tid >> 6;
            const float* vp = V + (size_t)(kb * 128 + k0) * D_MODEL + h * 64 + d;
            #pragma unroll
            for (int i = 0; i < 16; ++i)
                VsT[d * 132 + k0 + i * 8] = vp[(size_t)i * 8 * D_MODEL];
        }
        __syncthreads();

        float s_acc[2][4][4] = {};
        #pragma unroll
        for (int ks = 0; ks < 8; ++ks) {
            uint32_t a[2][4];
            const int c = ks * 8 + lc;
            #pragma unroll
            for (int mt = 0; mt < 2; ++mt) {
                const int r = wrow * 32 + mt * 16 + lr;
                a[mt][0] = __float_as_uint(Qs[r * 68 + c]);
                a[mt][1] = __float_as_uint(Qs[(r + 8) * 68 + c]);
                a[mt][2] = __float_as_uint(Qs[r * 68 + c + 4]);
                a[mt][3] = __float_as_uint(Qs[(r + 8) * 68 + c + 4]);
            }
            #pragma unroll
            for (int nt = 0; nt < 4; ++nt) {
                const int n = wcol * 32 + nt * 8 + lr;
                uint32_t b[2];
                b[0] = __float_as_uint(Ks[n * 68 + c]);
                b[1] = __float_as_uint(Ks[n * 68 + c + 4]);
                mma_tf32(s_acc[0][nt], a[0], b);
                mma_tf32(s_acc[1][nt], a[1], b);
            }
        }
        #pragma unroll
        for (int mt = 0; mt < 2; ++mt) {
            const int r = wrow * 32 + mt * 16 + lr;
            #pragma unroll
            for (int nt = 0; nt < 4; ++nt) {
                const int col = wcol * 32 + nt * 8 + 2 * lc;
                float2 v0; v0.x = s_acc[mt][nt][0]; v0.y = s_acc[mt][nt][1];
                float2 v1; v1.x = s_acc[mt][nt][2]; v1.y = s_acc[mt][nt][3];
                *(float2*)&Ss[r * 132 + col] = v0;
                *(float2*)&Ss[(r + 8) * 132 + col] = v1;
            }
        }
        __syncthreads();

        {
            const int row = tid >> 2, quarter = tid & 3;
            const int qq = qb * 128 + row;
            const int colbase = quarter * 32;
            float mx = -1e30f;
            #pragma unroll
            for (int c4 = 0; c4 < 32; c4 += 4) {
                float4 s4 = *(float4*)&Ss[row * 132 + colbase + c4];
                const int kk = kb * 128 + colbase + c4;
                s4.x = (kk     <= qq) ? fmaf(slope, (float)(kk     - qq), s4.x) : -1e30f;
                s4.y = (kk + 1 <= qq) ? fmaf(slope, (float)(kk + 1 - qq), s4.y) : -1e30f;
                s4.z = (kk + 2 <= qq) ? fmaf(slope, (float)(kk + 2 - qq), s4.z) : -1e30f;
                s4.w = (kk + 3 <= qq) ? fmaf(slope, (float)(kk + 3 - qq), s4.w) : -1e30f;
                *(float4*)&Ss[row * 132 + colbase + c4] = s4;
                mx = fmaxf(mx, fmaxf(fmaxf(s4.x, s4.y), fmaxf(s4.z, s4.w)));
            }
            mx = fmaxf(mx, __shfl_xor_sync(0xffffffffu, mx, 1));
            mx = fmaxf(mx, __shfl_xor_sync(0xffffffffu, mx, 2));
            const float m_old = m_sh[row];
            const float m_new = fmaxf(m_old, mx);
            float sum = 0.f;
            #pragma unroll
            for (int c4 = 0; c4 < 32; c4 += 4) {
                float4 s4 = *(float4*)&Ss[row * 132 + colbase + c4];
                s4.x = fexp(s4.x - m_new); s4.y = fexp(s4.y - m_new);
                s4.z = fexp(s4.z - m_new); s4.w = fexp(s4.w - m_new);
                *(float4*)&Ss[row * 132 + colbase + c4] = s4;
                sum += (s4.x + s4.y) + (s4.z + s4.w);
            }
            sum += __shfl_xor_sync(0xffffffffu, sum, 1);
            sum += __shfl_xor_sync(0xffffffffu, sum, 2);
            if (quarter == 0) {
                const float alpha = fexp(m_old - m_new);
                m_sh[row] = m_new;
                l_sh[row] = l_sh[row] * alpha + sum;
                a_sh[row] = alpha;
            }
        }
        __syncthreads();

        #pragma unroll
        for (int mt = 0; mt < 2; ++mt) {
            const float a0 = a_sh[wrow * 32 + mt * 16 + lr];
            const float a1 = a_sh[wrow * 32 + mt * 16 + lr + 8];
            #pragma unroll
            for (int nt = 0; nt < 2; ++nt) {
                o_acc[mt][nt][0] *= a0; o_acc[mt][nt][1] *= a0;
                o_acc[mt][nt][2] *= a1; o_acc[mt][nt][3] *= a1;
            }
        }
        #pragma unroll
        for (int ks = 0; ks < 16; ++ks) {
            uint32_t a[2][4];
            const int c = ks * 8 + lc;
            #pragma unroll
            for (int mt = 0; mt < 2; ++mt) {
                const int r = wrow * 32 + mt * 16 + lr;
                a[mt][0] = __float_as_uint(Ss[r * 132 + c]);
                a[mt][1] = __float_as_uint(Ss[(r + 8) * 132 + c]);
                a[mt][2] = __float_as_uint(Ss[r * 132 + c + 4]);
                a[mt][3] = __float_as_uint(Ss[(r + 8) * 132 + c + 4]);
            }
            #pragma unroll
            for (int nt = 0; nt < 2; ++nt) {
                const int n = wcol * 16 + nt * 8 + lr;
                uint32_t b[2];
                b[0] = __float_as_uint(VsT[n * 132 + c]);
                b[1] = __float_as_uint(VsT[n * 132 + c + 4]);
                mma_tf32(o_acc[0][nt], a[0], b);
                mma_tf32(o_acc[1][nt], a[1], b);
            }
        }
    }

    #pragma unroll
    for (int mt = 0; mt < 2; ++mt) {
        const int r = wrow * 32 + mt * 16 + lr;
        const float inv0 = 1.f / l_sh[r];
        const float inv1 = 1.f / l_sh[r + 8];
        #pragma unroll
        for (int nt = 0; nt < 2; ++nt) {
            const int col = h * 64 + wcol * 16 + nt * 8 + 2 * lc;
            float v0x = o_acc[mt][nt][0] * inv0, v0y = o_acc[mt][nt][1] * inv0;
            float v1x = o_acc[mt][nt][2] * inv1, v1y = o_acc[mt][nt][3] * inv1;
            size_t i0 = (size_t)(qb * 128 + r) * D_MODEL + col;
            size_t i1 = (size_t)(qb * 128 + r + 8) * D_MODEL + col;
            *(uint32_t*)&OH[i0] = bfpack(v0x, v0y);
            *(uint32_t*)&OL[i0] = bfpack(v0x - bfhi(v0x), v0y - bfhi(v0y));
            *(uint32_t*)&OH[i1] = bfpack(v1x, v1y);
            *(uint32_t*)&OL[i1] = bfpack(v1x - bfhi(v1x), v1y - bfhi(v1y));
        }
    }
}

// ---------------- launch ----------------
extern "C" void kernel_launch(void* const* d_in, const int* in_sizes, int n_in,
                              void* d_out, int out_size) {
    const float* x   = (const float*)d_in[0];
    const float* wq  = (const float*)d_in[3];
    const float* bq  = (const float*)d_in[4];
    const float* wk  = (const float*)d_in[5];
    const float* bk  = (const float*)d_in[6];
    const float* wv  = (const float*)d_in[7];
    const float* bv  = (const float*)d_in[8];
    const float* wo  = (const float*)d_in[9];
    const float* bo  = (const float*)d_in[10];
    const float* w1  = (const float*)d_in[11];
    const float* b1  = (const float*)d_in[12];
    const float* w2  = (const float*)d_in[13];
    const float* b2  = (const float*)d_in[14];
    const float* g1  = (const float*)d_in[15];
    const float* be1 = (const float*)d_in[16];
    const float* g2  = (const float*)d_in[17];
    const float* be2 = (const float*)d_in[18];
    float* out = (float*)d_out;

    float *p_q, *p_k, *p_v, *p_x1;
    bf16 *p_xnh, *p_xnl, *p_ah, *p_al, *p_hh, *p_hl;
    bf16 *p_wqh, *p_wql, *p_wkh, *p_wkl, *p_wvh, *p_wvl, *p_woh, *p_wol;
    bf16 *p_w1h, *p_w1l, *p_w2h, *p_w2l;
    cudaGetSymbolAddress((void**)&p_q,   g_q);
    cudaGetSymbolAddress((void**)&p_k,   g_k);
    cudaGetSymbolAddress((void**)&p_v,   g_v);
    cudaGetSymbolAddress((void**)&p_x1,  g_x1);
    cudaGetSymbolAddress((void**)&p_xnh, g_xnh);
    cudaGetSymbolAddress((void**)&p_xnl, g_xnl);
    cudaGetSymbolAddress((void**)&p_ah,  g_ah);
    cudaGetSymbolAddress((void**)&p_al,  g_al);
    cudaGetSymbolAddress((void**)&p_hh,  g_hh);
    cudaGetSymbolAddress((void**)&p_hl,  g_hl);
    cudaGetSymbolAddress((void**)&p_wqh, g_wqh);
    cudaGetSymbolAddress((void**)&p_wql, g_wql);
    cudaGetSymbolAddress((void**)&p_wkh, g_wkh);
    cudaGetSymbolAddress((void**)&p_wkl, g_wkl);
    cudaGetSymbolAddress((void**)&p_wvh, g_wvh);
    cudaGetSymbolAddress((void**)&p_wvl, g_wvl);
    cudaGetSymbolAddress((void**)&p_woh, g_woh);
    cudaGetSymbolAddress((void**)&p_wol, g_wol);
    cudaGetSymbolAddress((void**)&p_w1h, g_w1h);
    cudaGetSymbolAddress((void**)&p_w1l, g_w1l);
    cudaGetSymbolAddress((void**)&p_w2h, g_w2h);
    cudaGetSymbolAddress((void**)&p_w2l, g_w2l);

    const int smem64  = 3 * (2 * ARR_A + 2 * 32 * (64 * 2 + 16));    // 89088 (3-stage)
    const int smem128 = 2 * (2 * ARR_A + 2 * 32 * (128 * 2 + 16));   // 75776 (2-stage)

    cudaFuncSetAttribute(bgemm<0, false, false, 64>,  cudaFuncAttributeMaxDynamicSharedMemorySize, smem64);
    cudaFuncSetAttribute(bgemm<0, true,  false, 64>,  cudaFuncAttributeMaxDynamicSharedMemorySize, smem64);
    cudaFuncSetAttribute(bgemm<1, false, true,  128>, cudaFuncAttributeMaxDynamicSharedMemorySize, smem128);
    cudaFuncSetAttribute(attn_mma, cudaFuncAttributeMaxDynamicSharedMemorySize, SMEM_ATTN);

    // launch 1: split qkv+o weights (batched)
    wsplit4<<<dim3(256, 4), 256>>>(wq, wk, wv, wo,
                                   p_wqh, p_wql, p_wkh, p_wkl,
                                   p_wvh, p_wvl, p_woh, p_wol);
    // launch 2: split ffn weights (batched)
    wsplit2<<<dim3(1024, 2), 256>>>(w1, w2, p_w1h, p_w1l, p_w2h, p_w2l);

    // launch 3: LN1
    ln_kernel<<<T_SEQ, 256>>>(x, g1, be1, p_xnh, p_xnl);

    // launch 4: fused QKV  <-- profiled position
    bgemm<0, false, false, 64><<<dim3(D_MODEL / 64, T_SEQ / 128, 3), 256, smem64>>>(
        p_xnh, p_xnl, p_wqh, p_wql, p_wkh, p_wkl, p_wvh, p_wvl,
        bq, bk, bv, nullptr, p_q, p_k, p_v, nullptr, D_MODEL, D_MODEL);

    // launch 5: attention
    attn_mma<<<dim3(T_SEQ / 128, N_HEADS), 512, SMEM_ATTN>>>(p_q, p_k, p_v, p_ah, p_al);

    // launch 6: O projection + residual(x)
    bgemm<0, true, false, 64><<<dim3(D_MODEL / 64, T_SEQ / 128, 1), 256, smem64>>>(
        p_ah, p_al, p_woh, p_wol, p_woh, p_wol, p_woh, p_wol,
        bo, bo, bo, x, p_x1, p_x1, p_x1, nullptr, D_MODEL, D_MODEL);

    // launch 7: LN2
    ln_kernel<<<T_SEQ, 256>>>(p_x1, g2, be2, p_xnh, p_xnl);

    // launch 8: FFN1 + GELU
    bgemm<1, false, true, 128><<<dim3(FFN_DIM / 128, T_SEQ / 128, 1), 256, smem128>>>(
        p_xnh, p_xnl, p_w1h, p_w1l, p_w1h, p_w1l, p_w1h, p_w1l,
        b1, b1, b1, nullptr, p_hh, p_hh, p_hh, p_hl, FFN_DIM, D_MODEL);

    // launch 9: FFN2 + residual(x1)
    bgemm<0, true, false, 64><<<dim3(D_MODEL / 64, T_SEQ / 128, 1), 256, smem64>>>(
        p_hh, p_hl, p_w2h, p_w2l, p_w2h, p_w2l, p_w2h, p_w2l,
        b2, b2, b2, p_x1, out, out, out, nullptr, D_MODEL, FFN_DIM);
}

// round 9
// speedup vs baseline: 1.0631x; 1.0431x over previous
#include <cuda_runtime.h>
#include <cuda_bf16.h>
#include <math.h>
#include <stdint.h>

#define T_SEQ 2048
#define D_MODEL 1024
#define N_HEADS 16
#define HEAD_DIM 64
#define FFN_DIM 4096
typedef __nv_bfloat16 bf16;

// ---------------- scratch ----------------
__device__ float g_q[T_SEQ * D_MODEL];
__device__ float g_k[T_SEQ * D_MODEL];
__device__ float g_v[T_SEQ * D_MODEL];
__device__ float g_x1[T_SEQ * D_MODEL];
__device__ bf16  g_xnh[T_SEQ * D_MODEL];
__device__ bf16  g_xnl[T_SEQ * D_MODEL];
__device__ bf16  g_ah[T_SEQ * D_MODEL];
__device__ bf16  g_al[T_SEQ * D_MODEL];
__device__ bf16  g_hh[T_SEQ * FFN_DIM];
__device__ bf16  g_hl[T_SEQ * FFN_DIM];
__device__ bf16 g_wqh[D_MODEL * D_MODEL], g_wql[D_MODEL * D_MODEL];
__device__ bf16 g_wkh[D_MODEL * D_MODEL], g_wkl[D_MODEL * D_MODEL];
__device__ bf16 g_wvh[D_MODEL * D_MODEL], g_wvl[D_MODEL * D_MODEL];
__device__ bf16 g_woh[D_MODEL * D_MODEL], g_wol[D_MODEL * D_MODEL];
__device__ bf16 g_w1h[FFN_DIM * D_MODEL], g_w1l[FFN_DIM * D_MODEL];
__device__ bf16 g_w2h[D_MODEL * FFN_DIM], g_w2l[D_MODEL * FFN_DIM];

// ---------------- helpers ----------------
__device__ __forceinline__ uint32_t smem_u32(const void* p) {
    uint32_t a;
    asm("{ .reg .u64 t; cvta.to.shared.u64 t, %1; cvt.u32.u64 %0, t; }" : "=r"(a) : "l"(p));
    return a;
}
__device__ __forceinline__ void cp16(uint32_t s, const void* g) {
    asm volatile("cp.async.cg.shared.global [%0], [%1], 16;" :: "r"(s), "l"(g));
}
#define CP_COMMIT() asm volatile("cp.async.commit_group;" ::: "memory")
#define CP_WAIT(n)  asm volatile("cp.async.wait_group %0;" :: "n"(n) : "memory")

__device__ __forceinline__ void ldsm4(uint32_t* r, uint32_t addr) {
    asm volatile("ldmatrix.sync.aligned.m8n8.x4.shared.b16 {%0,%1,%2,%3}, [%4];"
        : "=r"(r[0]), "=r"(r[1]), "=r"(r[2]), "=r"(r[3]) : "r"(addr));
}
__device__ __forceinline__ void ldsm4t(uint32_t* r, uint32_t addr) {
    asm volatile("ldmatrix.sync.aligned.m8n8.x4.trans.shared.b16 {%0,%1,%2,%3}, [%4];"
        : "=r"(r[0]), "=r"(r[1]), "=r"(r[2]), "=r"(r[3]) : "r"(addr));
}
__device__ __forceinline__ void mma_bf16(float* d, const uint32_t* a, const uint32_t* b) {
    asm volatile(
        "mma.sync.aligned.m16n8k16.row.col.f32.bf16.bf16.f32 "
        "{%0,%1,%2,%3}, {%4,%5,%6,%7}, {%8,%9}, {%0,%1,%2,%3};"
        : "+f"(d[0]), "+f"(d[1]), "+f"(d[2]), "+f"(d[3])
        : "r"(a[0]), "r"(a[1]), "r"(a[2]), "r"(a[3]), "r"(b[0]), "r"(b[1]));
}
__device__ __forceinline__ void mma_tf32(float* d, const uint32_t* a, const uint32_t* b) {
    asm volatile(
        "mma.sync.aligned.m16n8k8.row.col.f32.tf32.tf32.f32 "
        "{%0,%1,%2,%3}, {%4,%5,%6,%7}, {%8,%9}, {%0,%1,%2,%3};"
        : "+f"(d[0]), "+f"(d[1]), "+f"(d[2]), "+f"(d[3])
        : "r"(a[0]), "r"(a[1]), "r"(a[2]), "r"(a[3]), "r"(b[0]), "r"(b[1]));
}
__device__ __forceinline__ uint32_t bfpack(float a, float b) {
    __nv_bfloat162 t = __floats2bfloat162_rn(a, b);
    return *reinterpret_cast<uint32_t*>(&t);
}
__device__ __forceinline__ float bfhi(float v) {
    return __bfloat162float(__float2bfloat16(v));
}
__device__ __forceinline__ float fexp(float x) {
    float y = fmaxf(x * 1.4426950408889634f, -125.0f);
    float r = rintf(y);
    float f = y - r;
    float p = 1.3333558146e-3f;
    p = fmaf(p, f, 9.6181291076e-3f);
    p = fmaf(p, f, 5.5504108665e-2f);
    p = fmaf(p, f, 2.4022650696e-1f);
    p = fmaf(p, f, 6.9314718056e-1f);
    p = fmaf(p, f, 1.0f);
    return __int_as_float(__float_as_int(p) + (((int)r) << 23));
}

// ---------------- batched weight splits ----------------
__global__ void wsplit4(const float* __restrict__ Wq, const float* __restrict__ Wk,
                        const float* __restrict__ Wv, const float* __restrict__ Wo,
                        bf16* __restrict__ Hq, bf16* __restrict__ Lq,
                        bf16* __restrict__ Hk, bf16* __restrict__ Lk,
                        bf16* __restrict__ Hv, bf16* __restrict__ Lv,
                        bf16* __restrict__ Ho, bf16* __restrict__ Lo) {
    const int m = blockIdx.y;
    const float* W = (m == 0) ? Wq : (m == 1) ? Wk : (m == 2) ? Wv : Wo;
    bf16* H = (m == 0) ? Hq : (m == 1) ? Hk : (m == 2) ? Hv : Ho;
    bf16* L = (m == 0) ? Lq : (m == 1) ? Lk : (m == 2) ? Lv : Lo;
    const size_t base = ((size_t)blockIdx.x * 4096) + threadIdx.x * 4;
    float4 v[4];
    #pragma unroll
    for (int j = 0; j < 4; ++j) v[j] = *(const float4*)&W[base + j * 1024];
    #pragma unroll
    for (int j = 0; j < 4; ++j) {
        uint2 hh, ll;
        hh.x = bfpack(v[j].x, v[j].y); hh.y = bfpack(v[j].z, v[j].w);
        ll.x = bfpack(v[j].x - bfhi(v[j].x), v[j].y - bfhi(v[j].y));
        ll.y = bfpack(v[j].z - bfhi(v[j].z), v[j].w - bfhi(v[j].w));
        *(uint2*)&H[base + j * 1024] = hh;
        *(uint2*)&L[base + j * 1024] = ll;
    }
}
__global__ void wsplit2(const float* __restrict__ W1, const float* __restrict__ W2,
                        bf16* __restrict__ H1, bf16* __restrict__ L1,
                        bf16* __restrict__ H2, bf16* __restrict__ L2) {
    const int m = blockIdx.y;
    const float* W = (m == 0) ? W1 : W2;
    bf16* H = (m == 0) ? H1 : H2;
    bf16* L = (m == 0) ? L1 : L2;
    const size_t base = ((size_t)blockIdx.x * 4096) + threadIdx.x * 4;
    float4 v[4];
    #pragma unroll
    for (int j = 0; j < 4; ++j) v[j] = *(const float4*)&W[base + j * 1024];
    #pragma unroll
    for (int j = 0; j < 4; ++j) {
        uint2 hh, ll;
        hh.x = bfpack(v[j].x, v[j].y); hh.y = bfpack(v[j].z, v[j].w);
        ll.x = bfpack(v[j].x - bfhi(v[j].x), v[j].y - bfhi(v[j].y));
        ll.y = bfpack(v[j].z - bfhi(v[j].z), v[j].w - bfhi(v[j].w));
        *(uint2*)&H[base + j * 1024] = hh;
        *(uint2*)&L[base + j * 1024] = ll;
    }
}

// ---------------- LayerNorm -> bf16 hi/lo ----------------
__global__ void ln_kernel(const float* __restrict__ x, const float* __restrict__ g,
                          const float* __restrict__ b, bf16* __restrict__ yh,
                          bf16* __restrict__ yl) {
    const int row = blockIdx.x, tid = threadIdx.x;
    const float4 xv = *(const float4*)&x[(size_t)row * D_MODEL + tid * 4];
    float s  = (xv.x + xv.y) + (xv.z + xv.w);
    float s2 = (xv.x * xv.x + xv.y * xv.y) + (xv.z * xv.z + xv.w * xv.w);
    __shared__ float red0[8], red1[8];
    #pragma unroll
    for (int o = 16; o > 0; o >>= 1) {
        s  += __shfl_down_sync(0xffffffffu, s, o);
        s2 += __shfl_down_sync(0xffffffffu, s2, o);
    }
    const int w = tid >> 5, l = tid & 31;
    if (l == 0) { red0[w] = s; red1[w] = s2; }
    __syncthreads();
    if (w == 0) {
        s  = (l < 8) ? red0[l] : 0.f;
        s2 = (l < 8) ? red1[l] : 0.f;
        #pragma unroll
        for (int o = 4; o > 0; o >>= 1) {
            s  += __shfl_down_sync(0xffffffffu, s, o);
            s2 += __shfl_down_sync(0xffffffffu, s2, o);
        }
        if (l == 0) { red0[0] = s; red1[0] = s2; }
    }
    __syncthreads();
    const float mu  = red0[0] * (1.f / D_MODEL);
    const float var = red1[0] * (1.f / D_MODEL) - mu * mu;
    const float inv = rsqrtf(var + 1e-5f);
    const float4 gv = *(const float4*)&g[tid * 4];
    const float4 bv = *(const float4*)&b[tid * 4];
    float o0 = (xv.x - mu) * inv * gv.x + bv.x;
    float o1 = (xv.y - mu) * inv * gv.y + bv.y;
    float o2 = (xv.z - mu) * inv * gv.z + bv.z;
    float o3 = (xv.w - mu) * inv * gv.w + bv.w;
    uint2 H, L;
    H.x = bfpack(o0, o1); H.y = bfpack(o2, o3);
    L.x = bfpack(o0 - bfhi(o0), o1 - bfhi(o1));
    L.y = bfpack(o2 - bfhi(o2), o3 - bfhi(o3));
    *(uint2*)&yh[(size_t)row * D_MODEL + tid * 4] = H;
    *(uint2*)&yl[(size_t)row * D_MODEL + tid * 4] = L;
}

// ---------------- bf16x3 mma GEMM with ldmatrix ----------------
// BN=64: BK=64, 2-stage, single barrier/iter. BN=128: BK=32, 2-stage.
template<int ACT, bool HAS_RES, bool OUT_HILO, int BN>
__global__ void __launch_bounds__(256, 2)
bgemm(const bf16* __restrict__ Ah, const bf16* __restrict__ Al,
      const bf16* __restrict__ W0h, const bf16* __restrict__ W0l,
      const bf16* __restrict__ W1h, const bf16* __restrict__ W1l,
      const bf16* __restrict__ W2h, const bf16* __restrict__ W2l,
      const float* __restrict__ b0, const float* __restrict__ b1, const float* __restrict__ b2,
      const float* __restrict__ Res,
      void* __restrict__ C0, void* __restrict__ C1, void* __restrict__ C2,
      void* __restrict__ Clo,
      int N, int K) {
    constexpr int KB     = (BN == 64) ? 64 : 32;       // k per stage
    constexpr int KSTEPS = KB / 16;
    constexpr int A_STR  = KB * 2 + 16;                // A row bytes (144 / 80)
    constexpr int B_STR  = BN * 2 + 16;                // B row bytes (144 / 272)
    constexpr int ARR_A  = 128 * A_STR;
    constexpr int ARR_B  = KB * B_STR;
    constexpr int STAGE  = 2 * ARR_A + 2 * ARR_B;
    constexpr int NT     = BN / 16;
    constexpr int NPAIR  = NT / 2;
    constexpr bool DUAL  = (NT <= 4);

    extern __shared__ char smem[];
    const int z = blockIdx.z;
    const bf16* Wh    = (z == 0) ? W0h : (z == 1) ? W1h : W2h;
    const bf16* Wl    = (z == 0) ? W0l : (z == 1) ? W1l : W2l;
    const float* bias = (z == 0) ? b0 : (z == 1) ? b1 : b2;
    void* Cv          = (z == 0) ? C0 : (z == 1) ? C1 : C2;

    const int m0 = blockIdx.y * 128;
    const int n0 = blockIdx.x * BN;
    const int tid = threadIdx.x;
    const int wid = tid >> 5, lane = tid & 31;
    const int wrow = wid & 3, wcol = wid >> 2;
    const int lr = lane >> 2, lc = lane & 3;
    const int lrow = lane & 7, sub = lane >> 3;

    const uint32_t sbase = smem_u32(smem);
    const int NKB = K / KB;

    const uint32_t aoff = (uint32_t)(wrow * 32 + lrow + 8 * (sub & 1)) * (uint32_t)A_STR + 16u * (sub >> 1);
    const uint32_t boff = (uint32_t)(lrow + 8 * (sub & 1)) * (uint32_t)B_STR +
                          (uint32_t)(wcol * (BN / 2) + 8 * (sub >> 1)) * 2u;

    auto load_stage = [&](int kb, int s) {
        const int k0 = kb * KB;
        const uint32_t st = sbase + s * STAGE;
        #pragma unroll
        for (int f = tid; f < 128 * (KB / 8); f += 256) {
            const int r = f / (KB / 8), cc = f % (KB / 8);
            const uint32_t doff = (uint32_t)r * (uint32_t)A_STR + (uint32_t)cc * 16u;
            const size_t go = (size_t)(m0 + r) * K + k0 + cc * 8;
            cp16(st + doff, Ah + go);
            cp16(st + ARR_A + doff, Al + go);
        }
        #pragma unroll
        for (int f = tid; f < KB * (BN / 8); f += 256) {
            const int r = f / (BN / 8), cc = f % (BN / 8);
            const uint32_t doff = (uint32_t)r * (uint32_t)B_STR + (uint32_t)cc * 16u;
            const size_t go = (size_t)(k0 + r) * N + n0 + cc * 8;
            cp16(st + 2 * ARR_A + doff, Wh + go);
            cp16(st + 2 * ARR_A + ARR_B + doff, Wl + go);
        }
    };

    float acc[2][NT][4];
    float accx[DUAL ? 2 : 1][DUAL ? NT : 1][4];
    #pragma unroll
    for (int mt = 0; mt < 2; ++mt)
        #pragma unroll
        for (int nt = 0; nt < NT; ++nt)
            #pragma unroll
            for (int i = 0; i < 4; ++i) {
                acc[mt][nt][i] = 0.f;
                if (DUAL) accx[mt][nt][i] = 0.f;
            }

    auto domma = [&](int s) {
        const uint32_t stg = sbase + s * STAGE;
        #pragma unroll
        for (int kstep = 0; kstep < KSTEPS; ++kstep) {
            uint32_t ah[2][4], al[2][4];
            #pragma unroll
            for (int mt = 0; mt < 2; ++mt) {
                ldsm4(ah[mt], stg + aoff + mt * 16 * A_STR + kstep * 32);
                ldsm4(al[mt], stg + ARR_A + aoff + mt * 16 * A_STR + kstep * 32);
            }
            uint32_t bh[NT][2], bl[NT][2];
            #pragma unroll
            for (int p = 0; p < NPAIR; ++p) {
                uint32_t t[4];
                ldsm4t(t, stg + 2 * ARR_A + boff + p * 32 + kstep * 16 * B_STR);
                bh[2 * p][0] = t[0]; bh[2 * p][1] = t[1];
                bh[2 * p + 1][0] = t[2]; bh[2 * p + 1][1] = t[3];
                ldsm4t(t, stg + 2 * ARR_A + ARR_B + boff + p * 32 + kstep * 16 * B_STR);
                bl[2 * p][0] = t[0]; bl[2 * p][1] = t[1];
                bl[2 * p + 1][0] = t[2]; bl[2 * p + 1][1] = t[3];
            }
            #pragma unroll
            for (int nt = 0; nt < NT; ++nt) {
                if (DUAL) {
                    mma_bf16(acc[0][nt],  ah[0], bh[nt]);
                    mma_bf16(acc[1][nt],  ah[1], bh[nt]);
                    mma_bf16(accx[0][nt], al[0], bh[nt]);
                    mma_bf16(accx[1][nt], al[1], bh[nt]);
                    mma_bf16(accx[0][nt], ah[0], bl[nt]);
                    mma_bf16(accx[1][nt], ah[1], bl[nt]);
                } else {
                    mma_bf16(acc[0][nt], ah[0], bh[nt]);
                    mma_bf16(acc[1][nt], ah[1], bh[nt]);
                    mma_bf16(acc[0][nt], al[0], bh[nt]);
                    mma_bf16(acc[1][nt], al[1], bh[nt]);
                    mma_bf16(acc[0][nt], ah[0], bl[nt]);
                    mma_bf16(acc[1][nt], ah[1], bl[nt]);
                }
            }
        }
    };

    // 2-stage, single barrier per iteration:
    // every ldsm result is consumed by an mma issued pre-barrier, so post-barrier
    // cp.async writes to the other stage cannot race prior reads.
    load_stage(0, 0);
    CP_COMMIT();
    for (int kb = 0; kb < NKB; ++kb) {
        const int s = kb & 1;
        CP_WAIT(0);
        __syncthreads();
        if (kb + 1 < NKB) {
            load_stage(kb + 1, s ^ 1);
            CP_COMMIT();
        }
        domma(s);
    }

    if (DUAL) {
        #pragma unroll
        for (int mt = 0; mt < 2; ++mt)
            #pragma unroll
            for (int nt = 0; nt < NT; ++nt)
                #pragma unroll
                for (int i = 0; i < 4; ++i)
                    acc[mt][nt][i] += accx[mt][nt][i];
    }

    // epilogue
    #pragma unroll
    for (int nt = 0; nt < NT; ++nt) {
        const int col = n0 + wcol * (BN / 2) + nt * 8 + lc * 2;
        const float2 bv = *(const float2*)&bias[col];
        #pragma unroll
        for (int mt = 0; mt < 2; ++mt) {
            const int row = m0 + wrow * 32 + mt * 16 + lr;
            #pragma unroll
            for (int half = 0; half < 2; ++half) {
                const int r = row + half * 8;
                float vx = acc[mt][nt][half * 2 + 0] + bv.x;
                float vy = acc[mt][nt][half * 2 + 1] + bv.y;
                if (ACT == 1) {
                    vx = 0.5f * vx * (1.0f + erff(vx * 0.7071067811865475f));
                    vy = 0.5f * vy * (1.0f + erff(vy * 0.7071067811865475f));
                }
                if (HAS_RES) {
                    float2 rv = *(const float2*)&Res[(size_t)r * N + col];
                    vx += rv.x; vy += rv.y;
                }
                if (OUT_HILO) {
                    bf16* Ch = (bf16*)Cv;
                    bf16* Cl = (bf16*)Clo;
                    *(uint32_t*)&Ch[(size_t)r * N + col] = bfpack(vx, vy);
                    *(uint32_t*)&Cl[(size_t)r * N + col] =
                        bfpack(vx - bfhi(vx), vy - bfhi(vy));
                } else {
                    float2 o; o.x = vx; o.y = vy;
                    *(float2*)&((float*)Cv)[(size_t)r * N + col] = o;
                }
            }
        }
    }
}

// ---------------- flash attention, 512 threads (16 warps, 4x4) ----------------
#define AT_QS   0
#define AT_KS   (128 * 68)
#define AT_VST  (AT_KS + 128 * 68)
#define AT_SS   (AT_VST + 64 * 132)
#define AT_MST  (AT_SS + 128 * 132)
#define AT_FLOATS (AT_MST + 3 * 128)
#define SMEM_ATTN (AT_FLOATS * 4)

__global__ void __launch_bounds__(512, 1)
attn_mma(const float* __restrict__ Q, const float* __restrict__ K,
         const float* __restrict__ V, bf16* __restrict__ OH, bf16* __restrict__ OL) {
    extern __shared__ float sm[];
    float* Qs   = sm + AT_QS;
    float* Ks   = sm + AT_KS;
    float* VsT  = sm + AT_VST;
    float* Ss   = sm + AT_SS;
    float* m_sh = sm + AT_MST;
    float* l_sh = m_sh + 128;
    float* a_sh = l_sh + 128;

    const int qb = gridDim.x - 1 - blockIdx.x;
    const int h  = blockIdx.y;
    const int tid = threadIdx.x;
    const int wid = tid >> 5, lane = tid & 31;
    const int lr = lane >> 2, lc = lane & 3;
    const int wrow = wid & 3, wcol = wid >> 2;

    #pragma unroll
    for (int i = 0; i < 4; ++i) {
        int f = tid + i * 512;
        int r = f >> 4, c4 = (f & 15) << 2;
        float4 v = *(const float4*)&Q[(size_t)(qb * 128 + r) * D_MODEL + h * 64 + c4];
        float* dst = &Qs[r * 68 + c4];
        dst[0] = v.x * 0.125f; dst[1] = v.y * 0.125f;
        dst[2] = v.z * 0.125f; dst[3] = v.w * 0.125f;
    }
    if (tid < 128) { m_sh[tid] = -1e30f; l_sh[tid] = 0.f; }

    float o_acc[2][2][4] = {};
    const float slope = exp2f(-0.5f * (float)(h + 1));

    for (int kb = 0; kb <= qb; ++kb) {
        __syncthreads();
        #pragma unroll
        for (int i = 0; i < 4; ++i) {
            int f = tid + i * 512;
            int r = f >> 4, c4 = (f & 15) << 2;
            float4 v = *(const float4*)&K[(size_t)(kb * 128 + r) * D_MODEL + h * 64 + c4];
            float* dst = &Ks[r * 68 + c4];
            dst[0] = v.x; dst[1] = v.y; dst[2] = v.z; dst[3] = v.w;
        }
        {
            const int d = tid & 63, k0 = tid >> 6;
            const float* vp = V + (size_t)(kb * 128 + k0) * D_MODEL + h * 64 + d;
            #pragma unroll
            for (int i = 0; i < 16; ++i)
                VsT[d * 132 + k0 + i * 8] = vp[(size_t)i * 8 * D_MODEL];
        }
        __syncthreads();

        float s_acc[2][4][4] = {};
        #pragma unroll
        for (int ks = 0; ks < 8; ++ks) {
            uint32_t a[2][4];
            const int c = ks * 8 + lc;
            #pragma unroll
            for (int mt = 0; mt < 2; ++mt) {
                const int r = wrow * 32 + mt * 16 + lr;
                a[mt][0] = __float_as_uint(Qs[r * 68 + c]);
                a[mt][1] = __float_as_uint(Qs[(r + 8) * 68 + c]);
                a[mt][2] = __float_as_uint(Qs[r * 68 + c + 4]);
                a[mt][3] = __float_as_uint(Qs[(r + 8) * 68 + c + 4]);
            }
            #pragma unroll
            for (int nt = 0; nt < 4; ++nt) {
                const int n = wcol * 32 + nt * 8 + lr;
                uint32_t b[2];
                b[0] = __float_as_uint(Ks[n * 68 + c]);
                b[1] = __float_as_uint(Ks[n * 68 + c + 4]);
                mma_tf32(s_acc[0][nt], a[0], b);
                mma_tf32(s_acc[1][nt], a[1], b);
            }
        }
        #pragma unroll
        for (int mt = 0; mt < 2; ++mt) {
            const int r = wrow * 32 + mt * 16 + lr;
            #pragma unroll
            for (int nt = 0; nt < 4; ++nt) {
                const int col = wcol * 32 + nt * 8 + 2 * lc;
                float2 v0; v0.x = s_acc[mt][nt][0]; v0.y = s_acc[mt][nt][1];
                float2 v1; v1.x = s_acc[mt][nt][2]; v1.y = s_acc[mt][nt][3];
                *(float2*)&Ss[r * 132 + col] = v0;
                *(float2*)&Ss[(r + 8) * 132 + col] = v1;
            }
        }
        __syncthreads();

        {
            const int row = tid >> 2, quarter = tid & 3;
            const int qq = qb * 128 + row;
            const int colbase = quarter * 32;
            float mx = -1e30f;
            #pragma unroll
            for (int c4 = 0; c4 < 32; c4 += 4) {
                float4 s4 = *(float4*)&Ss[row * 132 + colbase + c4];
                const int kk = kb * 128 + colbase + c4;
                s4.x = (kk     <= qq) ? fmaf(slope, (float)(kk     - qq), s4.x) : -1e30f;
                s4.y = (kk + 1 <= qq) ? fmaf(slope, (float)(kk + 1 - qq), s4.y) : -1e30f;
                s4.z = (kk + 2 <= qq) ? fmaf(slope, (float)(kk + 2 - qq), s4.z) : -1e30f;
                s4.w = (kk + 3 <= qq) ? fmaf(slope, (float)(kk + 3 - qq), s4.w) : -1e30f;
                *(float4*)&Ss[row * 132 + colbase + c4] = s4;
                mx = fmaxf(mx, fmaxf(fmaxf(s4.x, s4.y), fmaxf(s4.z, s4.w)));
            }
            mx = fmaxf(mx, __shfl_xor_sync(0xffffffffu, mx, 1));
            mx = fmaxf(mx, __shfl_xor_sync(0xffffffffu, mx, 2));
            const float m_old = m_sh[row];
            const float m_new = fmaxf(m_old, mx);
            float sum = 0.f;
            #pragma unroll
            for (int c4 = 0; c4 < 32; c4 += 4) {
                float4 s4 = *(float4*)&Ss[row * 132 + colbase + c4];
                s4.x = fexp(s4.x - m_new); s4.y = fexp(s4.y - m_new);
                s4.z = fexp(s4.z - m_new); s4.w = fexp(s4.w - m_new);
                *(float4*)&Ss[row * 132 + colbase + c4] = s4;
                sum += (s4.x + s4.y) + (s4.z + s4.w);
            }
            sum += __shfl_xor_sync(0xffffffffu, sum, 1);
            sum += __shfl_xor_sync(0xffffffffu, sum, 2);
            if (quarter == 0) {
                const float alpha = fexp(m_old - m_new);
                m_sh[row] = m_new;
                l_sh[row] = l_sh[row] * alpha + sum;
                a_sh[row] = alpha;
            }
        }
        __syncthreads();

        #pragma unroll
        for (int mt = 0; mt < 2; ++mt) {
            const float a0 = a_sh[wrow * 32 + mt * 16 + lr];
            const float a1 = a_sh[wrow * 32 + mt * 16 + lr + 8];
            #pragma unroll
            for (int nt = 0; nt < 2; ++nt) {
                o_acc[mt][nt][0] *= a0; o_acc[mt][nt][1] *= a0;
                o_acc[mt][nt][2] *= a1; o_acc[mt][nt][3] *= a1;
            }
        }
        #pragma unroll
        for (int ks = 0; ks < 16; ++ks) {
            uint32_t a[2][4];
            const int c = ks * 8 + lc;
            #pragma unroll
            for (int mt = 0; mt < 2; ++mt) {
                const int r = wrow * 32 + mt * 16 + lr;
                a[mt][0] = __float_as_uint(Ss[r * 132 + c]);
                a[mt][1] = __float_as_uint(Ss[(r + 8) * 132 + c]);
                a[mt][2] = __float_as_uint(Ss[r * 132 + c + 4]);
                a[mt][3] = __float_as_uint(Ss[(r + 8) * 132 + c + 4]);
            }
            #pragma unroll
            for (int nt = 0; nt < 2; ++nt) {
                const int n = wcol * 16 + nt * 8 + lr;
                uint32_t b[2];
                b[0] = __float_as_uint(VsT[n * 132 + c]);
                b[1] = __float_as_uint(VsT[n * 132 + c + 4]);
                mma_tf32(o_acc[0][nt], a[0], b);
                mma_tf32(o_acc[1][nt], a[1], b);
            }
        }
    }

    #pragma unroll
    for (int mt = 0; mt < 2; ++mt) {
        const int r = wrow * 32 + mt * 16 + lr;
        const float inv0 = 1.f / l_sh[r];
        const float inv1 = 1.f / l_sh[r + 8];
        #pragma unroll
        for (int nt = 0; nt < 2; ++nt) {
            const int col = h * 64 + wcol * 16 + nt * 8 + 2 * lc;
            float v0x = o_acc[mt][nt][0] * inv0, v0y = o_acc[mt][nt][1] * inv0;
            float v1x = o_acc[mt][nt][2] * inv1, v1y = o_acc[mt][nt][3] * inv1;
            size_t i0 = (size_t)(qb * 128 + r) * D_MODEL + col;
            size_t i1 = (size_t)(qb * 128 + r + 8) * D_MODEL + col;
            *(uint32_t*)&OH[i0] = bfpack(v0x, v0y);
            *(uint32_t*)&OL[i0] = bfpack(v0x - bfhi(v0x), v0y - bfhi(v0y));
            *(uint32_t*)&OH[i1] = bfpack(v1x, v1y);
            *(uint32_t*)&OL[i1] = bfpack(v1x - bfhi(v1x), v1y - bfhi(v1y));
        }
    }
}

// ---------------- launch ----------------
extern "C" void kernel_launch(void* const* d_in, const int* in_sizes, int n_in,
                              void* d_out, int out_size) {
    const float* x   = (const float*)d_in[0];
    const float* wq  = (const float*)d_in[3];
    const float* bq  = (const float*)d_in[4];
    const float* wk  = (const float*)d_in[5];
    const float* bk  = (const float*)d_in[6];
    const float* wv  = (const float*)d_in[7];
    const float* bv  = (const float*)d_in[8];
    const float* wo  = (const float*)d_in[9];
    const float* bo  = (const float*)d_in[10];
    const float* w1  = (const float*)d_in[11];
    const float* b1  = (const float*)d_in[12];
    const float* w2  = (const float*)d_in[13];
    const float* b2  = (const float*)d_in[14];
    const float* g1  = (const float*)d_in[15];
    const float* be1 = (const float*)d_in[16];
    const float* g2  = (const float*)d_in[17];
    const float* be2 = (const float*)d_in[18];
    float* out = (float*)d_out;

    float *p_q, *p_k, *p_v, *p_x1;
    bf16 *p_xnh, *p_xnl, *p_ah, *p_al, *p_hh, *p_hl;
    bf16 *p_wqh, *p_wql, *p_wkh, *p_wkl, *p_wvh, *p_wvl, *p_woh, *p_wol;
    bf16 *p_w1h, *p_w1l, *p_w2h, *p_w2l;
    cudaGetSymbolAddress((void**)&p_q,   g_q);
    cudaGetSymbolAddress((void**)&p_k,   g_k);
    cudaGetSymbolAddress((void**)&p_v,   g_v);
    cudaGetSymbolAddress((void**)&p_x1,  g_x1);
    cudaGetSymbolAddress((void**)&p_xnh, g_xnh);
    cudaGetSymbolAddress((void**)&p_xnl, g_xnl);
    cudaGetSymbolAddress((void**)&p_ah,  g_ah);
    cudaGetSymbolAddress((void**)&p_al,  g_al);
    cudaGetSymbolAddress((void**)&p_hh,  g_hh);
    cudaGetSymbolAddress((void**)&p_hl,  g_hl);
    cudaGetSymbolAddress((void**)&p_wqh, g_wqh);
    cudaGetSymbolAddress((void**)&p_wql, g_wql);
    cudaGetSymbolAddress((void**)&p_wkh, g_wkh);
    cudaGetSymbolAddress((void**)&p_wkl, g_wkl);
    cudaGetSymbolAddress((void**)&p_wvh, g_wvh);
    cudaGetSymbolAddress((void**)&p_wvl, g_wvl);
    cudaGetSymbolAddress((void**)&p_woh, g_woh);
    cudaGetSymbolAddress((void**)&p_wol, g_wol);
    cudaGetSymbolAddress((void**)&p_w1h, g_w1h);
    cudaGetSymbolAddress((void**)&p_w1l, g_w1l);
    cudaGetSymbolAddress((void**)&p_w2h, g_w2h);
    cudaGetSymbolAddress((void**)&p_w2l, g_w2l);

    // smem: BN=64 -> KB=64: stage = 2*128*144 + 2*64*144 = 55296; x2 = 110592
    //       BN=128 -> KB=32: stage = 2*128*80 + 2*32*272 = 37888;  x2 = 75776
    const int smem64  = 2 * (2 * 128 * 144 + 2 * 64 * 144);
    const int smem128 = 2 * (2 * 128 * 80 + 2 * 32 * 272);

    cudaFuncSetAttribute(bgemm<0, false, false, 64>,  cudaFuncAttributeMaxDynamicSharedMemorySize, smem64);
    cudaFuncSetAttribute(bgemm<0, true,  false, 64>,  cudaFuncAttributeMaxDynamicSharedMemorySize, smem64);
    cudaFuncSetAttribute(bgemm<1, false, true,  128>, cudaFuncAttributeMaxDynamicSharedMemorySize, smem128);
    cudaFuncSetAttribute(attn_mma, cudaFuncAttributeMaxDynamicSharedMemorySize, SMEM_ATTN);

    // launch 1: split qkv+o weights
    wsplit4<<<dim3(256, 4), 256>>>(wq, wk, wv, wo,
                                   p_wqh, p_wql, p_wkh, p_wkl,
                                   p_wvh, p_wvl, p_woh, p_wol);
    // launch 2: LN1
    ln_kernel<<<T_SEQ, 256>>>(x, g1, be1, p_xnh, p_xnl);

    // launch 3: fused QKV
    bgemm<0, false, false, 64><<<dim3(D_MODEL / 64, T_SEQ / 128, 3), 256, smem64>>>(
        p_xnh, p_xnl, p_wqh, p_wql, p_wkh, p_wkl, p_wvh, p_wvl,
        bq, bk, bv, nullptr, p_q, p_k, p_v, nullptr, D_MODEL, D_MODEL);

    // launch 4: attention  <-- profiled position
    attn_mma<<<dim3(T_SEQ / 128, N_HEADS), 512, SMEM_ATTN>>>(p_q, p_k, p_v, p_ah, p_al);

    // launch 5: O projection + residual(x)
    bgemm<0, true, false, 64><<<dim3(D_MODEL / 64, T_SEQ / 128, 1), 256, smem64>>>(
        p_ah, p_al, p_woh, p_wol, p_woh, p_wol, p_woh, p_wol,
        bo, bo, bo, x, p_x1, p_x1, p_x1, nullptr, D_MODEL, D_MODEL);

    // launch 6: LN2
    ln_kernel<<<T_SEQ, 256>>>(p_x1, g2, be2, p_xnh, p_xnl);

    // launch 7: split ffn weights (first consumer is FFN1)
    wsplit2<<<dim3(1024, 2), 256>>>(w1, w2, p_w1h, p_w1l, p_w2h, p_w2l);

    // launch 8: FFN1 + GELU
    bgemm<1, false, true, 128><<<dim3(FFN_DIM / 128, T_SEQ / 128, 1), 256, smem128>>>(
        p_xnh, p_xnl, p_w1h, p_w1l, p_w1h, p_w1l, p_w1h, p_w1l,
        b1, b1, b1, nullptr, p_hh, p_hh, p_hh, p_hl, FFN_DIM, D_MODEL);

    // launch 9: FFN2 + residual(x1)
    bgemm<0, true, false, 64><<<dim3(D_MODEL / 64, T_SEQ / 128, 1), 256, smem64>>>(
        p_hh, p_hl, p_w2h, p_w2l, p_w2h, p_w2l, p_w2h, p_w2l,
        b2, b2, b2, p_x1, out, out, out, nullptr, D_MODEL, FFN_DIM);
}

// round 10
// speedup vs baseline: 1.0635x; 1.0004x over previous
#include <cuda_runtime.h>
#include <cuda_bf16.h>
#include <math.h>
#include <stdint.h>

#define T_SEQ 2048
#define D_MODEL 1024
#define N_HEADS 16
#define HEAD_DIM 64
#define FFN_DIM 4096
typedef __nv_bfloat16 bf16;

// ---------------- scratch ----------------
__device__ float g_q[T_SEQ * D_MODEL];
__device__ float g_k[T_SEQ * D_MODEL];
__device__ float g_v[T_SEQ * D_MODEL];
__device__ float g_x1[T_SEQ * D_MODEL];
__device__ bf16  g_xnh[T_SEQ * D_MODEL];
__device__ bf16  g_xnl[T_SEQ * D_MODEL];
__device__ bf16  g_ah[T_SEQ * D_MODEL];
__device__ bf16  g_al[T_SEQ * D_MODEL];
__device__ bf16  g_hh[T_SEQ * FFN_DIM];
__device__ bf16  g_hl[T_SEQ * FFN_DIM];
__device__ bf16 g_wqh[D_MODEL * D_MODEL], g_wql[D_MODEL * D_MODEL];
__device__ bf16 g_wkh[D_MODEL * D_MODEL], g_wkl[D_MODEL * D_MODEL];
__device__ bf16 g_wvh[D_MODEL * D_MODEL], g_wvl[D_MODEL * D_MODEL];
__device__ bf16 g_woh[D_MODEL * D_MODEL], g_wol[D_MODEL * D_MODEL];
__device__ bf16 g_w1h[FFN_DIM * D_MODEL], g_w1l[FFN_DIM * D_MODEL];
__device__ bf16 g_w2h[D_MODEL * FFN_DIM], g_w2l[D_MODEL * FFN_DIM];

// ---------------- helpers ----------------
__device__ __forceinline__ uint32_t smem_u32(const void* p) {
    uint32_t a;
    asm("{ .reg .u64 t; cvta.to.shared.u64 t, %1; cvt.u32.u64 %0, t; }" : "=r"(a) : "l"(p));
    return a;
}
__device__ __forceinline__ void cp16(uint32_t s, const void* g) {
    asm volatile("cp.async.cg.shared.global [%0], [%1], 16;" :: "r"(s), "l"(g));
}
#define CP_COMMIT() asm volatile("cp.async.commit_group;" ::: "memory")
#define CP_WAIT(n)  asm volatile("cp.async.wait_group %0;" :: "n"(n) : "memory")

__device__ __forceinline__ void ldsm4(uint32_t* r, uint32_t addr) {
    asm volatile("ldmatrix.sync.aligned.m8n8.x4.shared.b16 {%0,%1,%2,%3}, [%4];"
        : "=r"(r[0]), "=r"(r[1]), "=r"(r[2]), "=r"(r[3]) : "r"(addr));
}
__device__ __forceinline__ void ldsm4t(uint32_t* r, uint32_t addr) {
    asm volatile("ldmatrix.sync.aligned.m8n8.x4.trans.shared.b16 {%0,%1,%2,%3}, [%4];"
        : "=r"(r[0]), "=r"(r[1]), "=r"(r[2]), "=r"(r[3]) : "r"(addr));
}
__device__ __forceinline__ void mma_bf16(float* d, const uint32_t* a, const uint32_t* b) {
    asm volatile(
        "mma.sync.aligned.m16n8k16.row.col.f32.bf16.bf16.f32 "
        "{%0,%1,%2,%3}, {%4,%5,%6,%7}, {%8,%9}, {%0,%1,%2,%3};"
        : "+f"(d[0]), "+f"(d[1]), "+f"(d[2]), "+f"(d[3])
        : "r"(a[0]), "r"(a[1]), "r"(a[2]), "r"(a[3]), "r"(b[0]), "r"(b[1]));
}
__device__ __forceinline__ void mma_tf32(float* d, const uint32_t* a, const uint32_t* b) {
    asm volatile(
        "mma.sync.aligned.m16n8k8.row.col.f32.tf32.tf32.f32 "
        "{%0,%1,%2,%3}, {%4,%5,%6,%7}, {%8,%9}, {%0,%1,%2,%3};"
        : "+f"(d[0]), "+f"(d[1]), "+f"(d[2]), "+f"(d[3])
        : "r"(a[0]), "r"(a[1]), "r"(a[2]), "r"(a[3]), "r"(b[0]), "r"(b[1]));
}
__device__ __forceinline__ uint32_t bfpack(float a, float b) {
    __nv_bfloat162 t = __floats2bfloat162_rn(a, b);
    return *reinterpret_cast<uint32_t*>(&t);
}
__device__ __forceinline__ float bfhi(float v) {
    return __bfloat162float(__float2bfloat16(v));
}
__device__ __forceinline__ float fexp(float x) {
    float y = fmaxf(x * 1.4426950408889634f, -125.0f);
    float r = rintf(y);
    float f = y - r;
    float p = 1.3333558146e-3f;
    p = fmaf(p, f, 9.6181291076e-3f);
    p = fmaf(p, f, 5.5504108665e-2f);
    p = fmaf(p, f, 2.4022650696e-1f);
    p = fmaf(p, f, 6.9314718056e-1f);
    p = fmaf(p, f, 1.0f);
    return __int_as_float(__float_as_int(p) + (((int)r) << 23));
}

// ---------------- batched weight splits ----------------
__global__ void wsplit4(const float* __restrict__ Wq, const float* __restrict__ Wk,
                        const float* __restrict__ Wv, const float* __restrict__ Wo,
                        bf16* __restrict__ Hq, bf16* __restrict__ Lq,
                        bf16* __restrict__ Hk, bf16* __restrict__ Lk,
                        bf16* __restrict__ Hv, bf16* __restrict__ Lv,
                        bf16* __restrict__ Ho, bf16* __restrict__ Lo) {
    const int m = blockIdx.y;
    const float* W = (m == 0) ? Wq : (m == 1) ? Wk : (m == 2) ? Wv : Wo;
    bf16* H = (m == 0) ? Hq : (m == 1) ? Hk : (m == 2) ? Hv : Ho;
    bf16* L = (m == 0) ? Lq : (m == 1) ? Lk : (m == 2) ? Lv : Lo;
    const size_t base = ((size_t)blockIdx.x * 4096) + threadIdx.x * 4;
    float4 v[4];
    #pragma unroll
    for (int j = 0; j < 4; ++j) v[j] = *(const float4*)&W[base + j * 1024];
    #pragma unroll
    for (int j = 0; j < 4; ++j) {
        uint2 hh, ll;
        hh.x = bfpack(v[j].x, v[j].y); hh.y = bfpack(v[j].z, v[j].w);
        ll.x = bfpack(v[j].x - bfhi(v[j].x), v[j].y - bfhi(v[j].y));
        ll.y = bfpack(v[j].z - bfhi(v[j].z), v[j].w - bfhi(v[j].w));
        *(uint2*)&H[base + j * 1024] = hh;
        *(uint2*)&L[base + j * 1024] = ll;
    }
}
__global__ void wsplit2(const float* __restrict__ W1, const float* __restrict__ W2,
                        bf16* __restrict__ H1, bf16* __restrict__ L1,
                        bf16* __restrict__ H2, bf16* __restrict__ L2) {
    const int m = blockIdx.y;
    const float* W = (m == 0) ? W1 : W2;
    bf16* H = (m == 0) ? H1 : H2;
    bf16* L = (m == 0) ? L1 : L2;
    const size_t base = ((size_t)blockIdx.x * 4096) + threadIdx.x * 4;
    float4 v[4];
    #pragma unroll
    for (int j = 0; j < 4; ++j) v[j] = *(const float4*)&W[base + j * 1024];
    #pragma unroll
    for (int j = 0; j < 4; ++j) {
        uint2 hh, ll;
        hh.x = bfpack(v[j].x, v[j].y); hh.y = bfpack(v[j].z, v[j].w);
        ll.x = bfpack(v[j].x - bfhi(v[j].x), v[j].y - bfhi(v[j].y));
        ll.y = bfpack(v[j].z - bfhi(v[j].z), v[j].w - bfhi(v[j].w));
        *(uint2*)&H[base + j * 1024] = hh;
        *(uint2*)&L[base + j * 1024] = ll;
    }
}

// ---------------- LayerNorm -> bf16 hi/lo ----------------
__global__ void ln_kernel(const float* __restrict__ x, const float* __restrict__ g,
                          const float* __restrict__ b, bf16* __restrict__ yh,
                          bf16* __restrict__ yl) {
    const int row = blockIdx.x, tid = threadIdx.x;
    const float4 xv = *(const float4*)&x[(size_t)row * D_MODEL + tid * 4];
    float s  = (xv.x + xv.y) + (xv.z + xv.w);
    float s2 = (xv.x * xv.x + xv.y * xv.y) + (xv.z * xv.z + xv.w * xv.w);
    __shared__ float red0[8], red1[8];
    #pragma unroll
    for (int o = 16; o > 0; o >>= 1) {
        s  += __shfl_down_sync(0xffffffffu, s, o);
        s2 += __shfl_down_sync(0xffffffffu, s2, o);
    }
    const int w = tid >> 5, l = tid & 31;
    if (l == 0) { red0[w] = s; red1[w] = s2; }
    __syncthreads();
    if (w == 0) {
        s  = (l < 8) ? red0[l] : 0.f;
        s2 = (l < 8) ? red1[l] : 0.f;
        #pragma unroll
        for (int o = 4; o > 0; o >>= 1) {
            s  += __shfl_down_sync(0xffffffffu, s, o);
            s2 += __shfl_down_sync(0xffffffffu, s2, o);
        }
        if (l == 0) { red0[0] = s; red1[0] = s2; }
    }
    __syncthreads();
    const float mu  = red0[0] * (1.f / D_MODEL);
    const float var = red1[0] * (1.f / D_MODEL) - mu * mu;
    const float inv = rsqrtf(var + 1e-5f);
    const float4 gv = *(const float4*)&g[tid * 4];
    const float4 bv = *(const float4*)&b[tid * 4];
    float o0 = (xv.x - mu) * inv * gv.x + bv.x;
    float o1 = (xv.y - mu) * inv * gv.y + bv.y;
    float o2 = (xv.z - mu) * inv * gv.z + bv.z;
    float o3 = (xv.w - mu) * inv * gv.w + bv.w;
    uint2 H, L;
    H.x = bfpack(o0, o1); H.y = bfpack(o2, o3);
    L.x = bfpack(o0 - bfhi(o0), o1 - bfhi(o1));
    L.y = bfpack(o2 - bfhi(o2), o3 - bfhi(o3));
    *(uint2*)&yh[(size_t)row * D_MODEL + tid * 4] = H;
    *(uint2*)&yl[(size_t)row * D_MODEL + tid * 4] = L;
}

// ---------------- bf16x3 mma GEMM with ldmatrix ----------------
// BN=64: BK=64, 2-stage, single barrier/iter. BN=128: BK=32, 2-stage.
template<int ACT, bool HAS_RES, bool OUT_HILO, int BN>
__global__ void __launch_bounds__(256, 2)
bgemm(const bf16* __restrict__ Ah, const bf16* __restrict__ Al,
      const bf16* __restrict__ W0h, const bf16* __restrict__ W0l,
      const bf16* __restrict__ W1h, const bf16* __restrict__ W1l,
      const bf16* __restrict__ W2h, const bf16* __restrict__ W2l,
      const float* __restrict__ b0, const float* __restrict__ b1, const float* __restrict__ b2,
      const float* __restrict__ Res,
      void* __restrict__ C0, void* __restrict__ C1, void* __restrict__ C2,
      void* __restrict__ Clo,
      int N, int K) {
    constexpr int KB     = (BN == 64) ? 64 : 32;       // k per stage
    constexpr int KSTEPS = KB / 16;
    constexpr int A_STR  = KB * 2 + 16;                // A row bytes (144 / 80)
    constexpr int B_STR  = BN * 2 + 16;                // B row bytes (144 / 272)
    constexpr int ARR_A  = 128 * A_STR;
    constexpr int ARR_B  = KB * B_STR;
    constexpr int STAGE  = 2 * ARR_A + 2 * ARR_B;
    constexpr int NT     = BN / 16;
    constexpr int NPAIR  = NT / 2;
    constexpr bool DUAL  = (NT <= 4);

    extern __shared__ char smem[];
    const int z = blockIdx.z;
    const bf16* Wh    = (z == 0) ? W0h : (z == 1) ? W1h : W2h;
    const bf16* Wl    = (z == 0) ? W0l : (z == 1) ? W1l : W2l;
    const float* bias = (z == 0) ? b0 : (z == 1) ? b1 : b2;
    void* Cv          = (z == 0) ? C0 : (z == 1) ? C1 : C2;

    const int m0 = blockIdx.y * 128;
    const int n0 = blockIdx.x * BN;
    const int tid = threadIdx.x;
    const int wid = tid >> 5, lane = tid & 31;
    const int wrow = wid & 3, wcol = wid >> 2;
    const int lr = lane >> 2, lc = lane & 3;
    const int lrow = lane & 7, sub = lane >> 3;

    const uint32_t sbase = smem_u32(smem);
    const int NKB = K / KB;

    const uint32_t aoff = (uint32_t)(wrow * 32 + lrow + 8 * (sub & 1)) * (uint32_t)A_STR + 16u * (sub >> 1);
    const uint32_t boff = (uint32_t)(lrow + 8 * (sub & 1)) * (uint32_t)B_STR +
                          (uint32_t)(wcol * (BN / 2) + 8 * (sub >> 1)) * 2u;

    auto load_stage = [&](int kb, int s) {
        const int k0 = kb * KB;
        const uint32_t st = sbase + s * STAGE;
        #pragma unroll
        for (int f = tid; f < 128 * (KB / 8); f += 256) {
            const int r = f / (KB / 8), cc = f % (KB / 8);
            const uint32_t doff = (uint32_t)r * (uint32_t)A_STR + (uint32_t)cc * 16u;
            const size_t go = (size_t)(m0 + r) * K + k0 + cc * 8;
            cp16(st + doff, Ah + go);
            cp16(st + ARR_A + doff, Al + go);
        }
        #pragma unroll
        for (int f = tid; f < KB * (BN / 8); f += 256) {
            const int r = f / (BN / 8), cc = f % (BN / 8);
            const uint32_t doff = (uint32_t)r * (uint32_t)B_STR + (uint32_t)cc * 16u;
            const size_t go = (size_t)(k0 + r) * N + n0 + cc * 8;
            cp16(st + 2 * ARR_A + doff, Wh + go);
            cp16(st + 2 * ARR_A + ARR_B + doff, Wl + go);
        }
    };

    float acc[2][NT][4];
    float accx[DUAL ? 2 : 1][DUAL ? NT : 1][4];
    #pragma unroll
    for (int mt = 0; mt < 2; ++mt)
        #pragma unroll
        for (int nt = 0; nt < NT; ++nt)
            #pragma unroll
            for (int i = 0; i < 4; ++i) {
                acc[mt][nt][i] = 0.f;
                if (DUAL) accx[mt][nt][i] = 0.f;
            }

    auto domma = [&](int s) {
        const uint32_t stg = sbase + s * STAGE;
        #pragma unroll
        for (int kstep = 0; kstep < KSTEPS; ++kstep) {
            uint32_t ah[2][4], al[2][4];
            #pragma unroll
            for (int mt = 0; mt < 2; ++mt) {
                ldsm4(ah[mt], stg + aoff + mt * 16 * A_STR + kstep * 32);
                ldsm4(al[mt], stg + ARR_A + aoff + mt * 16 * A_STR + kstep * 32);
            }
            uint32_t bh[NT][2], bl[NT][2];
            #pragma unroll
            for (int p = 0; p < NPAIR; ++p) {
                uint32_t t[4];
                ldsm4t(t, stg + 2 * ARR_A + boff + p * 32 + kstep * 16 * B_STR);
                bh[2 * p][0] = t[0]; bh[2 * p][1] = t[1];
                bh[2 * p + 1][0] = t[2]; bh[2 * p + 1][1] = t[3];
                ldsm4t(t, stg + 2 * ARR_A + ARR_B + boff + p * 32 + kstep * 16 * B_STR);
                bl[2 * p][0] = t[0]; bl[2 * p][1] = t[1];
                bl[2 * p + 1][0] = t[2]; bl[2 * p + 1][1] = t[3];
            }
            #pragma unroll
            for (int nt = 0; nt < NT; ++nt) {
                if (DUAL) {
                    mma_bf16(acc[0][nt],  ah[0], bh[nt]);
                    mma_bf16(acc[1][nt],  ah[1], bh[nt]);
                    mma_bf16(accx[0][nt], al[0], bh[nt]);
                    mma_bf16(accx[1][nt], al[1], bh[nt]);
                    mma_bf16(accx[0][nt], ah[0], bl[nt]);
                    mma_bf16(accx[1][nt], ah[1], bl[nt]);
                } else {
                    mma_bf16(acc[0][nt], ah[0], bh[nt]);
                    mma_bf16(acc[1][nt], ah[1], bh[nt]);
                    mma_bf16(acc[0][nt], al[0], bh[nt]);
                    mma_bf16(acc[1][nt], al[1], bh[nt]);
                    mma_bf16(acc[0][nt], ah[0], bl[nt]);
                    mma_bf16(acc[1][nt], ah[1], bl[nt]);
                }
            }
        }
    };

    // 2-stage, single barrier per iteration:
    // every ldsm result is consumed by an mma issued pre-barrier, so post-barrier
    // cp.async writes to the other stage cannot race prior reads.
    load_stage(0, 0);
    CP_COMMIT();
    for (int kb = 0; kb < NKB; ++kb) {
        const int s = kb & 1;
        CP_WAIT(0);
        __syncthreads();
        if (kb + 1 < NKB) {
            load_stage(kb + 1, s ^ 1);
            CP_COMMIT();
        }
        domma(s);
    }

    if (DUAL) {
        #pragma unroll
        for (int mt = 0; mt < 2; ++mt)
            #pragma unroll
            for (int nt = 0; nt < NT; ++nt)
                #pragma unroll
                for (int i = 0; i < 4; ++i)
                    acc[mt][nt][i] += accx[mt][nt][i];
    }

    // epilogue
    #pragma unroll
    for (int nt = 0; nt < NT; ++nt) {
        const int col = n0 + wcol * (BN / 2) + nt * 8 + lc * 2;
        const float2 bv = *(const float2*)&bias[col];
        #pragma unroll
        for (int mt = 0; mt < 2; ++mt) {
            const int row = m0 + wrow * 32 + mt * 16 + lr;
            #pragma unroll
            for (int half = 0; half < 2; ++half) {
                const int r = row + half * 8;
                float vx = acc[mt][nt][half * 2 + 0] + bv.x;
                float vy = acc[mt][nt][half * 2 + 1] + bv.y;
                if (ACT == 1) {
                    vx = 0.5f * vx * (1.0f + erff(vx * 0.7071067811865475f));
                    vy = 0.5f * vy * (1.0f + erff(vy * 0.7071067811865475f));
                }
                if (HAS_RES) {
                    float2 rv = *(const float2*)&Res[(size_t)r * N + col];
                    vx += rv.x; vy += rv.y;
                }
                if (OUT_HILO) {
                    bf16* Ch = (bf16*)Cv;
                    bf16* Cl = (bf16*)Clo;
                    *(uint32_t*)&Ch[(size_t)r * N + col] = bfpack(vx, vy);
                    *(uint32_t*)&Cl[(size_t)r * N + col] =
                        bfpack(vx - bfhi(vx), vy - bfhi(vy));
                } else {
                    float2 o; o.x = vx; o.y = vy;
                    *(float2*)&((float*)Cv)[(size_t)r * N + col] = o;
                }
            }
        }
    }
}

// ---------------- flash attention, 512 threads (16 warps, 4x4) ----------------
#define AT_QS   0
#define AT_KS   (128 * 68)
#define AT_VST  (AT_KS + 128 * 68)
#define AT_SS   (AT_VST + 64 * 132)
#define AT_MST  (AT_SS + 128 * 132)
#define AT_FLOATS (AT_MST + 3 * 128)
#define SMEM_ATTN (AT_FLOATS * 4)

__global__ void __launch_bounds__(512, 1)
attn_mma(const float* __restrict__ Q, const float* __restrict__ K,
         const float* __restrict__ V, bf16* __restrict__ OH, bf16* __restrict__ OL) {
    extern __shared__ float sm[];
    float* Qs   = sm + AT_QS;
    float* Ks   = sm + AT_KS;
    float* VsT  = sm + AT_VST;
    float* Ss   = sm + AT_SS;
    float* m_sh = sm + AT_MST;
    float* l_sh = m_sh + 128;
    float* a_sh = l_sh + 128;

    const int qb = gridDim.x - 1 - blockIdx.x;
    const int h  = blockIdx.y;
    const int tid = threadIdx.x;
    const int wid = tid >> 5, lane = tid & 31;
    const int lr = lane >> 2, lc = lane & 3;
    const int wrow = wid & 3, wcol = wid >> 2;

    #pragma unroll
    for (int i = 0; i < 4; ++i) {
        int f = tid + i * 512;
        int r = f >> 4, c4 = (f & 15) << 2;
        float4 v = *(const float4*)&Q[(size_t)(qb * 128 + r) * D_MODEL + h * 64 + c4];
        float* dst = &Qs[r * 68 + c4];
        dst[0] = v.x * 0.125f; dst[1] = v.y * 0.125f;
        dst[2] = v.z * 0.125f; dst[3] = v.w * 0.125f;
    }
    if (tid < 128) { m_sh[tid] = -1e30f; l_sh[tid] = 0.f; }

    float o_acc[2][2][4] = {};
    const float slope = exp2f(-0.5f * (float)(h + 1));

    for (int kb = 0; kb <= qb; ++kb) {
        __syncthreads();
        #pragma unroll
        for (int i = 0; i < 4; ++i) {
            int f = tid + i * 512;
            int r = f >> 4, c4 = (f & 15) << 2;
            float4 v = *(const float4*)&K[(size_t)(kb * 128 + r) * D_MODEL + h * 64 + c4];
            float* dst = &Ks[r * 68 + c4];
            dst[0] = v.x; dst[1] = v.y; dst[2] = v.z; dst[3] = v.w;
        }
        {
            const int d = tid & 63, k0 = tid >> 6;
            const float* vp = V + (size_t)(kb * 128 + k0) * D_MODEL + h * 64 + d;
            #pragma unroll
            for (int i = 0; i < 16; ++i)
                VsT[d * 132 + k0 + i * 8] = vp[(size_t)i * 8 * D_MODEL];
        }
        __syncthreads();

        float s_acc[2][4][4] = {};
        #pragma unroll
        for (int ks = 0; ks < 8; ++ks) {
            uint32_t a[2][4];
            const int c = ks * 8 + lc;
            #pragma unroll
            for (int mt = 0; mt < 2; ++mt) {
                const int r = wrow * 32 + mt * 16 + lr;
                a[mt][0] = __float_as_uint(Qs[r * 68 + c]);
                a[mt][1] = __float_as_uint(Qs[(r + 8) * 68 + c]);
                a[mt][2] = __float_as_uint(Qs[r * 68 + c + 4]);
                a[mt][3] = __float_as_uint(Qs[(r + 8) * 68 + c + 4]);
            }
            #pragma unroll
            for (int nt = 0; nt < 4; ++nt) {
                const int n = wcol * 32 + nt * 8 + lr;
                uint32_t b[2];
                b[0] = __float_as_uint(Ks[n * 68 + c]);
                b[1] = __float_as_uint(Ks[n * 68 + c + 4]);
                mma_tf32(s_acc[0][nt], a[0], b);
                mma_tf32(s_acc[1][nt], a[1], b);
            }
        }
        #pragma unroll
        for (int mt = 0; mt < 2; ++mt) {
            const int r = wrow * 32 + mt * 16 + lr;
            #pragma unroll
            for (int nt = 0; nt < 4; ++nt) {
                const int col = wcol * 32 + nt * 8 + 2 * lc;
                float2 v0; v0.x = s_acc[mt][nt][0]; v0.y = s_acc[mt][nt][1];
                float2 v1; v1.x = s_acc[mt][nt][2]; v1.y = s_acc[mt][nt][3];
                *(float2*)&Ss[r * 132 + col] = v0;
                *(float2*)&Ss[(r + 8) * 132 + col] = v1;
            }
        }
        __syncthreads();

        {
            const int row = tid >> 2, quarter = tid & 3;
            const int qq = qb * 128 + row;
            const int colbase = quarter * 32;
            float mx = -1e30f;
            #pragma unroll
            for (int c4 = 0; c4 < 32; c4 += 4) {
                float4 s4 = *(float4*)&Ss[row * 132 + colbase + c4];
                const int kk = kb * 128 + colbase + c4;
                s4.x = (kk     <= qq) ? fmaf(slope, (float)(kk     - qq), s4.x) : -1e30f;
                s4.y = (kk + 1 <= qq) ? fmaf(slope, (float)(kk + 1 - qq), s4.y) : -1e30f;
                s4.z = (kk + 2 <= qq) ? fmaf(slope, (float)(kk + 2 - qq), s4.z) : -1e30f;
                s4.w = (kk + 3 <= qq) ? fmaf(slope, (float)(kk + 3 - qq), s4.w) : -1e30f;
                *(float4*)&Ss[row * 132 + colbase + c4] = s4;
                mx = fmaxf(mx, fmaxf(fmaxf(s4.x, s4.y), fmaxf(s4.z, s4.w)));
            }
            mx = fmaxf(mx, __shfl_xor_sync(0xffffffffu, mx, 1));
            mx = fmaxf(mx, __shfl_xor_sync(0xffffffffu, mx, 2));
            const float m_old = m_sh[row];
            const float m_new = fmaxf(m_old, mx);
            float sum = 0.f;
            #pragma unroll
            for (int c4 = 0; c4 < 32; c4 += 4) {
                float4 s4 = *(float4*)&Ss[row * 132 + colbase + c4];
                s4.x = fexp(s4.x - m_new); s4.y = fexp(s4.y - m_new);
                s4.z = fexp(s4.z - m_new); s4.w = fexp(s4.w - m_new);
                *(float4*)&Ss[row * 132 + colbase + c4] = s4;
                sum += (s4.x + s4.y) + (s4.z + s4.w);
            }
            sum += __shfl_xor_sync(0xffffffffu, sum, 1);
            sum += __shfl_xor_sync(0xffffffffu, sum, 2);
            if (quarter == 0) {
                const float alpha = fexp(m_old - m_new);
                m_sh[row] = m_new;
                l_sh[row] = l_sh[row] * alpha + sum;
                a_sh[row] = alpha;
            }
        }
        __syncthreads();

        #pragma unroll
        for (int mt = 0; mt < 2; ++mt) {
            const float a0 = a_sh[wrow * 32 + mt * 16 + lr];
            const float a1 = a_sh[wrow * 32 + mt * 16 + lr + 8];
            #pragma unroll
            for (int nt = 0; nt < 2; ++nt) {
                o_acc[mt][nt][0] *= a0; o_acc[mt][nt][1] *= a0;
                o_acc[mt][nt][2] *= a1; o_acc[mt][nt][3] *= a1;
            }
        }
        #pragma unroll
        for (int ks = 0; ks < 16; ++ks) {
            uint32_t a[2][4];
            const int c = ks * 8 + lc;
            #pragma unroll
            for (int mt = 0; mt < 2; ++mt) {
                const int r = wrow * 32 + mt * 16 + lr;
                a[mt][0] = __float_as_uint(Ss[r * 132 + c]);
                a[mt][1] = __float_as_uint(Ss[(r + 8) * 132 + c]);
                a[mt][2] = __float_as_uint(Ss[r * 132 + c + 4]);
                a[mt][3] = __float_as_uint(Ss[(r + 8) * 132 + c + 4]);
            }
            #pragma unroll
            for (int nt = 0; nt < 2; ++nt) {
                const int n = wcol * 16 + nt * 8 + lr;
                uint32_t b[2];
                b[0] = __float_as_uint(VsT[n * 132 + c]);
                b[1] = __float_as_uint(VsT[n * 132 + c + 4]);
                mma_tf32(o_acc[0][nt], a[0], b);
                mma_tf32(o_acc[1][nt], a[1], b);
            }
        }
    }

    #pragma unroll
    for (int mt = 0; mt < 2; ++mt) {
        const int r = wrow * 32 + mt * 16 + lr;
        const float inv0 = 1.f / l_sh[r];
        const float inv1 = 1.f / l_sh[r + 8];
        #pragma unroll
        for (int nt = 0; nt < 2; ++nt) {
            const int col = h * 64 + wcol * 16 + nt * 8 + 2 * lc;
            float v0x = o_acc[mt][nt][0] * inv0, v0y = o_acc[mt][nt][1] * inv0;
            float v1x = o_acc[mt][nt][2] * inv1, v1y = o_acc[mt][nt][3] * inv1;
            size_t i0 = (size_t)(qb * 128 + r) * D_MODEL + col;
            size_t i1 = (size_t)(qb * 128 + r + 8) * D_MODEL + col;
            *(uint32_t*)&OH[i0] = bfpack(v0x, v0y);
            *(uint32_t*)&OL[i0] = bfpack(v0x - bfhi(v0x), v0y - bfhi(v0y));
            *(uint32_t*)&OH[i1] = bfpack(v1x, v1y);
            *(uint32_t*)&OL[i1] = bfpack(v1x - bfhi(v1x), v1y - bfhi(v1y));
        }
    }
}

// ---------------- launch ----------------
extern "C" void kernel_launch(void* const* d_in, const int* in_sizes, int n_in,
                              void* d_out, int out_size) {
    const float* x   = (const float*)d_in[0];
    const float* wq  = (const float*)d_in[3];
    const float* bq  = (const float*)d_in[4];
    const float* wk  = (const float*)d_in[5];
    const float* bk  = (const float*)d_in[6];
    const float* wv  = (const float*)d_in[7];
    const float* bv  = (const float*)d_in[8];
    const float* wo  = (const float*)d_in[9];
    const float* bo  = (const float*)d_in[10];
    const float* w1  = (const float*)d_in[11];
    const float* b1  = (const float*)d_in[12];
    const float* w2  = (const float*)d_in[13];
    const float* b2  = (const float*)d_in[14];
    const float* g1  = (const float*)d_in[15];
    const float* be1 = (const float*)d_in[16];
    const float* g2  = (const float*)d_in[17];
    const float* be2 = (const float*)d_in[18];
    float* out = (float*)d_out;

    float *p_q, *p_k, *p_v, *p_x1;
    bf16 *p_xnh, *p_xnl, *p_ah, *p_al, *p_hh, *p_hl;
    bf16 *p_wqh, *p_wql, *p_wkh, *p_wkl, *p_wvh, *p_wvl, *p_woh, *p_wol;
    bf16 *p_w1h, *p_w1l, *p_w2h, *p_w2l;
    cudaGetSymbolAddress((void**)&p_q,   g_q);
    cudaGetSymbolAddress((void**)&p_k,   g_k);
    cudaGetSymbolAddress((void**)&p_v,   g_v);
    cudaGetSymbolAddress((void**)&p_x1,  g_x1);
    cudaGetSymbolAddress((void**)&p_xnh, g_xnh);
    cudaGetSymbolAddress((void**)&p_xnl, g_xnl);
    cudaGetSymbolAddress((void**)&p_ah,  g_ah);
    cudaGetSymbolAddress((void**)&p_al,  g_al);
    cudaGetSymbolAddress((void**)&p_hh,  g_hh);
    cudaGetSymbolAddress((void**)&p_hl,  g_hl);
    cudaGetSymbolAddress((void**)&p_wqh, g_wqh);
    cudaGetSymbolAddress((void**)&p_wql, g_wql);
    cudaGetSymbolAddress((void**)&p_wkh, g_wkh);
    cudaGetSymbolAddress((void**)&p_wkl, g_wkl);
    cudaGetSymbolAddress((void**)&p_wvh, g_wvh);
    cudaGetSymbolAddress((void**)&p_wvl, g_wvl);
    cudaGetSymbolAddress((void**)&p_woh, g_woh);
    cudaGetSymbolAddress((void**)&p_wol, g_wol);
    cudaGetSymbolAddress((void**)&p_w1h, g_w1h);
    cudaGetSymbolAddress((void**)&p_w1l, g_w1l);
    cudaGetSymbolAddress((void**)&p_w2h, g_w2h);
    cudaGetSymbolAddress((void**)&p_w2l, g_w2l);

    // smem: BN=64 -> KB=64: stage = 2*128*144 + 2*64*144 = 55296; x2 = 110592
    //       BN=128 -> KB=32: stage = 2*128*80 + 2*32*272 = 37888;  x2 = 75776
    const int smem64  = 2 * (2 * 128 * 144 + 2 * 64 * 144);
    const int smem128 = 2 * (2 * 128 * 80 + 2 * 32 * 272);

    cudaFuncSetAttribute(bgemm<0, false, false, 64>,  cudaFuncAttributeMaxDynamicSharedMemorySize, smem64);
    cudaFuncSetAttribute(bgemm<0, true,  false, 64>,  cudaFuncAttributeMaxDynamicSharedMemorySize, smem64);
    cudaFuncSetAttribute(bgemm<1, false, true,  128>, cudaFuncAttributeMaxDynamicSharedMemorySize, smem128);
    cudaFuncSetAttribute(attn_mma, cudaFuncAttributeMaxDynamicSharedMemorySize, SMEM_ATTN);

    // launch 1: split qkv+o weights
    wsplit4<<<dim3(256, 4), 256>>>(wq, wk, wv, wo,
                                   p_wqh, p_wql, p_wkh, p_wkl,
                                   p_wvh, p_wvl, p_woh, p_wol);
    // launch 2: LN1
    ln_kernel<<<T_SEQ, 256>>>(x, g1, be1, p_xnh, p_xnl);

    // launch 3: fused QKV
    bgemm<0, false, false, 64><<<dim3(D_MODEL / 64, T_SEQ / 128, 3), 256, smem64>>>(
        p_xnh, p_xnl, p_wqh, p_wql, p_wkh, p_wkl, p_wvh, p_wvl,
        bq, bk, bv, nullptr, p_q, p_k, p_v, nullptr, D_MODEL, D_MODEL);

    // launch 4: attention  <-- profiled position
    attn_mma<<<dim3(T_SEQ / 128, N_HEADS), 512, SMEM_ATTN>>>(p_q, p_k, p_v, p_ah, p_al);

    // launch 5: O projection + residual(x)
    bgemm<0, true, false, 64><<<dim3(D_MODEL / 64, T_SEQ / 128, 1), 256, smem64>>>(
        p_ah, p_al, p_woh, p_wol, p_woh, p_wol, p_woh, p_wol,
        bo, bo, bo, x, p_x1, p_x1, p_x1, nullptr, D_MODEL, D_MODEL);

    // launch 6: LN2
    ln_kernel<<<T_SEQ, 256>>>(p_x1, g2, be2, p_xnh, p_xnl);

    // launch 7: split ffn weights (first consumer is FFN1)
    wsplit2<<<dim3(1024, 2), 256>>>(w1, w2, p_w1h, p_w1l, p_w2h, p_w2l);

    // launch 8: FFN1 + GELU
    bgemm<1, false, true, 128><<<dim3(FFN_DIM / 128, T_SEQ / 128, 1), 256, smem128>>>(
        p_xnh, p_xnl, p_w1h, p_w1l, p_w1h, p_w1l, p_w1h, p_w1l,
        b1, b1, b1, nullptr, p_hh, p_hh, p_hh, p_hl, FFN_DIM, D_MODEL);

    // launch 9: FFN2 + residual(x1)
    bgemm<0, true, false, 64><<<dim3(D_MODEL / 64, T_SEQ / 128, 1), 256, smem64>>>(
        p_hh, p_hl, p_w2h, p_w2l, p_w2h, p_w2l, p_w2h, p_w2l,
        b2, b2, b2, p_x1, out, out, out, nullptr, D_MODEL, FFN_DIM);
}

// round 11
// speedup vs baseline: 1.0914x; 1.0262x over previous
#include <cuda_runtime.h>
#include <cuda_bf16.h>
#include <math.h>
#include <stdint.h>

#define T_SEQ 2048
#define D_MODEL 1024
#define N_HEADS 16
#define HEAD_DIM 64
#define FFN_DIM 4096
typedef __nv_bfloat16 bf16;

// ---------------- scratch ----------------
__device__ float g_x1[T_SEQ * D_MODEL];
__device__ bf16  g_xnh[T_SEQ * D_MODEL], g_xnl[T_SEQ * D_MODEL];
__device__ bf16  g_qh[T_SEQ * D_MODEL], g_ql[T_SEQ * D_MODEL];
__device__ bf16  g_kh[T_SEQ * D_MODEL], g_kl[T_SEQ * D_MODEL];
__device__ bf16  g_vh[T_SEQ * D_MODEL], g_vl[T_SEQ * D_MODEL];
__device__ bf16  g_ah[T_SEQ * D_MODEL], g_al[T_SEQ * D_MODEL];
__device__ bf16  g_hh[T_SEQ * FFN_DIM], g_hl[T_SEQ * FFN_DIM];
__device__ bf16 g_wqh[D_MODEL * D_MODEL], g_wql[D_MODEL * D_MODEL];
__device__ bf16 g_wkh[D_MODEL * D_MODEL], g_wkl[D_MODEL * D_MODEL];
__device__ bf16 g_wvh[D_MODEL * D_MODEL], g_wvl[D_MODEL * D_MODEL];
__device__ bf16 g_woh[D_MODEL * D_MODEL], g_wol[D_MODEL * D_MODEL];
__device__ bf16 g_w1h[FFN_DIM * D_MODEL], g_w1l[FFN_DIM * D_MODEL];
__device__ bf16 g_w2h[D_MODEL * FFN_DIM], g_w2l[D_MODEL * FFN_DIM];

// ---------------- helpers ----------------
__device__ __forceinline__ uint32_t smem_u32(const void* p) {
    uint32_t a;
    asm("{ .reg .u64 t; cvta.to.shared.u64 t, %1; cvt.u32.u64 %0, t; }" : "=r"(a) : "l"(p));
    return a;
}
__device__ __forceinline__ void cp16(uint32_t s, const void* g) {
    asm volatile("cp.async.cg.shared.global [%0], [%1], 16;" :: "r"(s), "l"(g));
}
#define CP_COMMIT() asm volatile("cp.async.commit_group;" ::: "memory")
#define CP_WAIT(n)  asm volatile("cp.async.wait_group %0;" :: "n"(n) : "memory")

__device__ __forceinline__ void ldsm4(uint32_t* r, uint32_t addr) {
    asm volatile("ldmatrix.sync.aligned.m8n8.x4.shared.b16 {%0,%1,%2,%3}, [%4];"
        : "=r"(r[0]), "=r"(r[1]), "=r"(r[2]), "=r"(r[3]) : "r"(addr));
}
__device__ __forceinline__ void ldsm4t(uint32_t* r, uint32_t addr) {
    asm volatile("ldmatrix.sync.aligned.m8n8.x4.trans.shared.b16 {%0,%1,%2,%3}, [%4];"
        : "=r"(r[0]), "=r"(r[1]), "=r"(r[2]), "=r"(r[3]) : "r"(addr));
}
__device__ __forceinline__ void mma_bf16(float* d, const uint32_t* a, const uint32_t* b) {
    asm volatile(
        "mma.sync.aligned.m16n8k16.row.col.f32.bf16.bf16.f32 "
        "{%0,%1,%2,%3}, {%4,%5,%6,%7}, {%8,%9}, {%0,%1,%2,%3};"
        : "+f"(d[0]), "+f"(d[1]), "+f"(d[2]), "+f"(d[3])
        : "r"(a[0]), "r"(a[1]), "r"(a[2]), "r"(a[3]), "r"(b[0]), "r"(b[1]));
}
__device__ __forceinline__ uint32_t bfpack(float a, float b) {
    __nv_bfloat162 t = __floats2bfloat162_rn(a, b);
    return *reinterpret_cast<uint32_t*>(&t);
}
__device__ __forceinline__ float bfhi(float v) {
    return __bfloat162float(__float2bfloat16(v));
}
__device__ __forceinline__ float fexp(float x) {
    float y = fmaxf(x * 1.4426950408889634f, -125.0f);
    float r = rintf(y);
    float f = y - r;
    float p = 1.3333558146e-3f;
    p = fmaf(p, f, 9.6181291076e-3f);
    p = fmaf(p, f, 5.5504108665e-2f);
    p = fmaf(p, f, 2.4022650696e-1f);
    p = fmaf(p, f, 6.9314718056e-1f);
    p = fmaf(p, f, 1.0f);
    return __int_as_float(__float_as_int(p) + (((int)r) << 23));
}

// ---------------- batched weight splits ----------------
__global__ void wsplit4(const float* __restrict__ Wq, const float* __restrict__ Wk,
                        const float* __restrict__ Wv, const float* __restrict__ Wo,
                        bf16* __restrict__ Hq, bf16* __restrict__ Lq,
                        bf16* __restrict__ Hk, bf16* __restrict__ Lk,
                        bf16* __restrict__ Hv, bf16* __restrict__ Lv,
                        bf16* __restrict__ Ho, bf16* __restrict__ Lo) {
    const int m = blockIdx.y;
    const float* W = (m == 0) ? Wq : (m == 1) ? Wk : (m == 2) ? Wv : Wo;
    bf16* H = (m == 0) ? Hq : (m == 1) ? Hk : (m == 2) ? Hv : Ho;
    bf16* L = (m == 0) ? Lq : (m == 1) ? Lk : (m == 2) ? Lv : Lo;
    const size_t base = ((size_t)blockIdx.x * 4096) + threadIdx.x * 4;
    float4 v[4];
    #pragma unroll
    for (int j = 0; j < 4; ++j) v[j] = *(const float4*)&W[base + j * 1024];
    #pragma unroll
    for (int j = 0; j < 4; ++j) {
        uint2 hh, ll;
        hh.x = bfpack(v[j].x, v[j].y); hh.y = bfpack(v[j].z, v[j].w);
        ll.x = bfpack(v[j].x - bfhi(v[j].x), v[j].y - bfhi(v[j].y));
        ll.y = bfpack(v[j].z - bfhi(v[j].z), v[j].w - bfhi(v[j].w));
        *(uint2*)&H[base + j * 1024] = hh;
        *(uint2*)&L[base + j * 1024] = ll;
    }
}
__global__ void wsplit2(const float* __restrict__ W1, const float* __restrict__ W2,
                        bf16* __restrict__ H1, bf16* __restrict__ L1,
                        bf16* __restrict__ H2, bf16* __restrict__ L2) {
    const int m = blockIdx.y;
    const float* W = (m == 0) ? W1 : W2;
    bf16* H = (m == 0) ? H1 : H2;
    bf16* L = (m == 0) ? L1 : L2;
    const size_t base = ((size_t)blockIdx.x * 4096) + threadIdx.x * 4;
    float4 v[4];
    #pragma unroll
    for (int j = 0; j < 4; ++j) v[j] = *(const float4*)&W[base + j * 1024];
    #pragma unroll
    for (int j = 0; j < 4; ++j) {
        uint2 hh, ll;
        hh.x = bfpack(v[j].x, v[j].y); hh.y = bfpack(v[j].z, v[j].w);
        ll.x = bfpack(v[j].x - bfhi(v[j].x), v[j].y - bfhi(v[j].y));
        ll.y = bfpack(v[j].z - bfhi(v[j].z), v[j].w - bfhi(v[j].w));
        *(uint2*)&H[base + j * 1024] = hh;
        *(uint2*)&L[base + j * 1024] = ll;
    }
}

// ---------------- LayerNorm -> bf16 hi/lo ----------------
__global__ void ln_kernel(const float* __restrict__ x, const float* __restrict__ g,
                          const float* __restrict__ b, bf16* __restrict__ yh,
                          bf16* __restrict__ yl) {
    const int row = blockIdx.x, tid = threadIdx.x;
    const float4 xv = *(const float4*)&x[(size_t)row * D_MODEL + tid * 4];
    float s  = (xv.x + xv.y) + (xv.z + xv.w);
    float s2 = (xv.x * xv.x + xv.y * xv.y) + (xv.z * xv.z + xv.w * xv.w);
    __shared__ float red0[8], red1[8];
    #pragma unroll
    for (int o = 16; o > 0; o >>= 1) {
        s  += __shfl_down_sync(0xffffffffu, s, o);
        s2 += __shfl_down_sync(0xffffffffu, s2, o);
    }
    const int w = tid >> 5, l = tid & 31;
    if (l == 0) { red0[w] = s; red1[w] = s2; }
    __syncthreads();
    if (w == 0) {
        s  = (l < 8) ? red0[l] : 0.f;
        s2 = (l < 8) ? red1[l] : 0.f;
        #pragma unroll
        for (int o = 4; o > 0; o >>= 1) {
            s  += __shfl_down_sync(0xffffffffu, s, o);
            s2 += __shfl_down_sync(0xffffffffu, s2, o);
        }
        if (l == 0) { red0[0] = s; red1[0] = s2; }
    }
    __syncthreads();
    const float mu  = red0[0] * (1.f / D_MODEL);
    const float var = red1[0] * (1.f / D_MODEL) - mu * mu;
    const float inv = rsqrtf(var + 1e-5f);
    const float4 gv = *(const float4*)&g[tid * 4];
    const float4 bv = *(const float4*)&b[tid * 4];
    float o0 = (xv.x - mu) * inv * gv.x + bv.x;
    float o1 = (xv.y - mu) * inv * gv.y + bv.y;
    float o2 = (xv.z - mu) * inv * gv.z + bv.z;
    float o3 = (xv.w - mu) * inv * gv.w + bv.w;
    uint2 H, L;
    H.x = bfpack(o0, o1); H.y = bfpack(o2, o3);
    L.x = bfpack(o0 - bfhi(o0), o1 - bfhi(o1));
    L.y = bfpack(o2 - bfhi(o2), o3 - bfhi(o3));
    *(uint2*)&yh[(size_t)row * D_MODEL + tid * 4] = H;
    *(uint2*)&yl[(size_t)row * D_MODEL + tid * 4] = L;
}

// ---------------- bf16x3 mma GEMM with ldmatrix ----------------
template<int ACT, bool HAS_RES, bool OUT_HILO, int BN>
__global__ void __launch_bounds__(256, 2)
bgemm(const bf16* __restrict__ Ah, const bf16* __restrict__ Al,
      const bf16* __restrict__ W0h, const bf16* __restrict__ W0l,
      const bf16* __restrict__ W1h, const bf16* __restrict__ W1l,
      const bf16* __restrict__ W2h, const bf16* __restrict__ W2l,
      const float* __restrict__ b0, const float* __restrict__ b1, const float* __restrict__ b2,
      const float* __restrict__ Res,
      void* __restrict__ C0, void* __restrict__ C1, void* __restrict__ C2,
      void* __restrict__ Cl0, void* __restrict__ Cl1, void* __restrict__ Cl2,
      int N, int K) {
    constexpr int KB     = (BN == 64) ? 64 : 32;
    constexpr int KSTEPS = KB / 16;
    constexpr int A_STR  = KB * 2 + 16;
    constexpr int B_STR  = BN * 2 + 16;
    constexpr int ARR_A  = 128 * A_STR;
    constexpr int ARR_B  = KB * B_STR;
    constexpr int STAGE  = 2 * ARR_A + 2 * ARR_B;
    constexpr int NT     = BN / 16;
    constexpr int NPAIR  = NT / 2;
    constexpr bool DUAL  = (NT <= 4);

    extern __shared__ char smem[];
    const int z = blockIdx.z;
    const bf16* Wh    = (z == 0) ? W0h : (z == 1) ? W1h : W2h;
    const bf16* Wl    = (z == 0) ? W0l : (z == 1) ? W1l : W2l;
    const float* bias = (z == 0) ? b0 : (z == 1) ? b1 : b2;
    void* Cv          = (z == 0) ? C0 : (z == 1) ? C1 : C2;
    void* Clv         = (z == 0) ? Cl0 : (z == 1) ? Cl1 : Cl2;

    const int m0 = blockIdx.y * 128;
    const int n0 = blockIdx.x * BN;
    const int tid = threadIdx.x;
    const int wid = tid >> 5, lane = tid & 31;
    const int wrow = wid & 3, wcol = wid >> 2;
    const int lr = lane >> 2, lc = lane & 3;
    const int lrow = lane & 7, sub = lane >> 3;

    const uint32_t sbase = smem_u32(smem);
    const int NKB = K / KB;

    const uint32_t aoff = (uint32_t)(wrow * 32 + lrow + 8 * (sub & 1)) * (uint32_t)A_STR + 16u * (sub >> 1);
    const uint32_t boff = (uint32_t)(lrow + 8 * (sub & 1)) * (uint32_t)B_STR +
                          (uint32_t)(wcol * (BN / 2) + 8 * (sub >> 1)) * 2u;

    auto load_stage = [&](int kb, int s) {
        const int k0 = kb * KB;
        const uint32_t st = sbase + s * STAGE;
        #pragma unroll
        for (int f = tid; f < 128 * (KB / 8); f += 256) {
            const int r = f / (KB / 8), cc = f % (KB / 8);
            const uint32_t doff = (uint32_t)r * (uint32_t)A_STR + (uint32_t)cc * 16u;
            const size_t go = (size_t)(m0 + r) * K + k0 + cc * 8;
            cp16(st + doff, Ah + go);
            cp16(st + ARR_A + doff, Al + go);
        }
        #pragma unroll
        for (int f = tid; f < KB * (BN / 8); f += 256) {
            const int r = f / (BN / 8), cc = f % (BN / 8);
            const uint32_t doff = (uint32_t)r * (uint32_t)B_STR + (uint32_t)cc * 16u;
            const size_t go = (size_t)(k0 + r) * N + n0 + cc * 8;
            cp16(st + 2 * ARR_A + doff, Wh + go);
            cp16(st + 2 * ARR_A + ARR_B + doff, Wl + go);
        }
    };

    float acc[2][NT][4];
    float accx[DUAL ? 2 : 1][DUAL ? NT : 1][4];
    #pragma unroll
    for (int mt = 0; mt < 2; ++mt)
        #pragma unroll
        for (int nt = 0; nt < NT; ++nt)
            #pragma unroll
            for (int i = 0; i < 4; ++i) {
                acc[mt][nt][i] = 0.f;
                if (DUAL) accx[mt][nt][i] = 0.f;
            }

    auto domma = [&](int s) {
        const uint32_t stg = sbase + s * STAGE;
        #pragma unroll
        for (int kstep = 0; kstep < KSTEPS; ++kstep) {
            uint32_t ah[2][4], al[2][4];
            #pragma unroll
            for (int mt = 0; mt < 2; ++mt) {
                ldsm4(ah[mt], stg + aoff + mt * 16 * A_STR + kstep * 32);
                ldsm4(al[mt], stg + ARR_A + aoff + mt * 16 * A_STR + kstep * 32);
            }
            uint32_t bh[NT][2], bl[NT][2];
            #pragma unroll
            for (int p = 0; p < NPAIR; ++p) {
                uint32_t t[4];
                ldsm4t(t, stg + 2 * ARR_A + boff + p * 32 + kstep * 16 * B_STR);
                bh[2 * p][0] = t[0]; bh[2 * p][1] = t[1];
                bh[2 * p + 1][0] = t[2]; bh[2 * p + 1][1] = t[3];
                ldsm4t(t, stg + 2 * ARR_A + ARR_B + boff + p * 32 + kstep * 16 * B_STR);
                bl[2 * p][0] = t[0]; bl[2 * p][1] = t[1];
                bl[2 * p + 1][0] = t[2]; bl[2 * p + 1][1] = t[3];
            }
            #pragma unroll
            for (int nt = 0; nt < NT; ++nt) {
                if (DUAL) {
                    mma_bf16(acc[0][nt],  ah[0], bh[nt]);
                    mma_bf16(acc[1][nt],  ah[1], bh[nt]);
                    mma_bf16(accx[0][nt], al[0], bh[nt]);
                    mma_bf16(accx[1][nt], al[1], bh[nt]);
                    mma_bf16(accx[0][nt], ah[0], bl[nt]);
                    mma_bf16(accx[1][nt], ah[1], bl[nt]);
                } else {
                    mma_bf16(acc[0][nt], ah[0], bh[nt]);
                    mma_bf16(acc[1][nt], ah[1], bh[nt]);
                    mma_bf16(acc[0][nt], al[0], bh[nt]);
                    mma_bf16(acc[1][nt], al[1], bh[nt]);
                    mma_bf16(acc[0][nt], ah[0], bl[nt]);
                    mma_bf16(acc[1][nt], ah[1], bl[nt]);
                }
            }
        }
    };

    load_stage(0, 0);
    CP_COMMIT();
    for (int kb = 0; kb < NKB; ++kb) {
        const int s = kb & 1;
        CP_WAIT(0);
        __syncthreads();
        if (kb + 1 < NKB) {
            load_stage(kb + 1, s ^ 1);
            CP_COMMIT();
        }
        domma(s);
    }

    if (DUAL) {
        #pragma unroll
        for (int mt = 0; mt < 2; ++mt)
            #pragma unroll
            for (int nt = 0; nt < NT; ++nt)
                #pragma unroll
                for (int i = 0; i < 4; ++i)
                    acc[mt][nt][i] += accx[mt][nt][i];
    }

    #pragma unroll
    for (int nt = 0; nt < NT; ++nt) {
        const int col = n0 + wcol * (BN / 2) + nt * 8 + lc * 2;
        const float2 bv = *(const float2*)&bias[col];
        #pragma unroll
        for (int mt = 0; mt < 2; ++mt) {
            const int row = m0 + wrow * 32 + mt * 16 + lr;
            #pragma unroll
            for (int half = 0; half < 2; ++half) {
                const int r = row + half * 8;
                float vx = acc[mt][nt][half * 2 + 0] + bv.x;
                float vy = acc[mt][nt][half * 2 + 1] + bv.y;
                if (ACT == 1) {
                    vx = 0.5f * vx * (1.0f + erff(vx * 0.7071067811865475f));
                    vy = 0.5f * vy * (1.0f + erff(vy * 0.7071067811865475f));
                }
                if (HAS_RES) {
                    float2 rv = *(const float2*)&Res[(size_t)r * N + col];
                    vx += rv.x; vy += rv.y;
                }
                if (OUT_HILO) {
                    bf16* Ch = (bf16*)Cv;
                    bf16* Cl = (bf16*)Clv;
                    *(uint32_t*)&Ch[(size_t)r * N + col] = bfpack(vx, vy);
                    *(uint32_t*)&Cl[(size_t)r * N + col] =
                        bfpack(vx - bfhi(vx), vy - bfhi(vy));
                } else {
                    float2 o; o.x = vx; o.y = vy;
                    *(float2*)&((float*)Cv)[(size_t)r * N + col] = o;
                }
            }
        }
    }
}

// ---------------- flash attention v2: bf16x3, register P, ldmatrix ----------------
// CTA = 128 q-rows x head; 16 warps = 4 wrow x 4 wcol(kv-split); grid (16,16).
#define AS_KH(s)  ((s) * 73728 + 0)
#define AS_KL(s)  ((s) * 73728 + 18432)
#define AS_VH(s)  ((s) * 73728 + 36864)
#define AS_VL(s)  ((s) * 73728 + 55296)
#define AS_QH     147456
#define AS_QL     165888
#define AS_PMAX   184320
#define AS_PSUM   186368
#define AS_M      188416
#define AS_L      188928
#define SMEM_ATT2 189440

__global__ void __launch_bounds__(512, 1)
attn2(const bf16* __restrict__ Qh, const bf16* __restrict__ Ql,
      const bf16* __restrict__ Kh, const bf16* __restrict__ Kl,
      const bf16* __restrict__ Vh, const bf16* __restrict__ Vl,
      bf16* __restrict__ OH, bf16* __restrict__ OL) {
    extern __shared__ char smc[];
    const uint32_t sb = smem_u32(smc);
    const int qb = gridDim.x - 1 - blockIdx.x;
    const int h  = blockIdx.y;
    const int tid = threadIdx.x;
    const int wid = tid >> 5, lane = tid & 31;
    const int wrow = wid & 3, wcol = wid >> 2;
    const int lr = lane >> 2, lc = lane & 3;
    const int lrow = lane & 7, sub = lane >> 3;

    float* pmax = (float*)(smc + AS_PMAX);
    float* psum = (float*)(smc + AS_PSUM);
    float* m_sh = (float*)(smc + AS_M);
    float* l_sh = (float*)(smc + AS_L);

    // Q tile 128x64 hi/lo
    #pragma unroll
    for (int i = 0; i < 2; ++i) {
        const int f = tid + i * 512;
        const int r = f >> 3, c = f & 7;
        const size_t go = (size_t)(qb * 128 + r) * D_MODEL + h * 64 + c * 8;
        cp16(sb + AS_QH + r * 144 + c * 16, Qh + go);
        cp16(sb + AS_QL + r * 144 + c * 16, Ql + go);
    }
    auto load_kv = [&](int kb, int s) {
        #pragma unroll
        for (int i = 0; i < 2; ++i) {
            const int f = tid + i * 512;
            const int r = f >> 3, c = f & 7;
            const size_t go = (size_t)(kb * 128 + r) * D_MODEL + h * 64 + c * 8;
            cp16(sb + AS_KH(s) + r * 144 + c * 16, Kh + go);
            cp16(sb + AS_KL(s) + r * 144 + c * 16, Kl + go);
            cp16(sb + AS_VH(s) + r * 144 + c * 16, Vh + go);
            cp16(sb + AS_VL(s) + r * 144 + c * 16, Vl + go);
        }
    };
    load_kv(0, 0);
    CP_COMMIT();
    if (tid < 128) { m_sh[tid] = -1e30f; l_sh[tid] = 0.f; }

    const float slope = exp2f(-0.5f * (float)(h + 1));
    float oacc[2][8][4] = {};

    const uint32_t aoffQ = sb + AS_QH + (uint32_t)(wrow * 32 + lrow + 8 * (sub & 1)) * 144u + 16u * (sub >> 1);
    const uint32_t bSoff = (uint32_t)(32 * wcol + lrow + 8 * (sub >> 1)) * 144u + 16u * (sub & 1);
    const uint32_t bVoff = (uint32_t)(32 * wcol + lrow + 8 * (sub & 1)) * 144u + (uint32_t)(8 * (sub >> 1)) * 2u;

    for (int kb = 0; kb <= qb; ++kb) {
        const int s = kb & 1;
        CP_WAIT(0);
        __syncthreads();
        if (kb < qb) { load_kv(kb + 1, s ^ 1); CP_COMMIT(); }

        // S = Q K^T (bf16 x3); K natural [kv][d] -> B frags via non-trans ldsm
        float sacc[2][4][4] = {};
        #pragma unroll
        for (int ks = 0; ks < 4; ++ks) {
            uint32_t qhf[2][4], qlf[2][4];
            #pragma unroll
            for (int mt = 0; mt < 2; ++mt) {
                ldsm4(qhf[mt], aoffQ + mt * 2304 + ks * 32);
                ldsm4(qlf[mt], aoffQ + 18432 + mt * 2304 + ks * 32);
            }
            uint32_t khf[4][2], klf[4][2];
            #pragma unroll
            for (int p = 0; p < 2; ++p) {
                uint32_t t[4];
                ldsm4(t, sb + AS_KH(s) + bSoff + p * 2304 + ks * 32);
                khf[2 * p][0] = t[0]; khf[2 * p][1] = t[1];
                khf[2 * p + 1][0] = t[2]; khf[2 * p + 1][1] = t[3];
                ldsm4(t, sb + AS_KL(s) + bSoff + p * 2304 + ks * 32);
                klf[2 * p][0] = t[0]; klf[2 * p][1] = t[1];
                klf[2 * p + 1][0] = t[2]; klf[2 * p + 1][1] = t[3];
            }
            #pragma unroll
            for (int nt = 0; nt < 4; ++nt) {
                mma_bf16(sacc[0][nt], qhf[0], khf[nt]);
                mma_bf16(sacc[1][nt], qhf[1], khf[nt]);
                mma_bf16(sacc[0][nt], qlf[0], khf[nt]);
                mma_bf16(sacc[1][nt], qlf[1], khf[nt]);
                mma_bf16(sacc[0][nt], qhf[0], klf[nt]);
                mma_bf16(sacc[1][nt], qhf[1], klf[nt]);
            }
        }

        // scale + alibi + causal; quad row-max
        float mxa[2], mxb[2];
        #pragma unroll
        for (int mt = 0; mt < 2; ++mt) {
            const int ra = qb * 128 + wrow * 32 + mt * 16 + lr, rb = ra + 8;
            float ma = -1e30f, mb = -1e30f;
            #pragma unroll
            for (int nt = 0; nt < 4; ++nt) {
                const int c0 = kb * 128 + 32 * wcol + 8 * nt + 2 * lc;
                float* sv = sacc[mt][nt];
                sv[0] = (c0     <= ra) ? fmaf(sv[0], 0.125f, slope * (float)(c0 - ra))     : -1e30f;
                sv[1] = (c0 + 1 <= ra) ? fmaf(sv[1], 0.125f, slope * (float)(c0 + 1 - ra)) : -1e30f;
                sv[2] = (c0     <= rb) ? fmaf(sv[2], 0.125f, slope * (float)(c0 - rb))     : -1e30f;
                sv[3] = (c0 + 1 <= rb) ? fmaf(sv[3], 0.125f, slope * (float)(c0 + 1 - rb)) : -1e30f;
                ma = fmaxf(ma, fmaxf(sv[0], sv[1]));
                mb = fmaxf(mb, fmaxf(sv[2], sv[3]));
            }
            ma = fmaxf(ma, __shfl_xor_sync(0xffffffffu, ma, 1));
            ma = fmaxf(ma, __shfl_xor_sync(0xffffffffu, ma, 2));
            mb = fmaxf(mb, __shfl_xor_sync(0xffffffffu, mb, 1));
            mb = fmaxf(mb, __shfl_xor_sync(0xffffffffu, mb, 2));
            mxa[mt] = ma; mxb[mt] = mb;
        }
        if (lc == 0) {
            #pragma unroll
            for (int mt = 0; mt < 2; ++mt) {
                pmax[wcol * 128 + wrow * 32 + mt * 16 + lr]     = mxa[mt];
                pmax[wcol * 128 + wrow * 32 + mt * 16 + lr + 8] = mxb[mt];
            }
        }
        __syncthreads();

        float mna[2], mnb[2], ala[2], alb[2];
        #pragma unroll
        for (int mt = 0; mt < 2; ++mt) {
            const int rla = wrow * 32 + mt * 16 + lr, rlb = rla + 8;
            const float pa = fmaxf(fmaxf(pmax[rla], pmax[128 + rla]),
                                   fmaxf(pmax[256 + rla], pmax[384 + rla]));
            const float pb = fmaxf(fmaxf(pmax[rlb], pmax[128 + rlb]),
                                   fmaxf(pmax[256 + rlb], pmax[384 + rlb]));
            const float moa = m_sh[rla], mob = m_sh[rlb];
            mna[mt] = fmaxf(moa, pa); mnb[mt] = fmaxf(mob, pb);
            ala[mt] = fexp(moa - mna[mt]); alb[mt] = fexp(mob - mnb[mt]);
        }
        #pragma unroll
        for (int mt = 0; mt < 2; ++mt) {
            float sa = 0.f, sbv = 0.f;
            #pragma unroll
            for (int nt = 0; nt < 4; ++nt) {
                float* sv = sacc[mt][nt];
                sv[0] = fexp(sv[0] - mna[mt]); sv[1] = fexp(sv[1] - mna[mt]);
                sv[2] = fexp(sv[2] - mnb[mt]); sv[3] = fexp(sv[3] - mnb[mt]);
                sa += sv[0] + sv[1]; sbv += sv[2] + sv[3];
            }
            sa  += __shfl_xor_sync(0xffffffffu, sa, 1);
            sa  += __shfl_xor_sync(0xffffffffu, sa, 2);
            sbv += __shfl_xor_sync(0xffffffffu, sbv, 1);
            sbv += __shfl_xor_sync(0xffffffffu, sbv, 2);
            if (lc == 0) {
                psum[wcol * 128 + wrow * 32 + mt * 16 + lr]     = sa;
                psum[wcol * 128 + wrow * 32 + mt * 16 + lr + 8] = sbv;
            }
        }
        // rescale O
        #pragma unroll
        for (int mt = 0; mt < 2; ++mt)
            #pragma unroll
            for (int nt = 0; nt < 8; ++nt) {
                oacc[mt][nt][0] *= ala[mt]; oacc[mt][nt][1] *= ala[mt];
                oacc[mt][nt][2] *= alb[mt]; oacc[mt][nt][3] *= alb[mt];
            }
        __syncthreads();

        if (wcol == 0 && lc == 0) {
            #pragma unroll
            for (int mt = 0; mt < 2; ++mt) {
                const int rla = wrow * 32 + mt * 16 + lr, rlb = rla + 8;
                l_sh[rla] = l_sh[rla] * ala[mt] +
                            (psum[rla] + psum[128 + rla]) + (psum[256 + rla] + psum[384 + rla]);
                l_sh[rlb] = l_sh[rlb] * alb[mt] +
                            (psum[rlb] + psum[128 + rlb]) + (psum[256 + rlb] + psum[384 + rlb]);
                m_sh[rla] = mna[mt]; m_sh[rlb] = mnb[mt];
            }
        }

        // O += P V : C-frag of S == A-frag of PV (bit-exact mapping), V via ldsm4t
        #pragma unroll
        for (int g = 0; g < 2; ++g) {
            uint32_t pah[2][4], pal[2][4];
            #pragma unroll
            for (int mt = 0; mt < 2; ++mt) {
                const float* s0 = sacc[mt][2 * g];
                const float* s1 = sacc[mt][2 * g + 1];
                pah[mt][0] = bfpack(s0[0], s0[1]); pah[mt][1] = bfpack(s0[2], s0[3]);
                pah[mt][2] = bfpack(s1[0], s1[1]); pah[mt][3] = bfpack(s1[2], s1[3]);
                pal[mt][0] = bfpack(s0[0] - bfhi(s0[0]), s0[1] - bfhi(s0[1]));
                pal[mt][1] = bfpack(s0[2] - bfhi(s0[2]), s0[3] - bfhi(s0[3]));
                pal[mt][2] = bfpack(s1[0] - bfhi(s1[0]), s1[1] - bfhi(s1[1]));
                pal[mt][3] = bfpack(s1[2] - bfhi(s1[2]), s1[3] - bfhi(s1[3]));
            }
            #pragma unroll
            for (int p = 0; p < 4; ++p) {
                uint32_t vh[2][2], vl[2][2], t[4];
                ldsm4t(t, sb + AS_VH(s) + bVoff + g * 2304 + p * 32);
                vh[0][0] = t[0]; vh[0][1] = t[1]; vh[1][0] = t[2]; vh[1][1] = t[3];
                ldsm4t(t, sb + AS_VL(s) + bVoff + g * 2304 + p * 32);
                vl[0][0] = t[0]; vl[0][1] = t[1]; vl[1][0] = t[2]; vl[1][1] = t[3];
                #pragma unroll
                for (int q2 = 0; q2 < 2; ++q2) {
                    const int nt = 2 * p + q2;
                    mma_bf16(oacc[0][nt], pah[0], vh[q2]);
                    mma_bf16(oacc[1][nt], pah[1], vh[q2]);
                    mma_bf16(oacc[0][nt], pal[0], vh[q2]);
                    mma_bf16(oacc[1][nt], pal[1], vh[q2]);
                    mma_bf16(oacc[0][nt], pah[0], vl[q2]);
                    mma_bf16(oacc[1][nt], pah[1], vl[q2]);
                }
            }
        }
    }

    // reduce wcol partials through smem (aliases dead K region), normalize, store
    __syncthreads();
    float* Ob = (float*)smc;
    #pragma unroll
    for (int w = 0; w < 4; ++w) {
        if (wcol == w) {
            #pragma unroll
            for (int mt = 0; mt < 2; ++mt) {
                const int rla = wrow * 32 + mt * 16 + lr, rlb = rla + 8;
                #pragma unroll
                for (int nt = 0; nt < 8; ++nt) {
                    const int d0 = 8 * nt + 2 * lc;
                    if (w == 0) {
                        Ob[rla * 64 + d0]     = oacc[mt][nt][0];
                        Ob[rla * 64 + d0 + 1] = oacc[mt][nt][1];
                        Ob[rlb * 64 + d0]     = oacc[mt][nt][2];
                        Ob[rlb * 64 + d0 + 1] = oacc[mt][nt][3];
                    } else {
                        Ob[rla * 64 + d0]     += oacc[mt][nt][0];
                        Ob[rla * 64 + d0 + 1] += oacc[mt][nt][1];
                        Ob[rlb * 64 + d0]     += oacc[mt][nt][2];
                        Ob[rlb * 64 + d0 + 1] += oacc[mt][nt][3];
                    }
                }
            }
        }
        __syncthreads();
    }
    #pragma unroll
    for (int i = 0; i < 16; ++i) {
        const int f = tid + i * 512;
        const int r = f >> 6, d = f & 63;
        const float val = Ob[f] / l_sh[r];
        const size_t go = (size_t)(qb * 128 + r) * D_MODEL + h * 64 + d;
        OH[go] = __float2bfloat16(val);
        OL[go] = __float2bfloat16(val - bfhi(val));
    }
}

// ---------------- launch ----------------
extern "C" void kernel_launch(void* const* d_in, const int* in_sizes, int n_in,
                              void* d_out, int out_size) {
    const float* x   = (const float*)d_in[0];
    const float* wq  = (const float*)d_in[3];
    const float* bq  = (const float*)d_in[4];
    const float* wk  = (const float*)d_in[5];
    const float* bk  = (const float*)d_in[6];
    const float* wv  = (const float*)d_in[7];
    const float* bv  = (const float*)d_in[8];
    const float* wo  = (const float*)d_in[9];
    const float* bo  = (const float*)d_in[10];
    const float* w1  = (const float*)d_in[11];
    const float* b1  = (const float*)d_in[12];
    const float* w2  = (const float*)d_in[13];
    const float* b2  = (const float*)d_in[14];
    const float* g1  = (const float*)d_in[15];
    const float* be1 = (const float*)d_in[16];
    const float* g2  = (const float*)d_in[17];
    const float* be2 = (const float*)d_in[18];
    float* out = (float*)d_out;

    float* p_x1;
    bf16 *p_xnh, *p_xnl, *p_ah, *p_al, *p_hh, *p_hl;
    bf16 *p_qh, *p_ql, *p_kh, *p_kl, *p_vh, *p_vl;
    bf16 *p_wqh, *p_wql, *p_wkh, *p_wkl, *p_wvh, *p_wvl, *p_woh, *p_wol;
    bf16 *p_w1h, *p_w1l, *p_w2h, *p_w2l;
    cudaGetSymbolAddress((void**)&p_x1,  g_x1);
    cudaGetSymbolAddress((void**)&p_xnh, g_xnh);
    cudaGetSymbolAddress((void**)&p_xnl, g_xnl);
    cudaGetSymbolAddress((void**)&p_qh,  g_qh);
    cudaGetSymbolAddress((void**)&p_ql,  g_ql);
    cudaGetSymbolAddress((void**)&p_kh,  g_kh);
    cudaGetSymbolAddress((void**)&p_kl,  g_kl);
    cudaGetSymbolAddress((void**)&p_vh,  g_vh);
    cudaGetSymbolAddress((void**)&p_vl,  g_vl);
    cudaGetSymbolAddress((void**)&p_ah,  g_ah);
    cudaGetSymbolAddress((void**)&p_al,  g_al);
    cudaGetSymbolAddress((void**)&p_hh,  g_hh);
    cudaGetSymbolAddress((void**)&p_hl,  g_hl);
    cudaGetSymbolAddress((void**)&p_wqh, g_wqh);
    cudaGetSymbolAddress((void**)&p_wql, g_wql);
    cudaGetSymbolAddress((void**)&p_wkh, g_wkh);
    cudaGetSymbolAddress((void**)&p_wkl, g_wkl);
    cudaGetSymbolAddress((void**)&p_wvh, g_wvh);
    cudaGetSymbolAddress((void**)&p_wvl, g_wvl);
    cudaGetSymbolAddress((void**)&p_woh, g_woh);
    cudaGetSymbolAddress((void**)&p_wol, g_wol);
    cudaGetSymbolAddress((void**)&p_w1h, g_w1h);
    cudaGetSymbolAddress((void**)&p_w1l, g_w1l);
    cudaGetSymbolAddress((void**)&p_w2h, g_w2h);
    cudaGetSymbolAddress((void**)&p_w2l, g_w2l);

    const int smem64  = 2 * (2 * 128 * 144 + 2 * 64 * 144);
    const int smem128 = 2 * (2 * 128 * 80 + 2 * 32 * 272);

    cudaFuncSetAttribute(bgemm<0, false, true,  64>,  cudaFuncAttributeMaxDynamicSharedMemorySize, smem64);
    cudaFuncSetAttribute(bgemm<0, true,  false, 64>,  cudaFuncAttributeMaxDynamicSharedMemorySize, smem64);
    cudaFuncSetAttribute(bgemm<1, false, true,  128>, cudaFuncAttributeMaxDynamicSharedMemorySize, smem128);
    cudaFuncSetAttribute(attn2, cudaFuncAttributeMaxDynamicSharedMemorySize, SMEM_ATT2);

    wsplit4<<<dim3(256, 4), 256>>>(wq, wk, wv, wo,
                                   p_wqh, p_wql, p_wkh, p_wkl,
                                   p_wvh, p_wvl, p_woh, p_wol);
    ln_kernel<<<T_SEQ, 256>>>(x, g1, be1, p_xnh, p_xnl);

    // fused QKV -> bf16 hi/lo
    bgemm<0, false, true, 64><<<dim3(D_MODEL / 64, T_SEQ / 128, 3), 256, smem64>>>(
        p_xnh, p_xnl, p_wqh, p_wql, p_wkh, p_wkl, p_wvh, p_wvl,
        bq, bk, bv, nullptr, p_qh, p_kh, p_vh, p_ql, p_kl, p_vl, D_MODEL, D_MODEL);

    // attention v2  <-- profiled position
    attn2<<<dim3(16, N_HEADS), 512, SMEM_ATT2>>>(p_qh, p_ql, p_kh, p_kl, p_vh, p_vl, p_ah, p_al);

    // O projection + residual(x)
    bgemm<0, true, false, 64><<<dim3(D_MODEL / 64, T_SEQ / 128, 1), 256, smem64>>>(
        p_ah, p_al, p_woh, p_wol, p_woh, p_wol, p_woh, p_wol,
        bo, bo, bo, x, p_x1, p_x1, p_x1, nullptr, nullptr, nullptr, D_MODEL, D_MODEL);

    ln_kernel<<<T_SEQ, 256>>>(p_x1, g2, be2, p_xnh, p_xnl);
    wsplit2<<<dim3(1024, 2), 256>>>(w1, w2, p_w1h, p_w1l, p_w2h, p_w2l);

    // FFN1 + GELU -> hi/lo
    bgemm<1, false, true, 128><<<dim3(FFN_DIM / 128, T_SEQ / 128, 1), 256, smem128>>>(
        p_xnh, p_xnl, p_w1h, p_w1l, p_w1h, p_w1l, p_w1h, p_w1l,
        b1, b1, b1, nullptr, p_hh, p_hh, p_hh, p_hl, p_hl, p_hl, FFN_DIM, D_MODEL);

    // FFN2 + residual(x1)
    bgemm<0, true, false, 64><<<dim3(D_MODEL / 64, T_SEQ / 128, 1), 256, smem64>>>(
        p_hh, p_hl, p_w2h, p_w2l, p_w2h, p_w2l, p_w2h, p_w2l,
        b2, b2, b2, p_x1, out, out, out, nullptr, nullptr, nullptr, D_MODEL, FFN_DIM);
}

// round 12
// speedup vs baseline: 1.1357x; 1.0406x over previous
#include <cuda_runtime.h>
#include <cuda_bf16.h>
#include <math.h>
#include <stdint.h>

#define T_SEQ 2048
#define D_MODEL 1024
#define N_HEADS 16
#define HEAD_DIM 64
#define FFN_DIM 4096
typedef __nv_bfloat16 bf16;

// ---------------- scratch ----------------
__device__ float g_x1[T_SEQ * D_MODEL];
__device__ bf16  g_xnh[T_SEQ * D_MODEL], g_xnl[T_SEQ * D_MODEL];
__device__ bf16  g_qh[T_SEQ * D_MODEL], g_ql[T_SEQ * D_MODEL];
__device__ bf16  g_kh[T_SEQ * D_MODEL], g_kl[T_SEQ * D_MODEL];
__device__ bf16  g_vh[T_SEQ * D_MODEL], g_vl[T_SEQ * D_MODEL];
__device__ bf16  g_ah[T_SEQ * D_MODEL], g_al[T_SEQ * D_MODEL];
__device__ bf16  g_hh[T_SEQ * FFN_DIM], g_hl[T_SEQ * FFN_DIM];
__device__ bf16 g_wqh[D_MODEL * D_MODEL], g_wql[D_MODEL * D_MODEL];
__device__ bf16 g_wkh[D_MODEL * D_MODEL], g_wkl[D_MODEL * D_MODEL];
__device__ bf16 g_wvh[D_MODEL * D_MODEL], g_wvl[D_MODEL * D_MODEL];
__device__ bf16 g_woh[D_MODEL * D_MODEL], g_wol[D_MODEL * D_MODEL];
__device__ bf16 g_w1h[FFN_DIM * D_MODEL], g_w1l[FFN_DIM * D_MODEL];
__device__ bf16 g_w2h[D_MODEL * FFN_DIM], g_w2l[D_MODEL * FFN_DIM];

// ---------------- helpers ----------------
__device__ __forceinline__ uint32_t smem_u32(const void* p) {
    uint32_t a;
    asm("{ .reg .u64 t; cvta.to.shared.u64 t, %1; cvt.u32.u64 %0, t; }" : "=r"(a) : "l"(p));
    return a;
}
__device__ __forceinline__ void cp16(uint32_t s, const void* g) {
    asm volatile("cp.async.cg.shared.global [%0], [%1], 16;" :: "r"(s), "l"(g));
}
#define CP_COMMIT() asm volatile("cp.async.commit_group;" ::: "memory")
#define CP_WAIT(n)  asm volatile("cp.async.wait_group %0;" :: "n"(n) : "memory")

__device__ __forceinline__ void ldsm4(uint32_t* r, uint32_t addr) {
    asm volatile("ldmatrix.sync.aligned.m8n8.x4.shared.b16 {%0,%1,%2,%3}, [%4];"
        : "=r"(r[0]), "=r"(r[1]), "=r"(r[2]), "=r"(r[3]) : "r"(addr));
}
__device__ __forceinline__ void ldsm4t(uint32_t* r, uint32_t addr) {
    asm volatile("ldmatrix.sync.aligned.m8n8.x4.trans.shared.b16 {%0,%1,%2,%3}, [%4];"
        : "=r"(r[0]), "=r"(r[1]), "=r"(r[2]), "=r"(r[3]) : "r"(addr));
}
__device__ __forceinline__ void mma_bf16(float* d, const uint32_t* a, const uint32_t* b) {
    asm volatile(
        "mma.sync.aligned.m16n8k16.row.col.f32.bf16.bf16.f32 "
        "{%0,%1,%2,%3}, {%4,%5,%6,%7}, {%8,%9}, {%0,%1,%2,%3};"
        : "+f"(d[0]), "+f"(d[1]), "+f"(d[2]), "+f"(d[3])
        : "r"(a[0]), "r"(a[1]), "r"(a[2]), "r"(a[3]), "r"(b[0]), "r"(b[1]));
}
__device__ __forceinline__ uint32_t bfpack(float a, float b) {
    __nv_bfloat162 t = __floats2bfloat162_rn(a, b);
    return *reinterpret_cast<uint32_t*>(&t);
}
__device__ __forceinline__ float bfhi(float v) {
    return __bfloat162float(__float2bfloat16(v));
}
// raw hardware exp2 (MUFU.EX2) — logits pre-scaled into log2 domain
__device__ __forceinline__ float ex2(float x) {
    float y;
    asm("ex2.approx.ftz.f32 %0, %1;" : "=f"(y) : "f"(x));
    return y;
}

// ---------------- batched weight splits ----------------
__global__ void wsplit4(const float* __restrict__ Wq, const float* __restrict__ Wk,
                        const float* __restrict__ Wv, const float* __restrict__ Wo,
                        bf16* __restrict__ Hq, bf16* __restrict__ Lq,
                        bf16* __restrict__ Hk, bf16* __restrict__ Lk,
                        bf16* __restrict__ Hv, bf16* __restrict__ Lv,
                        bf16* __restrict__ Ho, bf16* __restrict__ Lo) {
    const int m = blockIdx.y;
    const float* W = (m == 0) ? Wq : (m == 1) ? Wk : (m == 2) ? Wv : Wo;
    bf16* H = (m == 0) ? Hq : (m == 1) ? Hk : (m == 2) ? Hv : Ho;
    bf16* L = (m == 0) ? Lq : (m == 1) ? Lk : (m == 2) ? Lv : Lo;
    const size_t base = ((size_t)blockIdx.x * 4096) + threadIdx.x * 4;
    float4 v[4];
    #pragma unroll
    for (int j = 0; j < 4; ++j) v[j] = *(const float4*)&W[base + j * 1024];
    #pragma unroll
    for (int j = 0; j < 4; ++j) {
        uint2 hh, ll;
        hh.x = bfpack(v[j].x, v[j].y); hh.y = bfpack(v[j].z, v[j].w);
        ll.x = bfpack(v[j].x - bfhi(v[j].x), v[j].y - bfhi(v[j].y));
        ll.y = bfpack(v[j].z - bfhi(v[j].z), v[j].w - bfhi(v[j].w));
        *(uint2*)&H[base + j * 1024] = hh;
        *(uint2*)&L[base + j * 1024] = ll;
    }
}
__global__ void wsplit2(const float* __restrict__ W1, const float* __restrict__ W2,
                        bf16* __restrict__ H1, bf16* __restrict__ L1,
                        bf16* __restrict__ H2, bf16* __restrict__ L2) {
    const int m = blockIdx.y;
    const float* W = (m == 0) ? W1 : W2;
    bf16* H = (m == 0) ? H1 : H2;
    bf16* L = (m == 0) ? L1 : L2;
    const size_t base = ((size_t)blockIdx.x * 4096) + threadIdx.x * 4;
    float4 v[4];
    #pragma unroll
    for (int j = 0; j < 4; ++j) v[j] = *(const float4*)&W[base + j * 1024];
    #pragma unroll
    for (int j = 0; j < 4; ++j) {
        uint2 hh, ll;
        hh.x = bfpack(v[j].x, v[j].y); hh.y = bfpack(v[j].z, v[j].w);
        ll.x = bfpack(v[j].x - bfhi(v[j].x), v[j].y - bfhi(v[j].y));
        ll.y = bfpack(v[j].z - bfhi(v[j].z), v[j].w - bfhi(v[j].w));
        *(uint2*)&H[base + j * 1024] = hh;
        *(uint2*)&L[base + j * 1024] = ll;
    }
}

// ---------------- LayerNorm -> bf16 hi/lo ----------------
__global__ void ln_kernel(const float* __restrict__ x, const float* __restrict__ g,
                          const float* __restrict__ b, bf16* __restrict__ yh,
                          bf16* __restrict__ yl) {
    const int row = blockIdx.x, tid = threadIdx.x;
    const float4 xv = *(const float4*)&x[(size_t)row * D_MODEL + tid * 4];
    float s  = (xv.x + xv.y) + (xv.z + xv.w);
    float s2 = (xv.x * xv.x + xv.y * xv.y) + (xv.z * xv.z + xv.w * xv.w);
    __shared__ float red0[8], red1[8];
    #pragma unroll
    for (int o = 16; o > 0; o >>= 1) {
        s  += __shfl_down_sync(0xffffffffu, s, o);
        s2 += __shfl_down_sync(0xffffffffu, s2, o);
    }
    const int w = tid >> 5, l = tid & 31;
    if (l == 0) { red0[w] = s; red1[w] = s2; }
    __syncthreads();
    if (w == 0) {
        s  = (l < 8) ? red0[l] : 0.f;
        s2 = (l < 8) ? red1[l] : 0.f;
        #pragma unroll
        for (int o = 4; o > 0; o >>= 1) {
            s  += __shfl_down_sync(0xffffffffu, s, o);
            s2 += __shfl_down_sync(0xffffffffu, s2, o);
        }
        if (l == 0) { red0[0] = s; red1[0] = s2; }
    }
    __syncthreads();
    const float mu  = red0[0] * (1.f / D_MODEL);
    const float var = red1[0] * (1.f / D_MODEL) - mu * mu;
    const float inv = rsqrtf(var + 1e-5f);
    const float4 gv = *(const float4*)&g[tid * 4];
    const float4 bv = *(const float4*)&b[tid * 4];
    float o0 = (xv.x - mu) * inv * gv.x + bv.x;
    float o1 = (xv.y - mu) * inv * gv.y + bv.y;
    float o2 = (xv.z - mu) * inv * gv.z + bv.z;
    float o3 = (xv.w - mu) * inv * gv.w + bv.w;
    uint2 H, L;
    H.x = bfpack(o0, o1); H.y = bfpack(o2, o3);
    L.x = bfpack(o0 - bfhi(o0), o1 - bfhi(o1));
    L.y = bfpack(o2 - bfhi(o2), o3 - bfhi(o3));
    *(uint2*)&yh[(size_t)row * D_MODEL + tid * 4] = H;
    *(uint2*)&yl[(size_t)row * D_MODEL + tid * 4] = L;
}

// ---------------- bf16x3 mma GEMM with ldmatrix ----------------
template<int ACT, bool HAS_RES, bool OUT_HILO, int BN>
__global__ void __launch_bounds__(256, 2)
bgemm(const bf16* __restrict__ Ah, const bf16* __restrict__ Al,
      const bf16* __restrict__ W0h, const bf16* __restrict__ W0l,
      const bf16* __restrict__ W1h, const bf16* __restrict__ W1l,
      const bf16* __restrict__ W2h, const bf16* __restrict__ W2l,
      const float* __restrict__ b0, const float* __restrict__ b1, const float* __restrict__ b2,
      const float* __restrict__ Res,
      void* __restrict__ C0, void* __restrict__ C1, void* __restrict__ C2,
      void* __restrict__ Cl0, void* __restrict__ Cl1, void* __restrict__ Cl2,
      int N, int K) {
    constexpr int KB     = (BN == 64) ? 64 : 32;
    constexpr int KSTEPS = KB / 16;
    constexpr int A_STR  = KB * 2 + 16;
    constexpr int B_STR  = BN * 2 + 16;
    constexpr int ARR_A  = 128 * A_STR;
    constexpr int ARR_B  = KB * B_STR;
    constexpr int STAGE  = 2 * ARR_A + 2 * ARR_B;
    constexpr int NT     = BN / 16;
    constexpr int NPAIR  = NT / 2;
    constexpr bool DUAL  = (NT <= 4);

    extern __shared__ char smem[];
    const int z = blockIdx.z;
    const bf16* Wh    = (z == 0) ? W0h : (z == 1) ? W1h : W2h;
    const bf16* Wl    = (z == 0) ? W0l : (z == 1) ? W1l : W2l;
    const float* bias = (z == 0) ? b0 : (z == 1) ? b1 : b2;
    void* Cv          = (z == 0) ? C0 : (z == 1) ? C1 : C2;
    void* Clv         = (z == 0) ? Cl0 : (z == 1) ? Cl1 : Cl2;

    const int m0 = blockIdx.y * 128;
    const int n0 = blockIdx.x * BN;
    const int tid = threadIdx.x;
    const int wid = tid >> 5, lane = tid & 31;
    const int wrow = wid & 3, wcol = wid >> 2;
    const int lr = lane >> 2, lc = lane & 3;
    const int lrow = lane & 7, sub = lane >> 3;

    const uint32_t sbase = smem_u32(smem);
    const int NKB = K / KB;

    const uint32_t aoff = (uint32_t)(wrow * 32 + lrow + 8 * (sub & 1)) * (uint32_t)A_STR + 16u * (sub >> 1);
    const uint32_t boff = (uint32_t)(lrow + 8 * (sub & 1)) * (uint32_t)B_STR +
                          (uint32_t)(wcol * (BN / 2) + 8 * (sub >> 1)) * 2u;

    auto load_stage = [&](int kb, int s) {
        const int k0 = kb * KB;
        const uint32_t st = sbase + s * STAGE;
        #pragma unroll
        for (int f = tid; f < 128 * (KB / 8); f += 256) {
            const int r = f / (KB / 8), cc = f % (KB / 8);
            const uint32_t doff = (uint32_t)r * (uint32_t)A_STR + (uint32_t)cc * 16u;
            const size_t go = (size_t)(m0 + r) * K + k0 + cc * 8;
            cp16(st + doff, Ah + go);
            cp16(st + ARR_A + doff, Al + go);
        }
        #pragma unroll
        for (int f = tid; f < KB * (BN / 8); f += 256) {
            const int r = f / (BN / 8), cc = f % (BN / 8);
            const uint32_t doff = (uint32_t)r * (uint32_t)B_STR + (uint32_t)cc * 16u;
            const size_t go = (size_t)(k0 + r) * N + n0 + cc * 8;
            cp16(st + 2 * ARR_A + doff, Wh + go);
            cp16(st + 2 * ARR_A + ARR_B + doff, Wl + go);
        }
    };

    float acc[2][NT][4];
    float accx[DUAL ? 2 : 1][DUAL ? NT : 1][4];
    #pragma unroll
    for (int mt = 0; mt < 2; ++mt)
        #pragma unroll
        for (int nt = 0; nt < NT; ++nt)
            #pragma unroll
            for (int i = 0; i < 4; ++i) {
                acc[mt][nt][i] = 0.f;
                if (DUAL) accx[mt][nt][i] = 0.f;
            }

    auto domma = [&](int s) {
        const uint32_t stg = sbase + s * STAGE;
        #pragma unroll
        for (int kstep = 0; kstep < KSTEPS; ++kstep) {
            uint32_t ah[2][4], al[2][4];
            #pragma unroll
            for (int mt = 0; mt < 2; ++mt) {
                ldsm4(ah[mt], stg + aoff + mt * 16 * A_STR + kstep * 32);
                ldsm4(al[mt], stg + ARR_A + aoff + mt * 16 * A_STR + kstep * 32);
            }
            uint32_t bh[NT][2], bl[NT][2];
            #pragma unroll
            for (int p = 0; p < NPAIR; ++p) {
                uint32_t t[4];
                ldsm4t(t, stg + 2 * ARR_A + boff + p * 32 + kstep * 16 * B_STR);
                bh[2 * p][0] = t[0]; bh[2 * p][1] = t[1];
                bh[2 * p + 1][0] = t[2]; bh[2 * p + 1][1] = t[3];
                ldsm4t(t, stg + 2 * ARR_A + ARR_B + boff + p * 32 + kstep * 16 * B_STR);
                bl[2 * p][0] = t[0]; bl[2 * p][1] = t[1];
                bl[2 * p + 1][0] = t[2]; bl[2 * p + 1][1] = t[3];
            }
            #pragma unroll
            for (int nt = 0; nt < NT; ++nt) {
                if (DUAL) {
                    mma_bf16(acc[0][nt],  ah[0], bh[nt]);
                    mma_bf16(acc[1][nt],  ah[1], bh[nt]);
                    mma_bf16(accx[0][nt], al[0], bh[nt]);
                    mma_bf16(accx[1][nt], al[1], bh[nt]);
                    mma_bf16(accx[0][nt], ah[0], bl[nt]);
                    mma_bf16(accx[1][nt], ah[1], bl[nt]);
                } else {
                    mma_bf16(acc[0][nt], ah[0], bh[nt]);
                    mma_bf16(acc[1][nt], ah[1], bh[nt]);
                    mma_bf16(acc[0][nt], al[0], bh[nt]);
                    mma_bf16(acc[1][nt], al[1], bh[nt]);
                    mma_bf16(acc[0][nt], ah[0], bl[nt]);
                    mma_bf16(acc[1][nt], ah[1], bl[nt]);
                }
            }
        }
    };

    load_stage(0, 0);
    CP_COMMIT();
    for (int kb = 0; kb < NKB; ++kb) {
        const int s = kb & 1;
        CP_WAIT(0);
        __syncthreads();
        if (kb + 1 < NKB) {
            load_stage(kb + 1, s ^ 1);
            CP_COMMIT();
        }
        domma(s);
    }

    if (DUAL) {
        #pragma unroll
        for (int mt = 0; mt < 2; ++mt)
            #pragma unroll
            for (int nt = 0; nt < NT; ++nt)
                #pragma unroll
                for (int i = 0; i < 4; ++i)
                    acc[mt][nt][i] += accx[mt][nt][i];
    }

    #pragma unroll
    for (int nt = 0; nt < NT; ++nt) {
        const int col = n0 + wcol * (BN / 2) + nt * 8 + lc * 2;
        const float2 bv = *(const float2*)&bias[col];
        #pragma unroll
        for (int mt = 0; mt < 2; ++mt) {
            const int row = m0 + wrow * 32 + mt * 16 + lr;
            #pragma unroll
            for (int half = 0; half < 2; ++half) {
                const int r = row + half * 8;
                float vx = acc[mt][nt][half * 2 + 0] + bv.x;
                float vy = acc[mt][nt][half * 2 + 1] + bv.y;
                if (ACT == 1) {
                    vx = 0.5f * vx * (1.0f + erff(vx * 0.7071067811865475f));
                    vy = 0.5f * vy * (1.0f + erff(vy * 0.7071067811865475f));
                }
                if (HAS_RES) {
                    float2 rv = *(const float2*)&Res[(size_t)r * N + col];
                    vx += rv.x; vy += rv.y;
                }
                if (OUT_HILO) {
                    bf16* Ch = (bf16*)Cv;
                    bf16* Cl = (bf16*)Clv;
                    *(uint32_t*)&Ch[(size_t)r * N + col] = bfpack(vx, vy);
                    *(uint32_t*)&Cl[(size_t)r * N + col] =
                        bfpack(vx - bfhi(vx), vy - bfhi(vy));
                } else {
                    float2 o; o.x = vx; o.y = vy;
                    *(float2*)&((float*)Cv)[(size_t)r * N + col] = o;
                }
            }
        }
    }
}

// ---------------- flash attention v2: bf16x3, register P, exp2 softmax ----------------
#define AS_KH(s)  ((s) * 73728 + 0)
#define AS_KL(s)  ((s) * 73728 + 18432)
#define AS_VH(s)  ((s) * 73728 + 36864)
#define AS_VL(s)  ((s) * 73728 + 55296)
#define AS_QH     147456
#define AS_QL     165888
#define AS_PMAX   184320
#define AS_PSUM   186368
#define AS_M      188416
#define AS_L      188928
#define SMEM_ATT2 189440

__global__ void __launch_bounds__(512, 1)
attn2(const bf16* __restrict__ Qh, const bf16* __restrict__ Ql,
      const bf16* __restrict__ Kh, const bf16* __restrict__ Kl,
      const bf16* __restrict__ Vh, const bf16* __restrict__ Vl,
      bf16* __restrict__ OH, bf16* __restrict__ OL) {
    extern __shared__ char smc[];
    const uint32_t sb = smem_u32(smc);
    const int qb = gridDim.x - 1 - blockIdx.x;
    const int h  = blockIdx.y;
    const int tid = threadIdx.x;
    const int wid = tid >> 5, lane = tid & 31;
    const int wrow = wid & 3, wcol = wid >> 2;
    const int lr = lane >> 2, lc = lane & 3;
    const int lrow = lane & 7, sub = lane >> 3;

    float* pmax = (float*)(smc + AS_PMAX);
    float* psum = (float*)(smc + AS_PSUM);
    float* m_sh = (float*)(smc + AS_M);
    float* l_sh = (float*)(smc + AS_L);

    #pragma unroll
    for (int i = 0; i < 2; ++i) {
        const int f = tid + i * 512;
        const int r = f >> 3, c = f & 7;
        const size_t go = (size_t)(qb * 128 + r) * D_MODEL + h * 64 + c * 8;
        cp16(sb + AS_QH + r * 144 + c * 16, Qh + go);
        cp16(sb + AS_QL + r * 144 + c * 16, Ql + go);
    }
    auto load_kv = [&](int kb, int s) {
        #pragma unroll
        for (int i = 0; i < 2; ++i) {
            const int f = tid + i * 512;
            const int r = f >> 3, c = f & 7;
            const size_t go = (size_t)(kb * 128 + r) * D_MODEL + h * 64 + c * 8;
            cp16(sb + AS_KH(s) + r * 144 + c * 16, Kh + go);
            cp16(sb + AS_KL(s) + r * 144 + c * 16, Kl + go);
            cp16(sb + AS_VH(s) + r * 144 + c * 16, Vh + go);
            cp16(sb + AS_VL(s) + r * 144 + c * 16, Vl + go);
        }
    };
    load_kv(0, 0);
    CP_COMMIT();
    if (tid < 128) { m_sh[tid] = -1e30f; l_sh[tid] = 0.f; }

    // log2-domain constants: s2 = s_raw * (0.125*log2e) + slope2 * (kk - qq)
    const float QS = 0.125f * 1.4426950408889634f;
    const float slope2 = 1.4426950408889634f * exp2f(-0.5f * (float)(h + 1));
    float oacc[2][8][4] = {};

    const uint32_t aoffQ = sb + AS_QH + (uint32_t)(wrow * 32 + lrow + 8 * (sub & 1)) * 144u + 16u * (sub >> 1);
    const uint32_t bSoff = (uint32_t)(32 * wcol + lrow + 8 * (sub >> 1)) * 144u + 16u * (sub & 1);
    const uint32_t bVoff = (uint32_t)(32 * wcol + lrow + 8 * (sub & 1)) * 144u + (uint32_t)(8 * (sub >> 1)) * 2u;

    for (int kb = 0; kb <= qb; ++kb) {
        const int s = kb & 1;
        CP_WAIT(0);
        __syncthreads();
        if (kb < qb) { load_kv(kb + 1, s ^ 1); CP_COMMIT(); }

        // S = Q K^T (bf16 x3)
        float sacc[2][4][4] = {};
        #pragma unroll
        for (int ks = 0; ks < 4; ++ks) {
            uint32_t qhf[2][4], qlf[2][4];
            #pragma unroll
            for (int mt = 0; mt < 2; ++mt) {
                ldsm4(qhf[mt], aoffQ + mt * 2304 + ks * 32);
                ldsm4(qlf[mt], aoffQ + 18432 + mt * 2304 + ks * 32);
            }
            uint32_t khf[4][2], klf[4][2];
            #pragma unroll
            for (int p = 0; p < 2; ++p) {
                uint32_t t[4];
                ldsm4(t, sb + AS_KH(s) + bSoff + p * 2304 + ks * 32);
                khf[2 * p][0] = t[0]; khf[2 * p][1] = t[1];
                khf[2 * p + 1][0] = t[2]; khf[2 * p + 1][1] = t[3];
                ldsm4(t, sb + AS_KL(s) + bSoff + p * 2304 + ks * 32);
                klf[2 * p][0] = t[0]; klf[2 * p][1] = t[1];
                klf[2 * p + 1][0] = t[2]; klf[2 * p + 1][1] = t[3];
            }
            #pragma unroll
            for (int nt = 0; nt < 4; ++nt) {
                mma_bf16(sacc[0][nt], qhf[0], khf[nt]);
                mma_bf16(sacc[1][nt], qhf[1], khf[nt]);
                mma_bf16(sacc[0][nt], qlf[0], khf[nt]);
                mma_bf16(sacc[1][nt], qlf[1], khf[nt]);
                mma_bf16(sacc[0][nt], qhf[0], klf[nt]);
                mma_bf16(sacc[1][nt], qhf[1], klf[nt]);
            }
        }

        // scale + alibi (+ mask only on diagonal tile); quad row-max (log2 domain)
        const bool diag = (kb == qb);
        float mxa[2], mxb[2];
        #pragma unroll
        for (int mt = 0; mt < 2; ++mt) {
            const int ra = qb * 128 + wrow * 32 + mt * 16 + lr, rb = ra + 8;
            float ma = -1e30f, mb = -1e30f;
            #pragma unroll
            for (int nt = 0; nt < 4; ++nt) {
                const int c0 = kb * 128 + 32 * wcol + 8 * nt + 2 * lc;
                float* sv = sacc[mt][nt];
                if (diag) {
                    sv[0] = (c0     <= ra) ? fmaf(sv[0], QS, slope2 * (float)(c0 - ra))     : -1e30f;
                    sv[1] = (c0 + 1 <= ra) ? fmaf(sv[1], QS, slope2 * (float)(c0 + 1 - ra)) : -1e30f;
                    sv[2] = (c0     <= rb) ? fmaf(sv[2], QS, slope2 * (float)(c0 - rb))     : -1e30f;
                    sv[3] = (c0 + 1 <= rb) ? fmaf(sv[3], QS, slope2 * (float)(c0 + 1 - rb)) : -1e30f;
                } else {
                    sv[0] = fmaf(sv[0], QS, slope2 * (float)(c0 - ra));
                    sv[1] = fmaf(sv[1], QS, slope2 * (float)(c0 + 1 - ra));
                    sv[2] = fmaf(sv[2], QS, slope2 * (float)(c0 - rb));
                    sv[3] = fmaf(sv[3], QS, slope2 * (float)(c0 + 1 - rb));
                }
                ma = fmaxf(ma, fmaxf(sv[0], sv[1]));
                mb = fmaxf(mb, fmaxf(sv[2], sv[3]));
            }
            ma = fmaxf(ma, __shfl_xor_sync(0xffffffffu, ma, 1));
            ma = fmaxf(ma, __shfl_xor_sync(0xffffffffu, ma, 2));
            mb = fmaxf(mb, __shfl_xor_sync(0xffffffffu, mb, 1));
            mb = fmaxf(mb, __shfl_xor_sync(0xffffffffu, mb, 2));
            mxa[mt] = ma; mxb[mt] = mb;
        }
        if (lc == 0) {
            #pragma unroll
            for (int mt = 0; mt < 2; ++mt) {
                pmax[wcol * 128 + wrow * 32 + mt * 16 + lr]     = mxa[mt];
                pmax[wcol * 128 + wrow * 32 + mt * 16 + lr + 8] = mxb[mt];
            }
        }
        __syncthreads();

        float mna[2], mnb[2], ala[2], alb[2];
        #pragma unroll
        for (int mt = 0; mt < 2; ++mt) {
            const int rla = wrow * 32 + mt * 16 + lr, rlb = rla + 8;
            const float pa = fmaxf(fmaxf(pmax[rla], pmax[128 + rla]),
                                   fmaxf(pmax[256 + rla], pmax[384 + rla]));
            const float pb = fmaxf(fmaxf(pmax[rlb], pmax[128 + rlb]),
                                   fmaxf(pmax[256 + rlb], pmax[384 + rlb]));
            const float moa = m_sh[rla], mob = m_sh[rlb];
            mna[mt] = fmaxf(moa, pa); mnb[mt] = fmaxf(mob, pb);
            ala[mt] = ex2(moa - mna[mt]); alb[mt] = ex2(mob - mnb[mt]);
        }
        #pragma unroll
        for (int mt = 0; mt < 2; ++mt) {
            float sa = 0.f, sbv = 0.f;
            #pragma unroll
            for (int nt = 0; nt < 4; ++nt) {
                float* sv = sacc[mt][nt];
                sv[0] = ex2(sv[0] - mna[mt]); sv[1] = ex2(sv[1] - mna[mt]);
                sv[2] = ex2(sv[2] - mnb[mt]); sv[3] = ex2(sv[3] - mnb[mt]);
                sa += sv[0] + sv[1]; sbv += sv[2] + sv[3];
            }
            sa  += __shfl_xor_sync(0xffffffffu, sa, 1);
            sa  += __shfl_xor_sync(0xffffffffu, sa, 2);
            sbv += __shfl_xor_sync(0xffffffffu, sbv, 1);
            sbv += __shfl_xor_sync(0xffffffffu, sbv, 2);
            if (lc == 0) {
                psum[wcol * 128 + wrow * 32 + mt * 16 + lr]     = sa;
                psum[wcol * 128 + wrow * 32 + mt * 16 + lr + 8] = sbv;
            }
        }
        #pragma unroll
        for (int mt = 0; mt < 2; ++mt)
            #pragma unroll
            for (int nt = 0; nt < 8; ++nt) {
                oacc[mt][nt][0] *= ala[mt]; oacc[mt][nt][1] *= ala[mt];
                oacc[mt][nt][2] *= alb[mt]; oacc[mt][nt][3] *= alb[mt];
            }
        __syncthreads();

        if (wcol == 0 && lc == 0) {
            #pragma unroll
            for (int mt = 0; mt < 2; ++mt) {
                const int rla = wrow * 32 + mt * 16 + lr, rlb = rla + 8;
                l_sh[rla] = l_sh[rla] * ala[mt] +
                            (psum[rla] + psum[128 + rla]) + (psum[256 + rla] + psum[384 + rla]);
                l_sh[rlb] = l_sh[rlb] * alb[mt] +
                            (psum[rlb] + psum[128 + rlb]) + (psum[256 + rlb] + psum[384 + rlb]);
                m_sh[rla] = mna[mt]; m_sh[rlb] = mnb[mt];
            }
        }

        // O += P V
        #pragma unroll
        for (int g = 0; g < 2; ++g) {
            uint32_t pah[2][4], pal[2][4];
            #pragma unroll
            for (int mt = 0; mt < 2; ++mt) {
                const float* s0 = sacc[mt][2 * g];
                const float* s1 = sacc[mt][2 * g + 1];
                pah[mt][0] = bfpack(s0[0], s0[1]); pah[mt][1] = bfpack(s0[2], s0[3]);
                pah[mt][2] = bfpack(s1[0], s1[1]); pah[mt][3] = bfpack(s1[2], s1[3]);
                pal[mt][0] = bfpack(s0[0] - bfhi(s0[0]), s0[1] - bfhi(s0[1]));
                pal[mt][1] = bfpack(s0[2] - bfhi(s0[2]), s0[3] - bfhi(s0[3]));
                pal[mt][2] = bfpack(s1[0] - bfhi(s1[0]), s1[1] - bfhi(s1[1]));
                pal[mt][3] = bfpack(s1[2] - bfhi(s1[2]), s1[3] - bfhi(s1[3]));
            }
            #pragma unroll
            for (int p = 0; p < 4; ++p) {
                uint32_t vh[2][2], vl[2][2], t[4];
                ldsm4t(t, sb + AS_VH(s) + bVoff + g * 2304 + p * 32);
                vh[0][0] = t[0]; vh[0][1] = t[1]; vh[1][0] = t[2]; vh[1][1] = t[3];
                ldsm4t(t, sb + AS_VL(s) + bVoff + g * 2304 + p * 32);
                vl[0][0] = t[0]; vl[0][1] = t[1]; vl[1][0] = t[2]; vl[1][1] = t[3];
                #pragma unroll
                for (int q2 = 0; q2 < 2; ++q2) {
                    const int nt = 2 * p + q2;
                    mma_bf16(oacc[0][nt], pah[0], vh[q2]);
                    mma_bf16(oacc[1][nt], pah[1], vh[q2]);
                    mma_bf16(oacc[0][nt], pal[0], vh[q2]);
                    mma_bf16(oacc[1][nt], pal[1], vh[q2]);
                    mma_bf16(oacc[0][nt], pah[0], vl[q2]);
                    mma_bf16(oacc[1][nt], pah[1], vl[q2]);
                }
            }
        }
    }

    __syncthreads();
    float* Ob = (float*)smc;
    #pragma unroll
    for (int w = 0; w < 4; ++w) {
        if (wcol == w) {
            #pragma unroll
            for (int mt = 0; mt < 2; ++mt) {
                const int rla = wrow * 32 + mt * 16 + lr, rlb = rla + 8;
                #pragma unroll
                for (int nt = 0; nt < 8; ++nt) {
                    const int d0 = 8 * nt + 2 * lc;
                    if (w == 0) {
                        Ob[rla * 64 + d0]     = oacc[mt][nt][0];
                        Ob[rla * 64 + d0 + 1] = oacc[mt][nt][1];
                        Ob[rlb * 64 + d0]     = oacc[mt][nt][2];
                        Ob[rlb * 64 + d0 + 1] = oacc[mt][nt][3];
                    } else {
                        Ob[rla * 64 + d0]     += oacc[mt][nt][0];
                        Ob[rla * 64 + d0 + 1] += oacc[mt][nt][1];
                        Ob[rlb * 64 + d0]     += oacc[mt][nt][2];
                        Ob[rlb * 64 + d0 + 1] += oacc[mt][nt][3];
                    }
                }
            }
        }
        __syncthreads();
    }
    #pragma unroll
    for (int i = 0; i < 16; ++i) {
        const int f = tid + i * 512;
        const int r = f >> 6, d = f & 63;
        const float val = Ob[f] / l_sh[r];
        const size_t go = (size_t)(qb * 128 + r) * D_MODEL + h * 64 + d;
        OH[go] = __float2bfloat16(val);
        OL[go] = __float2bfloat16(val - bfhi(val));
    }
}

// ---------------- launch ----------------
extern "C" void kernel_launch(void* const* d_in, const int* in_sizes, int n_in,
                              void* d_out, int out_size) {
    const float* x   = (const float*)d_in[0];
    const float* wq  = (const float*)d_in[3];
    const float* bq  = (const float*)d_in[4];
    const float* wk  = (const float*)d_in[5];
    const float* bk  = (const float*)d_in[6];
    const float* wv  = (const float*)d_in[7];
    const float* bv  = (const float*)d_in[8];
    const float* wo  = (const float*)d_in[9];
    const float* bo  = (const float*)d_in[10];
    const float* w1  = (const float*)d_in[11];
    const float* b1  = (const float*)d_in[12];
    const float* w2  = (const float*)d_in[13];
    const float* b2  = (const float*)d_in[14];
    const float* g1  = (const float*)d_in[15];
    const float* be1 = (const float*)d_in[16];
    const float* g2  = (const float*)d_in[17];
    const float* be2 = (const float*)d_in[18];
    float* out = (float*)d_out;

    float* p_x1;
    bf16 *p_xnh, *p_xnl, *p_ah, *p_al, *p_hh, *p_hl;
    bf16 *p_qh, *p_ql, *p_kh, *p_kl, *p_vh, *p_vl;
    bf16 *p_wqh, *p_wql, *p_wkh, *p_wkl, *p_wvh, *p_wvl, *p_woh, *p_wol;
    bf16 *p_w1h, *p_w1l, *p_w2h, *p_w2l;
    cudaGetSymbolAddress((void**)&p_x1,  g_x1);
    cudaGetSymbolAddress((void**)&p_xnh, g_xnh);
    cudaGetSymbolAddress((void**)&p_xnl, g_xnl);
    cudaGetSymbolAddress((void**)&p_qh,  g_qh);
    cudaGetSymbolAddress((void**)&p_ql,  g_ql);
    cudaGetSymbolAddress((void**)&p_kh,  g_kh);
    cudaGetSymbolAddress((void**)&p_kl,  g_kl);
    cudaGetSymbolAddress((void**)&p_vh,  g_vh);
    cudaGetSymbolAddress((void**)&p_vl,  g_vl);
    cudaGetSymbolAddress((void**)&p_ah,  g_ah);
    cudaGetSymbolAddress((void**)&p_al,  g_al);
    cudaGetSymbolAddress((void**)&p_hh,  g_hh);
    cudaGetSymbolAddress((void**)&p_hl,  g_hl);
    cudaGetSymbolAddress((void**)&p_wqh, g_wqh);
    cudaGetSymbolAddress((void**)&p_wql, g_wql);
    cudaGetSymbolAddress((void**)&p_wkh, g_wkh);
    cudaGetSymbolAddress((void**)&p_wkl, g_wkl);
    cudaGetSymbolAddress((void**)&p_wvh, g_wvh);
    cudaGetSymbolAddress((void**)&p_wvl, g_wvl);
    cudaGetSymbolAddress((void**)&p_woh, g_woh);
    cudaGetSymbolAddress((void**)&p_wol, g_wol);
    cudaGetSymbolAddress((void**)&p_w1h, g_w1h);
    cudaGetSymbolAddress((void**)&p_w1l, g_w1l);
    cudaGetSymbolAddress((void**)&p_w2h, g_w2h);
    cudaGetSymbolAddress((void**)&p_w2l, g_w2l);

    const int smem64  = 2 * (2 * 128 * 144 + 2 * 64 * 144);
    const int smem128 = 2 * (2 * 128 * 80 + 2 * 32 * 272);

    cudaFuncSetAttribute(bgemm<0, false, true,  64>,  cudaFuncAttributeMaxDynamicSharedMemorySize, smem64);
    cudaFuncSetAttribute(bgemm<0, true,  false, 64>,  cudaFuncAttributeMaxDynamicSharedMemorySize, smem64);
    cudaFuncSetAttribute(bgemm<1, false, true,  128>, cudaFuncAttributeMaxDynamicSharedMemorySize, smem128);
    cudaFuncSetAttribute(attn2, cudaFuncAttributeMaxDynamicSharedMemorySize, SMEM_ATT2);

    wsplit4<<<dim3(256, 4), 256>>>(wq, wk, wv, wo,
                                   p_wqh, p_wql, p_wkh, p_wkl,
                                   p_wvh, p_wvl, p_woh, p_wol);
    ln_kernel<<<T_SEQ, 256>>>(x, g1, be1, p_xnh, p_xnl);

    // fused QKV -> bf16 hi/lo
    bgemm<0, false, true, 64><<<dim3(D_MODEL / 64, T_SEQ / 128, 3), 256, smem64>>>(
        p_xnh, p_xnl, p_wqh, p_wql, p_wkh, p_wkl, p_wvh, p_wvl,
        bq, bk, bv, nullptr, p_qh, p_kh, p_vh, p_ql, p_kl, p_vl, D_MODEL, D_MODEL);

    // attention v2  <-- profiled position
    attn2<<<dim3(16, N_HEADS), 512, SMEM_ATT2>>>(p_qh, p_ql, p_kh, p_kl, p_vh, p_vl, p_ah, p_al);

    // O projection + residual(x)
    bgemm<0, true, false, 64><<<dim3(D_MODEL / 64, T_SEQ / 128, 1), 256, smem64>>>(
        p_ah, p_al, p_woh, p_wol, p_woh, p_wol, p_woh, p_wol,
        bo, bo, bo, x, p_x1, p_x1, p_x1, nullptr, nullptr, nullptr, D_MODEL, D_MODEL);

    ln_kernel<<<T_SEQ, 256>>>(p_x1, g2, be2, p_xnh, p_xnl);
    wsplit2<<<dim3(1024, 2), 256>>>(w1, w2, p_w1h, p_w1l, p_w2h, p_w2l);

    // FFN1 + GELU -> hi/lo
    bgemm<1, false, true, 128><<<dim3(FFN_DIM / 128, T_SEQ / 128, 1), 256, smem128>>>(
        p_xnh, p_xnl, p_w1h, p_w1l, p_w1h, p_w1l, p_w1h, p_w1l,
        b1, b1, b1, nullptr, p_hh, p_hh, p_hh, p_hl, p_hl, p_hl, FFN_DIM, D_MODEL);

    // FFN2 + residual(x1)
    bgemm<0, true, false, 64><<<dim3(D_MODEL / 64, T_SEQ / 128, 1), 256, smem64>>>(
        p_hh, p_hl, p_w2h, p_w2l, p_w2h, p_w2l, p_w2h, p_w2l,
        b2, b2, b2, p_x1, out, out, out, nullptr, nullptr, nullptr, D_MODEL, FFN_DIM);
}